// round 1
// baseline (speedup 1.0000x reference)
#include <cuda_runtime.h>
#include <cuda_bf16.h>
#include <math.h>

// ---------------------------------------------------------------------------
// Problem constants
// ---------------------------------------------------------------------------
#define TOTAL_Q   2048
#define TOTAL_KV  2048
#define Q_IN      1024
#define KV_IN     1033
#define D_QK      1024
#define D_V       1024
#define N_HEADS   16
#define HEAD_DIM  64            // D_QK / N_HEADS == D_V / N_HEADS
#define N_IMAGES  32
#define SCALER    0.125f        // 1/sqrt(64)

// ---------------------------------------------------------------------------
// Device scratch (no allocations allowed)
// ---------------------------------------------------------------------------
__device__ float g_Q [TOTAL_Q  * D_QK];
__device__ float g_K [TOTAL_KV * D_QK];
__device__ float g_V [TOTAL_KV * D_V ];
__device__ float g_WV[TOTAL_Q  * D_V ];
__device__ int   g_kv_start[N_IMAGES];
__device__ int   g_kv_end  [N_IMAGES];

// ---------------------------------------------------------------------------
// fp32 tiled GEMM with bias: C[M,N] = A[M,K] @ B[K,N] + bias[N]
// BM=BN=128, BK=8, 256 threads, 8x8 register micro-tile per thread.
// M % 128 == 0, N % 128 == 0 required; K arbitrary (guarded).
// ---------------------------------------------------------------------------
__global__ __launch_bounds__(256) void gemm_bias_kernel(
    const float* __restrict__ A, const float* __restrict__ B,
    const float* __restrict__ bias, float* __restrict__ C,
    int M, int N, int K)
{
    __shared__ float As[8][128];
    __shared__ float Bs[8][128];

    const int bm  = blockIdx.y * 128;
    const int bn  = blockIdx.x * 128;
    const int tid = threadIdx.x;
    const int tx  = tid & 15;   // n direction
    const int ty  = tid >> 4;   // m direction

    float acc[8][8];
#pragma unroll
    for (int i = 0; i < 8; i++)
#pragma unroll
        for (int j = 0; j < 8; j++) acc[i][j] = 0.f;

    for (int k0 = 0; k0 < K; k0 += 8) {
        // A tile: 128 rows x 8 k (scalar loads; K may be odd, e.g. 1033)
#pragma unroll
        for (int r = 0; r < 4; r++) {
            int idx = tid + r * 256;       // 0..1023
            int m   = idx >> 3;
            int k   = idx & 7;
            float v = 0.f;
            if (k0 + k < K) v = A[(size_t)(bm + m) * K + k0 + k];
            As[k][m] = v;
        }
        // B tile: 8 rows x 128 cols (rows are 16B aligned since N=1024)
        {
            int row = tid >> 5;            // 0..7
            int col = (tid & 31) * 4;      // 0..124
            float4 v = make_float4(0.f, 0.f, 0.f, 0.f);
            if (k0 + row < K)
                v = *reinterpret_cast<const float4*>(&B[(size_t)(k0 + row) * N + bn + col]);
            *reinterpret_cast<float4*>(&Bs[row][col]) = v;
        }
        __syncthreads();

#pragma unroll
        for (int k = 0; k < 8; k++) {
            float a[8], b[8];
            *reinterpret_cast<float4*>(&a[0]) = *reinterpret_cast<float4*>(&As[k][ty * 8]);
            *reinterpret_cast<float4*>(&a[4]) = *reinterpret_cast<float4*>(&As[k][ty * 8 + 4]);
            *reinterpret_cast<float4*>(&b[0]) = *reinterpret_cast<float4*>(&Bs[k][tx * 8]);
            *reinterpret_cast<float4*>(&b[4]) = *reinterpret_cast<float4*>(&Bs[k][tx * 8 + 4]);
#pragma unroll
            for (int i = 0; i < 8; i++)
#pragma unroll
                for (int j = 0; j < 8; j++)
                    acc[i][j] += a[i] * b[j];
        }
        __syncthreads();
    }

#pragma unroll
    for (int i = 0; i < 8; i++) {
        int m = bm + ty * 8 + i;
#pragma unroll
        for (int j = 0; j < 8; j += 4) {
            int n = bn + tx * 8 + j;
            float4 o;
            o.x = acc[i][j]     + bias[n];
            o.y = acc[i][j + 1] + bias[n + 1];
            o.z = acc[i][j + 2] + bias[n + 2];
            o.w = acc[i][j + 3] + bias[n + 3];
            *reinterpret_cast<float4*>(&C[(size_t)m * N + n]) = o;
        }
    }
}

// ---------------------------------------------------------------------------
// Segment boundaries from sorted/contiguous segment ids
// ---------------------------------------------------------------------------
__global__ void seg_bounds_kernel(const int* __restrict__ seg, int n)
{
    int i = blockIdx.x * blockDim.x + threadIdx.x;
    if (i >= n) return;
    int s = seg[i];
    if (i == 0     || seg[i - 1] != s) g_kv_start[s] = i;
    if (i == n - 1 || seg[i + 1] != s) g_kv_end[s]   = i + 1;
}

// ---------------------------------------------------------------------------
// Attention: one warp per (query row, head). Online softmax over the query's
// segment kv range. Lane l holds dims (2l, 2l+1) of the 64-dim head vectors.
// ---------------------------------------------------------------------------
__global__ __launch_bounds__(256) void attn_kernel(const int* __restrict__ seg_q)
{
    const int gwarp = (blockIdx.x * blockDim.x + threadIdx.x) >> 5;
    const int lane  = threadIdx.x & 31;
    const int i = gwarp >> 4;        // query row
    const int h = gwarp & 15;        // head
    if (i >= TOTAL_Q) return;

    const int s  = seg_q[i];
    const int k0 = g_kv_start[s];
    const int k1 = g_kv_end[s];

    const float2 qv = *reinterpret_cast<const float2*>(
        &g_Q[(size_t)i * D_QK + h * HEAD_DIM + 2 * lane]);

    float  m   = -1e30f;
    float  den = 0.f;
    float2 acc = make_float2(0.f, 0.f);

    for (int kk = k0; kk < k1; kk++) {
        const float2 kvv = *reinterpret_cast<const float2*>(
            &g_K[(size_t)kk * D_QK + h * HEAD_DIM + 2 * lane]);
        float partial = qv.x * kvv.x + qv.y * kvv.y;
#pragma unroll
        for (int off = 16; off; off >>= 1)
            partial += __shfl_xor_sync(0xffffffffu, partial, off);
        const float sc = partial * SCALER;

        const float nm   = fmaxf(m, sc);
        const float corr = __expf(m - nm);
        const float p    = __expf(sc - nm);
        m   = nm;
        den = den * corr + p;

        const float2 vv = *reinterpret_cast<const float2*>(
            &g_V[(size_t)kk * D_V + h * HEAD_DIM + 2 * lane]);
        acc.x = acc.x * corr + p * vv.x;
        acc.y = acc.y * corr + p * vv.y;
    }

    const float inv = 1.f / den;
    float2 o = make_float2(acc.x * inv, acc.y * inv);
    *reinterpret_cast<float2*>(&g_WV[(size_t)i * D_V + h * HEAD_DIM + 2 * lane]) = o;
}

// ---------------------------------------------------------------------------
// Launch
// ---------------------------------------------------------------------------
extern "C" void kernel_launch(void* const* d_in, const int* in_sizes, int n_in,
                              void* d_out, int out_size)
{
    const float* A     = (const float*)d_in[0];
    const float* B0    = (const float*)d_in[1];
    const int*   seg_q = (const int*)  d_in[2];
    const int*   seg_kv= (const int*)  d_in[3];
    const float* Wq    = (const float*)d_in[4];
    const float* bq    = (const float*)d_in[5];
    const float* Wk    = (const float*)d_in[6];
    const float* bk    = (const float*)d_in[7];
    const float* Wv    = (const float*)d_in[8];
    const float* bv    = (const float*)d_in[9];
    const float* Wf    = (const float*)d_in[10];
    const float* bf    = (const float*)d_in[11];
    float*       out   = (float*)d_out;

    float *Qp, *Kp, *Vp, *WVp;
    cudaGetSymbolAddress((void**)&Qp,  g_Q);
    cudaGetSymbolAddress((void**)&Kp,  g_K);
    cudaGetSymbolAddress((void**)&Vp,  g_V);
    cudaGetSymbolAddress((void**)&WVp, g_WV);

    dim3 gblk(256);
    dim3 ggrid_q(D_QK / 128, TOTAL_Q / 128);   // (8, 16)

    // Projections
    gemm_bias_kernel<<<ggrid_q, gblk>>>(A,  Wq, bq, Qp, TOTAL_Q,  D_QK, Q_IN);
    gemm_bias_kernel<<<ggrid_q, gblk>>>(B0, Wk, bk, Kp, TOTAL_KV, D_QK, KV_IN);
    gemm_bias_kernel<<<ggrid_q, gblk>>>(B0, Wv, bv, Vp, TOTAL_KV, D_V,  KV_IN);

    // Segment boundaries (kv side)
    seg_bounds_kernel<<<(TOTAL_KV + 255) / 256, 256>>>(seg_kv, TOTAL_KV);

    // Attention: one warp per (row, head) -> 2048*16 warps, 8 warps/block
    attn_kernel<<<(TOTAL_Q * N_HEADS) / 8, 256>>>(seg_q);

    // Output projection -> d_out
    gemm_bias_kernel<<<ggrid_q, gblk>>>(WVp, Wf, bf, out, TOTAL_Q, Q_IN, D_V);
}

// round 4
// speedup vs baseline: 1.5120x; 1.5120x over previous
#include <cuda_runtime.h>
#include <cuda_bf16.h>
#include <cstdint>
#include <math.h>

// ---------------------------------------------------------------------------
// Problem constants
// ---------------------------------------------------------------------------
#define TOTAL_Q   2048
#define TOTAL_KV  2048
#define Q_IN      1024
#define KV_IN     1033
#define D_QK      1024
#define D_V       1024
#define N_HEADS   16
#define HEAD_DIM  64
#define N_IMAGES  32
#define SCALER    0.125f

// ---------------------------------------------------------------------------
// Device scratch
// ---------------------------------------------------------------------------
__device__ float g_Q [TOTAL_Q  * D_QK];
__device__ float g_K [TOTAL_KV * D_QK];
__device__ float g_V [TOTAL_KV * D_V ];
__device__ float g_WV[TOTAL_Q  * D_V ];
__device__ int   g_kv_start[N_IMAGES], g_kv_end[N_IMAGES];
__device__ int   g_q_start [N_IMAGES], g_q_end [N_IMAGES];

// ---------------------------------------------------------------------------
// mma.sync helper (bf16 x bf16 -> f32, m16n8k16, A row-major, B col-major)
// ---------------------------------------------------------------------------
__device__ __forceinline__ void mma16816(float* c,
    uint32_t a0, uint32_t a1, uint32_t a2, uint32_t a3,
    uint32_t b0, uint32_t b1)
{
    asm volatile(
        "mma.sync.aligned.m16n8k16.row.col.f32.bf16.bf16.f32 "
        "{%0,%1,%2,%3}, {%4,%5,%6,%7}, {%8,%9}, {%0,%1,%2,%3};"
        : "+f"(c[0]), "+f"(c[1]), "+f"(c[2]), "+f"(c[3])
        : "r"(a0), "r"(a1), "r"(a2), "r"(a3), "r"(b0), "r"(b1));
}

__device__ __forceinline__ void split_bf16(float x, __nv_bfloat16& hi, __nv_bfloat16& lo)
{
    hi = __float2bfloat16(x);
    lo = __float2bfloat16(x - __bfloat162float(hi));
}

// ---------------------------------------------------------------------------
// Split-bf16 (3-term) tensor-core GEMM:
//   C[M,N] = A[M,K](fp32) @ W[K,N](fp32) + bias,
//   A*W ~= Ahi*Whi + Ahi*Wlo + Alo*Whi   (error ~2^-16)
// BM=64, BN=128, BK=32, 256 threads (8 warps, warp tile 16x64),
// double-buffered SMEM with register prefetch.
// ---------------------------------------------------------------------------
#define BM 64
#define BN 128
#define BK 32
// SMEM layouts: A [64][34] bf16 (pad 2), B stored [n][k] = [128][34]
#define AHI_OFF 0
#define ALO_OFF 4352
#define BHI_OFF 8704
#define BLO_OFF 17408
#define STAGE   26112
#define GEMM_SMEM (2 * STAGE)

__global__ __launch_bounds__(256, 2) void gemm_bf16x3(
    const float* __restrict__ A, const float* __restrict__ W,
    const float* __restrict__ bias, float* __restrict__ C,
    int N, int K)
{
    extern __shared__ char smc[];
    const int tid  = threadIdx.x;
    const int lane = tid & 31;
    const int wid  = tid >> 5;
    const int qid  = lane >> 2;   // 0..7
    const int tq   = lane & 3;    // 0..3
    const int warpM = wid & 3;    // 4 warps along M (16 rows each)
    const int warpN = wid >> 2;   // 2 warps along N (64 cols each)
    const int bm = blockIdx.y * BM;
    const int bn = blockIdx.x * BN;

    const int chunks = (K + BK - 1) / BK;
    const bool k_vec_ok = ((K & 3) == 0);   // float4 A loads legal only if rows 16B-aligned
    const int arow = tid >> 3;          // 0..31
    const int acq  = (tid & 7) * 4;     // 0..28

    float acc[8][4];
#pragma unroll
    for (int t = 0; t < 8; t++)
#pragma unroll
        for (int j = 0; j < 4; j++) acc[t][j] = 0.f;

    float a_pre[8];
    float b_pre[16];

    // ---- global load of one K-chunk into registers ----
    auto LOADG = [&](int c) {
        const int k0 = c * BK;
        const bool full = (k0 + BK <= K);
        // A rows (2 rows of 4 floats per thread)
        if (full && k_vec_ok) {
#pragma unroll
            for (int i = 0; i < 2; i++)
                *(float4*)&a_pre[i * 4] =
                    *(const float4*)&A[(size_t)(bm + arow + i * 32) * K + k0 + acq];
        } else {
#pragma unroll
            for (int i = 0; i < 2; i++)
#pragma unroll
                for (int j = 0; j < 4; j++) {
                    int k = k0 + acq + j;
                    a_pre[i * 4 + j] = (k < K)
                        ? A[(size_t)(bm + arow + i * 32) * K + k] : 0.f;
                }
        }
        // W rows (N multiple of 4 -> float4 always aligned; guard row index)
        if (full) {
#pragma unroll
            for (int i = 0; i < 4; i++)
                *(float4*)&b_pre[i * 4] =
                    *(const float4*)&W[(size_t)(k0 + arow) * N + bn + acq + i * 32];
        } else {
            bool rowok = (k0 + arow) < K;
#pragma unroll
            for (int i = 0; i < 4; i++) {
                float4 v = make_float4(0.f, 0.f, 0.f, 0.f);
                if (rowok)
                    v = *(const float4*)&W[(size_t)(k0 + arow) * N + bn + acq + i * 32];
                *(float4*)&b_pre[i * 4] = v;
            }
        }
    };

    // ---- convert + store registers into SMEM stage s ----
    auto STORES = [&](int s) {
        char* base = smc + s * STAGE;
#pragma unroll
        for (int i = 0; i < 2; i++) {
            int m = arow + 32 * i;
            __nv_bfloat16 h[4], l[4];
#pragma unroll
            for (int j = 0; j < 4; j++) split_bf16(a_pre[i * 4 + j], h[j], l[j]);
            __nv_bfloat162 ph0, ph1, pl0, pl1;
            ph0.x = h[0]; ph0.y = h[1]; ph1.x = h[2]; ph1.y = h[3];
            pl0.x = l[0]; pl0.y = l[1]; pl1.x = l[2]; pl1.y = l[3];
            uint32_t off = (m * 34 + acq) * 2;
            *(uint32_t*)(base + AHI_OFF + off)     = *(uint32_t*)&ph0;
            *(uint32_t*)(base + AHI_OFF + off + 4) = *(uint32_t*)&ph1;
            *(uint32_t*)(base + ALO_OFF + off)     = *(uint32_t*)&pl0;
            *(uint32_t*)(base + ALO_OFF + off + 4) = *(uint32_t*)&pl1;
        }
        int kk = arow;   // k row within chunk
#pragma unroll
        for (int i = 0; i < 4; i++) {
            int n = acq + 32 * i;
#pragma unroll
            for (int j = 0; j < 4; j++) {
                __nv_bfloat16 h, l;
                split_bf16(b_pre[i * 4 + j], h, l);
                uint32_t off = ((n + j) * 34 + kk) * 2;
                *(__nv_bfloat16*)(base + BHI_OFF + off) = h;
                *(__nv_bfloat16*)(base + BLO_OFF + off) = l;
            }
        }
    };

    // ---- compute on stage s ----
    auto COMPUTE = [&](int s) {
        const char* base = smc + s * STAGE;
#pragma unroll
        for (int ks = 0; ks < 2; ks++) {
            const int cc = ks * 16 + tq * 2;
            const int r0 = warpM * 16 + qid;
            uint32_t ah0 = *(const uint32_t*)(base + AHI_OFF + (r0 * 34 + cc) * 2);
            uint32_t ah1 = *(const uint32_t*)(base + AHI_OFF + ((r0 + 8) * 34 + cc) * 2);
            uint32_t ah2 = *(const uint32_t*)(base + AHI_OFF + (r0 * 34 + cc + 8) * 2);
            uint32_t ah3 = *(const uint32_t*)(base + AHI_OFF + ((r0 + 8) * 34 + cc + 8) * 2);
            uint32_t al0 = *(const uint32_t*)(base + ALO_OFF + (r0 * 34 + cc) * 2);
            uint32_t al1 = *(const uint32_t*)(base + ALO_OFF + ((r0 + 8) * 34 + cc) * 2);
            uint32_t al2 = *(const uint32_t*)(base + ALO_OFF + (r0 * 34 + cc + 8) * 2);
            uint32_t al3 = *(const uint32_t*)(base + ALO_OFF + ((r0 + 8) * 34 + cc + 8) * 2);
#pragma unroll
            for (int tn = 0; tn < 8; tn++) {
                const int nb = warpN * 64 + tn * 8 + qid;
                uint32_t bh0 = *(const uint32_t*)(base + BHI_OFF + (nb * 34 + cc) * 2);
                uint32_t bh1 = *(const uint32_t*)(base + BHI_OFF + (nb * 34 + cc + 8) * 2);
                uint32_t bl0 = *(const uint32_t*)(base + BLO_OFF + (nb * 34 + cc) * 2);
                uint32_t bl1 = *(const uint32_t*)(base + BLO_OFF + (nb * 34 + cc + 8) * 2);
                mma16816(acc[tn], ah0, ah1, ah2, ah3, bh0, bh1);
                mma16816(acc[tn], ah0, ah1, ah2, ah3, bl0, bl1);
                mma16816(acc[tn], al0, al1, al2, al3, bh0, bh1);
            }
        }
    };

    LOADG(0);
    STORES(0);
    __syncthreads();

    for (int c = 0; c < chunks; c++) {
        if (c + 1 < chunks) LOADG(c + 1);
        COMPUTE(c & 1);
        if (c + 1 < chunks) STORES((c + 1) & 1);
        __syncthreads();
    }

    // ---- epilogue: bias + store fp32 ----
    const int r0 = bm + warpM * 16 + qid;
#pragma unroll
    for (int tn = 0; tn < 8; tn++) {
        const int col = bn + warpN * 64 + tn * 8 + tq * 2;
        float2 b2 = *(const float2*)&bias[col];
        float2 v0 = make_float2(acc[tn][0] + b2.x, acc[tn][1] + b2.y);
        float2 v1 = make_float2(acc[tn][2] + b2.x, acc[tn][3] + b2.y);
        *(float2*)&C[(size_t)r0 * N + col]       = v0;
        *(float2*)&C[(size_t)(r0 + 8) * N + col] = v1;
    }
}

// ---------------------------------------------------------------------------
// Segment boundaries (contiguous ids)
// ---------------------------------------------------------------------------
__global__ void seg_bounds_kernel(const int* __restrict__ seg, int n,
                                  int* __restrict__ start, int* __restrict__ end)
{
    int i = blockIdx.x * blockDim.x + threadIdx.x;
    if (i >= n) return;
    int s = seg[i];
    if (i == 0     || seg[i - 1] != s) start[s] = i;
    if (i == n - 1 || seg[i + 1] != s) end[s]   = i + 1;
}

// ---------------------------------------------------------------------------
// Attention: block = (head, segment, qblock of 64 queries), 8 warps.
// K/V staged in SMEM in 64-row chunks; each warp owns up to 8 queries
// (online softmax, lane holds dims 2l, 2l+1).
// ---------------------------------------------------------------------------
__global__ __launch_bounds__(256) void attn_kernel()
{
    __shared__ float Ks[64 * 64];
    __shared__ float Vs[64 * 64];
    const int h  = blockIdx.x;
    const int s  = blockIdx.y;
    const int qb = blockIdx.z;
    const int k0 = g_kv_start[s], k1 = g_kv_end[s];
    const int qs = g_q_start[s],  qe = g_q_end[s];
    const int q0 = qs + qb * 64;
    const int q1 = min(qs + (qb + 1) * 64, qe);
    if (q0 >= q1) return;

    const int tid = threadIdx.x, wid = tid >> 5, lid = tid & 31;

    float2 qv[8], acc[8];
    float  m[8], den[8];
    int nq = 0;
#pragma unroll
    for (int j = 0; j < 8; j++) {
        int q = q0 + wid + 8 * j;
        if (q < q1) {
            nq = j + 1;
            qv[j] = *(const float2*)&g_Q[(size_t)q * D_QK + h * HEAD_DIM + 2 * lid];
        } else {
            qv[j] = make_float2(0.f, 0.f);
        }
        m[j] = -1e30f; den[j] = 0.f; acc[j] = make_float2(0.f, 0.f);
    }

    for (int kc = k0; kc < k1; kc += 64) {
        int cl = min(64, k1 - kc);
        __syncthreads();
        for (int f4 = tid; f4 < cl * 16; f4 += 256) {
            int kk = f4 >> 4, c4 = f4 & 15;
            *(float4*)&Ks[kk * 64 + c4 * 4] =
                *(const float4*)&g_K[(size_t)(kc + kk) * D_QK + h * HEAD_DIM + c4 * 4];
            *(float4*)&Vs[kk * 64 + c4 * 4] =
                *(const float4*)&g_V[(size_t)(kc + kk) * D_V + h * HEAD_DIM + c4 * 4];
        }
        __syncthreads();
        for (int kk = 0; kk < cl; kk++) {
            float2 kv = *(const float2*)&Ks[kk * 64 + 2 * lid];
            float2 vv = *(const float2*)&Vs[kk * 64 + 2 * lid];
#pragma unroll
            for (int j = 0; j < 8; j++) {
                if (j >= nq) break;
                float part = qv[j].x * kv.x + qv[j].y * kv.y;
#pragma unroll
                for (int o = 16; o; o >>= 1)
                    part += __shfl_xor_sync(0xffffffffu, part, o);
                float sc = part * SCALER;
                if (sc > m[j]) {
                    float corr = __expf(m[j] - sc);
                    den[j] = den[j] * corr + 1.f;
                    acc[j].x = acc[j].x * corr + vv.x;
                    acc[j].y = acc[j].y * corr + vv.y;
                    m[j] = sc;
                } else {
                    float p = __expf(sc - m[j]);
                    den[j] += p;
                    acc[j].x += p * vv.x;
                    acc[j].y += p * vv.y;
                }
            }
        }
    }

    for (int j = 0; j < nq; j++) {
        int q = q0 + wid + 8 * j;
        if (q < q1) {
            float inv = 1.f / den[j];
            *(float2*)&g_WV[(size_t)q * D_V + h * HEAD_DIM + 2 * lid] =
                make_float2(acc[j].x * inv, acc[j].y * inv);
        }
    }
}

// ---------------------------------------------------------------------------
// Launch
// ---------------------------------------------------------------------------
extern "C" void kernel_launch(void* const* d_in, const int* in_sizes, int n_in,
                              void* d_out, int out_size)
{
    const float* A     = (const float*)d_in[0];
    const float* B0    = (const float*)d_in[1];
    const int*   seg_q = (const int*)  d_in[2];
    const int*   seg_kv= (const int*)  d_in[3];
    const float* Wq    = (const float*)d_in[4];
    const float* bq    = (const float*)d_in[5];
    const float* Wk    = (const float*)d_in[6];
    const float* bk    = (const float*)d_in[7];
    const float* Wv    = (const float*)d_in[8];
    const float* bv    = (const float*)d_in[9];
    const float* Wf    = (const float*)d_in[10];
    const float* bf    = (const float*)d_in[11];
    float*       out   = (float*)d_out;

    float *Qp, *Kp, *Vp, *WVp;
    int *kvS, *kvE, *qS, *qE;
    cudaGetSymbolAddress((void**)&Qp,  g_Q);
    cudaGetSymbolAddress((void**)&Kp,  g_K);
    cudaGetSymbolAddress((void**)&Vp,  g_V);
    cudaGetSymbolAddress((void**)&WVp, g_WV);
    cudaGetSymbolAddress((void**)&kvS, g_kv_start);
    cudaGetSymbolAddress((void**)&kvE, g_kv_end);
    cudaGetSymbolAddress((void**)&qS,  g_q_start);
    cudaGetSymbolAddress((void**)&qE,  g_q_end);

    cudaFuncSetAttribute(gemm_bf16x3, cudaFuncAttributeMaxDynamicSharedMemorySize, GEMM_SMEM);

    dim3 ggrid(D_QK / BN, TOTAL_Q / BM);   // (8, 32)

    gemm_bf16x3<<<ggrid, 256, GEMM_SMEM>>>(A,  Wq, bq, Qp, D_QK, Q_IN);
    gemm_bf16x3<<<ggrid, 256, GEMM_SMEM>>>(B0, Wk, bk, Kp, D_QK, KV_IN);
    gemm_bf16x3<<<ggrid, 256, GEMM_SMEM>>>(B0, Wv, bv, Vp, D_V,  KV_IN);

    seg_bounds_kernel<<<(TOTAL_KV + 255) / 256, 256>>>(seg_kv, TOTAL_KV, kvS, kvE);
    seg_bounds_kernel<<<(TOTAL_Q  + 255) / 256, 256>>>(seg_q,  TOTAL_Q,  qS,  qE);

    attn_kernel<<<dim3(N_HEADS, N_IMAGES, 8), 256>>>();

    gemm_bf16x3<<<ggrid, 256, GEMM_SMEM>>>(WVp, Wf, bf, out, Q_IN, D_V);
}

// round 6
// speedup vs baseline: 1.6326x; 1.0798x over previous
#include <cuda_runtime.h>
#include <cuda_bf16.h>
#include <cstdint>
#include <math.h>

// ---------------------------------------------------------------------------
// Problem constants
// ---------------------------------------------------------------------------
#define TOTAL_Q   2048
#define TOTAL_KV  2048
#define Q_IN      1024
#define KV_IN     1033
#define D_QK      1024
#define D_V       1024
#define N_HEADS   16
#define HEAD_DIM  64
#define N_IMAGES  32
#define SCALER    0.125f

#define KP_A 1024              // padded K (multiple of 32) for 1024-dim operands
#define KP_B 1056              // padded K for KV_IN = 1033

// ---------------------------------------------------------------------------
// Device scratch
// ---------------------------------------------------------------------------
__device__ float g_Q [TOTAL_Q  * D_QK];
__device__ float g_K [TOTAL_KV * D_QK];
__device__ float g_V [TOTAL_KV * D_V ];
__device__ int   g_kv_start[N_IMAGES], g_kv_end[N_IMAGES];
__device__ int   g_q_start [N_IMAGES], g_q_end [N_IMAGES];

__device__ __nv_bfloat16 g_Ahi [TOTAL_Q  * KP_A], g_Alo [TOTAL_Q  * KP_A];
__device__ __nv_bfloat16 g_B0hi[TOTAL_KV * KP_B], g_B0lo[TOTAL_KV * KP_B];
__device__ __nv_bfloat16 g_WVhi[TOTAL_Q  * KP_A], g_WVlo[TOTAL_Q  * KP_A];
__device__ __nv_bfloat16 g_WqThi[D_QK * KP_A], g_WqTlo[D_QK * KP_A];
__device__ __nv_bfloat16 g_WkThi[D_QK * KP_B], g_WkTlo[D_QK * KP_B];
__device__ __nv_bfloat16 g_WvThi[D_V  * KP_B], g_WvTlo[D_V  * KP_B];
__device__ __nv_bfloat16 g_WfThi[Q_IN * KP_A], g_WfTlo[Q_IN * KP_A];

// ---------------------------------------------------------------------------
// mma.sync helper (bf16 x bf16 -> f32, m16n8k16, A row-major, B col-major)
// ---------------------------------------------------------------------------
__device__ __forceinline__ void mma16816(float* c,
    uint32_t a0, uint32_t a1, uint32_t a2, uint32_t a3,
    uint32_t b0, uint32_t b1)
{
    asm volatile(
        "mma.sync.aligned.m16n8k16.row.col.f32.bf16.bf16.f32 "
        "{%0,%1,%2,%3}, {%4,%5,%6,%7}, {%8,%9}, {%0,%1,%2,%3};"
        : "+f"(c[0]), "+f"(c[1]), "+f"(c[2]), "+f"(c[3])
        : "r"(a0), "r"(a1), "r"(a2), "r"(a3), "r"(b0), "r"(b1));
}

__device__ __forceinline__ void split_bf16(float x, __nv_bfloat16& hi, __nv_bfloat16& lo)
{
    hi = __float2bfloat16(x);
    lo = __float2bfloat16(x - __bfloat162float(hi));
}

// ---------------------------------------------------------------------------
// Conversion: X[M,K] fp32 -> hi/lo bf16 [M,Kp] (zero-padded)
// ---------------------------------------------------------------------------
__global__ void convert_act(const float* __restrict__ X,
                            __nv_bfloat16* __restrict__ hi,
                            __nv_bfloat16* __restrict__ lo,
                            int M, int K, int Kp)
{
    int idx = blockIdx.x * blockDim.x + threadIdx.x;
    if (idx >= M * Kp) return;
    int m = idx / Kp, k = idx - m * Kp;
    float x = (k < K) ? X[(size_t)m * K + k] : 0.f;
    __nv_bfloat16 h, l;
    split_bf16(x, h, l);
    hi[idx] = h;
    lo[idx] = l;
}

// W[K,N] fp32 -> transposed hi/lo bf16 [N,Kp] (zero-padded)
__global__ void convert_wT(const float* __restrict__ W,
                           __nv_bfloat16* __restrict__ hiT,
                           __nv_bfloat16* __restrict__ loT,
                           int K, int N, int Kp)
{
    __shared__ float t[32][33];
    int k0 = blockIdx.x * 32, n0 = blockIdx.y * 32;
    int tx = threadIdx.x, ty = threadIdx.y;   // (32, 8)
#pragma unroll
    for (int i = 0; i < 4; i++) {
        int k = k0 + ty + i * 8;
        t[ty + i * 8][tx] = (k < K) ? W[(size_t)k * N + n0 + tx] : 0.f;
    }
    __syncthreads();
#pragma unroll
    for (int i = 0; i < 4; i++) {
        int n = n0 + ty + i * 8;
        float x = t[tx][ty + i * 8];
        __nv_bfloat16 h, l;
        split_bf16(x, h, l);
        size_t o = (size_t)n * Kp + k0 + tx;
        hiT[o] = h;
        loT[o] = l;
    }
}

// ---------------------------------------------------------------------------
// Split-bf16 (3-term) tensor-core GEMM on preconverted operands:
//   C[M,N] = (Ahi+Alo)[M,Kp] @ (Bhi+Blo)[N,Kp]^T + bias
//   using Ahi*Bhi + Ahi*Blo + Alo*Bhi.
// BM=64, BN=128, BK=32, 256 threads (8 warps, warp tile 16x64),
// double-buffered SMEM with register prefetch. Rows stride 40 bf16 (80B):
// conflict-free for all mma fragment load patterns.
// ---------------------------------------------------------------------------
#define BM 64
#define BN 128
#define BK 32
#define RSTRIDE 80                   // bytes per SMEM row (40 bf16)
#define AHI_OFF 0
#define ALO_OFF (64 * RSTRIDE)       // 5120
#define BHI_OFF (2 * 64 * RSTRIDE)   // 10240
#define BLO_OFF (BHI_OFF + 128 * RSTRIDE)
#define STAGE   (BLO_OFF + 128 * RSTRIDE)   // 30720
#define GEMM_SMEM (2 * STAGE)

__global__ __launch_bounds__(256, 2) void gemm_bf3(
    const __nv_bfloat16* __restrict__ Ahi, const __nv_bfloat16* __restrict__ Alo,
    const __nv_bfloat16* __restrict__ Bhi, const __nv_bfloat16* __restrict__ Blo,
    const float* __restrict__ bias, float* __restrict__ C,
    int N, int Kp)
{
    extern __shared__ char smc[];
    const int tid  = threadIdx.x;
    const int lane = tid & 31;
    const int wid  = tid >> 5;
    const int qid  = lane >> 2;   // 0..7
    const int tq   = lane & 3;    // 0..3
    const int warpM = wid & 3;    // 4 warps along M (16 rows each)
    const int warpN = wid >> 2;   // 2 warps along N (64 cols each)
    const int bm = blockIdx.y * BM;
    const int bn = blockIdx.x * BN;
    const int chunks = Kp / BK;

    const int ar   = tid >> 2;    // A row 0..63
    const int aseg = tid & 3;     // 8-bf16 segment

    float acc[8][4];
#pragma unroll
    for (int t = 0; t < 8; t++)
#pragma unroll
        for (int j = 0; j < 4; j++) acc[t][j] = 0.f;

    uint4 pa_hi, pa_lo, pb_hi[2], pb_lo[2];

    auto LOADG = [&](int c) {
        size_t ao = (size_t)(bm + ar) * Kp + c * BK + aseg * 8;
        pa_hi = *(const uint4*)&Ahi[ao];
        pa_lo = *(const uint4*)&Alo[ao];
#pragma unroll
        for (int i = 0; i < 2; i++) {
            int u = tid + i * 256;
            size_t bo = (size_t)(bn + (u >> 2)) * Kp + c * BK + (u & 3) * 8;
            pb_hi[i] = *(const uint4*)&Bhi[bo];
            pb_lo[i] = *(const uint4*)&Blo[bo];
        }
    };

    auto STORES = [&](int s) {
        char* base = smc + s * STAGE;
        uint32_t aoff = ar * RSTRIDE + aseg * 16;
        *(uint4*)(base + AHI_OFF + aoff) = pa_hi;
        *(uint4*)(base + ALO_OFF + aoff) = pa_lo;
#pragma unroll
        for (int i = 0; i < 2; i++) {
            int u = tid + i * 256;
            uint32_t boff = (u >> 2) * RSTRIDE + (u & 3) * 16;
            *(uint4*)(base + BHI_OFF + boff) = pb_hi[i];
            *(uint4*)(base + BLO_OFF + boff) = pb_lo[i];
        }
    };

    auto COMPUTE = [&](int s) {
        const char* base = smc + s * STAGE;
#pragma unroll
        for (int ks = 0; ks < 2; ks++) {
            const int cc = ks * 16 + tq * 2;     // bf16 col
            const int r0 = warpM * 16 + qid;
            uint32_t ah0 = *(const uint32_t*)(base + AHI_OFF + r0 * RSTRIDE + cc * 2);
            uint32_t ah1 = *(const uint32_t*)(base + AHI_OFF + (r0 + 8) * RSTRIDE + cc * 2);
            uint32_t ah2 = *(const uint32_t*)(base + AHI_OFF + r0 * RSTRIDE + (cc + 8) * 2);
            uint32_t ah3 = *(const uint32_t*)(base + AHI_OFF + (r0 + 8) * RSTRIDE + (cc + 8) * 2);
            uint32_t al0 = *(const uint32_t*)(base + ALO_OFF + r0 * RSTRIDE + cc * 2);
            uint32_t al1 = *(const uint32_t*)(base + ALO_OFF + (r0 + 8) * RSTRIDE + cc * 2);
            uint32_t al2 = *(const uint32_t*)(base + ALO_OFF + r0 * RSTRIDE + (cc + 8) * 2);
            uint32_t al3 = *(const uint32_t*)(base + ALO_OFF + (r0 + 8) * RSTRIDE + (cc + 8) * 2);
#pragma unroll
            for (int tn = 0; tn < 8; tn++) {
                const int nb = warpN * 64 + tn * 8 + qid;
                uint32_t bh0 = *(const uint32_t*)(base + BHI_OFF + nb * RSTRIDE + cc * 2);
                uint32_t bh1 = *(const uint32_t*)(base + BHI_OFF + nb * RSTRIDE + (cc + 8) * 2);
                uint32_t bl0 = *(const uint32_t*)(base + BLO_OFF + nb * RSTRIDE + cc * 2);
                uint32_t bl1 = *(const uint32_t*)(base + BLO_OFF + nb * RSTRIDE + (cc + 8) * 2);
                mma16816(acc[tn], ah0, ah1, ah2, ah3, bh0, bh1);
                mma16816(acc[tn], ah0, ah1, ah2, ah3, bl0, bl1);
                mma16816(acc[tn], al0, al1, al2, al3, bh0, bh1);
            }
        }
    };

    LOADG(0);
    STORES(0);
    __syncthreads();

    for (int c = 0; c < chunks; c++) {
        if (c + 1 < chunks) LOADG(c + 1);
        COMPUTE(c & 1);
        if (c + 1 < chunks) STORES((c + 1) & 1);
        __syncthreads();
    }

    // ---- epilogue: bias + store fp32 ----
    const int r0 = bm + warpM * 16 + qid;
#pragma unroll
    for (int tn = 0; tn < 8; tn++) {
        const int col = bn + warpN * 64 + tn * 8 + tq * 2;
        float2 b2 = *(const float2*)&bias[col];
        float2 v0 = make_float2(acc[tn][0] + b2.x, acc[tn][1] + b2.y);
        float2 v1 = make_float2(acc[tn][2] + b2.x, acc[tn][3] + b2.y);
        *(float2*)&C[(size_t)r0 * N + col]       = v0;
        *(float2*)&C[(size_t)(r0 + 8) * N + col] = v1;
    }
}

// ---------------------------------------------------------------------------
// Segment boundaries (contiguous ids)
// ---------------------------------------------------------------------------
__global__ void seg_bounds_kernel(const int* __restrict__ seg, int n,
                                  int* __restrict__ start, int* __restrict__ end)
{
    int i = blockIdx.x * blockDim.x + threadIdx.x;
    if (i >= n) return;
    int s = seg[i];
    if (i == 0     || seg[i - 1] != s) start[s] = i;
    if (i == n - 1 || seg[i + 1] != s) end[s]   = i + 1;
}

// ---------------------------------------------------------------------------
// Attention: block = (head, segment, qblock of 64 queries), 8 warps.
// K/V staged in SMEM in 64-row chunks; each warp owns up to 8 queries
// (online softmax, lane holds dims 2l, 2l+1).
// Output written directly as split bf16 hi/lo (feeds final GEMM).
// ---------------------------------------------------------------------------
__global__ __launch_bounds__(256) void attn_kernel()
{
    __shared__ float Ks[64 * 64];
    __shared__ float Vs[64 * 64];
    const int h  = blockIdx.x;
    const int s  = blockIdx.y;
    const int qb = blockIdx.z;
    const int k0 = g_kv_start[s], k1 = g_kv_end[s];
    const int qs = g_q_start[s],  qe = g_q_end[s];
    const int q0 = qs + qb * 64;
    const int q1 = min(qs + (qb + 1) * 64, qe);
    if (q0 >= q1) return;

    const int tid = threadIdx.x, wid = tid >> 5, lid = tid & 31;

    float2 qv[8], acc[8];
    float  m[8], den[8];
    int nq = 0;
#pragma unroll
    for (int j = 0; j < 8; j++) {
        int q = q0 + wid + 8 * j;
        if (q < q1) {
            nq = j + 1;
            qv[j] = *(const float2*)&g_Q[(size_t)q * D_QK + h * HEAD_DIM + 2 * lid];
        } else {
            qv[j] = make_float2(0.f, 0.f);
        }
        m[j] = -1e30f; den[j] = 0.f; acc[j] = make_float2(0.f, 0.f);
    }

    for (int kc = k0; kc < k1; kc += 64) {
        int cl = min(64, k1 - kc);
        __syncthreads();
        for (int f4 = tid; f4 < cl * 16; f4 += 256) {
            int kk = f4 >> 4, c4 = f4 & 15;
            *(float4*)&Ks[kk * 64 + c4 * 4] =
                *(const float4*)&g_K[(size_t)(kc + kk) * D_QK + h * HEAD_DIM + c4 * 4];
            *(float4*)&Vs[kk * 64 + c4 * 4] =
                *(const float4*)&g_V[(size_t)(kc + kk) * D_V + h * HEAD_DIM + c4 * 4];
        }
        __syncthreads();
        for (int kk = 0; kk < cl; kk++) {
            float2 kv = *(const float2*)&Ks[kk * 64 + 2 * lid];
            float2 vv = *(const float2*)&Vs[kk * 64 + 2 * lid];
#pragma unroll
            for (int j = 0; j < 8; j++) {
                if (j >= nq) break;
                float part = qv[j].x * kv.x + qv[j].y * kv.y;
#pragma unroll
                for (int o = 16; o; o >>= 1)
                    part += __shfl_xor_sync(0xffffffffu, part, o);
                float sc = part * SCALER;
                if (sc > m[j]) {
                    float corr = __expf(m[j] - sc);
                    den[j] = den[j] * corr + 1.f;
                    acc[j].x = acc[j].x * corr + vv.x;
                    acc[j].y = acc[j].y * corr + vv.y;
                    m[j] = sc;
                } else {
                    float p = __expf(sc - m[j]);
                    den[j] += p;
                    acc[j].x += p * vv.x;
                    acc[j].y += p * vv.y;
                }
            }
        }
    }

    for (int j = 0; j < nq; j++) {
        int q = q0 + wid + 8 * j;
        if (q < q1) {
            float inv = 1.f / den[j];
            float ox = acc[j].x * inv, oy = acc[j].y * inv;
            __nv_bfloat16 hx, lx, hy, ly;
            split_bf16(ox, hx, lx);
            split_bf16(oy, hy, ly);
            __nv_bfloat162 hv, lv;
            hv.x = hx; hv.y = hy;
            lv.x = lx; lv.y = ly;
            size_t o = (size_t)q * KP_A + h * HEAD_DIM + 2 * lid;
            *(__nv_bfloat162*)&g_WVhi[o] = hv;
            *(__nv_bfloat162*)&g_WVlo[o] = lv;
        }
    }
}

// ---------------------------------------------------------------------------
// Launch
// ---------------------------------------------------------------------------
extern "C" void kernel_launch(void* const* d_in, const int* in_sizes, int n_in,
                              void* d_out, int out_size)
{
    const float* A     = (const float*)d_in[0];
    const float* B0    = (const float*)d_in[1];
    const int*   seg_q = (const int*)  d_in[2];
    const int*   seg_kv= (const int*)  d_in[3];
    const float* Wq    = (const float*)d_in[4];
    const float* bq    = (const float*)d_in[5];
    const float* Wk    = (const float*)d_in[6];
    const float* bk    = (const float*)d_in[7];
    const float* Wv    = (const float*)d_in[8];
    const float* bv    = (const float*)d_in[9];
    const float* Wf    = (const float*)d_in[10];
    const float* bf    = (const float*)d_in[11];
    float*       out   = (float*)d_out;

    float *Qp, *Kp, *Vp;
    int *kvS, *kvE, *qS, *qE;
    __nv_bfloat16 *Ahi, *Alo, *B0hi, *B0lo, *WVhi, *WVlo;
    __nv_bfloat16 *WqThi, *WqTlo, *WkThi, *WkTlo, *WvThi, *WvTlo, *WfThi, *WfTlo;
    cudaGetSymbolAddress((void**)&Qp,  g_Q);
    cudaGetSymbolAddress((void**)&Kp,  g_K);
    cudaGetSymbolAddress((void**)&Vp,  g_V);
    cudaGetSymbolAddress((void**)&kvS, g_kv_start);
    cudaGetSymbolAddress((void**)&kvE, g_kv_end);
    cudaGetSymbolAddress((void**)&qS,  g_q_start);
    cudaGetSymbolAddress((void**)&qE,  g_q_end);
    cudaGetSymbolAddress((void**)&Ahi,  g_Ahi);  cudaGetSymbolAddress((void**)&Alo,  g_Alo);
    cudaGetSymbolAddress((void**)&B0hi, g_B0hi); cudaGetSymbolAddress((void**)&B0lo, g_B0lo);
    cudaGetSymbolAddress((void**)&WVhi, g_WVhi); cudaGetSymbolAddress((void**)&WVlo, g_WVlo);
    cudaGetSymbolAddress((void**)&WqThi, g_WqThi); cudaGetSymbolAddress((void**)&WqTlo, g_WqTlo);
    cudaGetSymbolAddress((void**)&WkThi, g_WkThi); cudaGetSymbolAddress((void**)&WkTlo, g_WkTlo);
    cudaGetSymbolAddress((void**)&WvThi, g_WvThi); cudaGetSymbolAddress((void**)&WvTlo, g_WvTlo);
    cudaGetSymbolAddress((void**)&WfThi, g_WfThi); cudaGetSymbolAddress((void**)&WfTlo, g_WfTlo);

    cudaFuncSetAttribute(gemm_bf3, cudaFuncAttributeMaxDynamicSharedMemorySize, GEMM_SMEM);

    // Segment bounds (independent; run first)
    seg_bounds_kernel<<<(TOTAL_KV + 255) / 256, 256>>>(seg_kv, TOTAL_KV, kvS, kvE);
    seg_bounds_kernel<<<(TOTAL_Q  + 255) / 256, 256>>>(seg_q,  TOTAL_Q,  qS,  qE);

    // Preconversion passes
    dim3 wb(32, 8);
    convert_act<<<(TOTAL_Q  * KP_A + 255) / 256, 256>>>(A,  Ahi,  Alo,  TOTAL_Q,  Q_IN,  KP_A);
    convert_act<<<(TOTAL_KV * KP_B + 255) / 256, 256>>>(B0, B0hi, B0lo, TOTAL_KV, KV_IN, KP_B);
    convert_wT<<<dim3(KP_A / 32, D_QK / 32), wb>>>(Wq, WqThi, WqTlo, Q_IN,  D_QK, KP_A);
    convert_wT<<<dim3(KP_B / 32, D_QK / 32), wb>>>(Wk, WkThi, WkTlo, KV_IN, D_QK, KP_B);
    convert_wT<<<dim3(KP_B / 32, D_V  / 32), wb>>>(Wv, WvThi, WvTlo, KV_IN, D_V,  KP_B);
    convert_wT<<<dim3(KP_A / 32, Q_IN / 32), wb>>>(Wf, WfThi, WfTlo, D_V,   Q_IN, KP_A);

    // Projections (tensor-core split-bf16, preconverted operands)
    dim3 ggrid(D_QK / BN, TOTAL_Q / BM);   // (8, 32)
    gemm_bf3<<<ggrid, 256, GEMM_SMEM>>>(Ahi,  Alo,  WqThi, WqTlo, bq, Qp, D_QK, KP_A);
    gemm_bf3<<<ggrid, 256, GEMM_SMEM>>>(B0hi, B0lo, WkThi, WkTlo, bk, Kp, D_QK, KP_B);
    gemm_bf3<<<ggrid, 256, GEMM_SMEM>>>(B0hi, B0lo, WvThi, WvTlo, bv, Vp, D_V,  KP_B);

    // Attention (writes split-bf16 WV directly)
    attn_kernel<<<dim3(N_HEADS, N_IMAGES, 8), 256>>>();

    // Output projection -> d_out
    gemm_bf3<<<ggrid, 256, GEMM_SMEM>>>(WVhi, WVlo, WfThi, WfTlo, bf, out, Q_IN, KP_A);
}

// round 7
// speedup vs baseline: 1.7937x; 1.0986x over previous
#include <cuda_runtime.h>
#include <cuda_bf16.h>
#include <cstdint>
#include <math.h>

// ---------------------------------------------------------------------------
// Problem constants
// ---------------------------------------------------------------------------
#define TOTAL_Q   2048
#define TOTAL_KV  2048
#define Q_IN      1024
#define KV_IN     1033
#define D_QK      1024
#define D_V       1024
#define N_HEADS   16
#define HEAD_DIM  64
#define N_IMAGES  32
#define SCALER    0.125f

#define KP_A 1024
#define KP_B 1056

// ---------------------------------------------------------------------------
// Device scratch
// ---------------------------------------------------------------------------
__device__ float g_Q [TOTAL_Q  * D_QK];
__device__ float g_K [TOTAL_KV * D_QK];
__device__ float g_V [TOTAL_KV * D_V ];
__device__ int   g_kv_start[N_IMAGES], g_kv_end[N_IMAGES];
__device__ int   g_q_start [N_IMAGES], g_q_end [N_IMAGES];

__device__ __nv_bfloat16 g_Ahi [TOTAL_Q  * KP_A], g_Alo [TOTAL_Q  * KP_A];
__device__ __nv_bfloat16 g_B0hi[TOTAL_KV * KP_B], g_B0lo[TOTAL_KV * KP_B];
__device__ __nv_bfloat16 g_WVhi[TOTAL_Q  * KP_A], g_WVlo[TOTAL_Q  * KP_A];
__device__ __nv_bfloat16 g_WqThi[D_QK * KP_A], g_WqTlo[D_QK * KP_A];
__device__ __nv_bfloat16 g_WkThi[D_QK * KP_B], g_WkTlo[D_QK * KP_B];
__device__ __nv_bfloat16 g_WvThi[D_V  * KP_B], g_WvTlo[D_V  * KP_B];
__device__ __nv_bfloat16 g_WfThi[Q_IN * KP_A], g_WfTlo[Q_IN * KP_A];

// ---------------------------------------------------------------------------
// PTX helpers
// ---------------------------------------------------------------------------
__device__ __forceinline__ uint32_t smem_u32(const void* p) {
    uint32_t a;
    asm("{ .reg .u64 t; cvta.to.shared.u64 t, %1; cvt.u32.u64 %0, t; }" : "=r"(a) : "l"(p));
    return a;
}
__device__ __forceinline__ void mma16816(float* c,
    uint32_t a0, uint32_t a1, uint32_t a2, uint32_t a3,
    uint32_t b0, uint32_t b1)
{
    asm volatile(
        "mma.sync.aligned.m16n8k16.row.col.f32.bf16.bf16.f32 "
        "{%0,%1,%2,%3}, {%4,%5,%6,%7}, {%8,%9}, {%0,%1,%2,%3};"
        : "+f"(c[0]), "+f"(c[1]), "+f"(c[2]), "+f"(c[3])
        : "r"(a0), "r"(a1), "r"(a2), "r"(a3), "r"(b0), "r"(b1));
}
__device__ __forceinline__ void ldsm4(uint32_t& r0, uint32_t& r1, uint32_t& r2, uint32_t& r3,
                                      uint32_t addr)
{
    asm volatile("ldmatrix.sync.aligned.m8n8.x4.shared.b16 {%0,%1,%2,%3}, [%4];"
                 : "=r"(r0), "=r"(r1), "=r"(r2), "=r"(r3) : "r"(addr));
}
__device__ __forceinline__ void cp16(uint32_t dst, const void* src)
{
    asm volatile("cp.async.cg.shared.global [%0], [%1], 16;" :: "r"(dst), "l"(src) : "memory");
}
__device__ __forceinline__ void cp_commit() { asm volatile("cp.async.commit_group;" ::: "memory"); }
__device__ __forceinline__ void cp_wait0()  { asm volatile("cp.async.wait_group 0;"  ::: "memory"); }

__device__ __forceinline__ void split_bf16(float x, __nv_bfloat16& hi, __nv_bfloat16& lo)
{
    hi = __float2bfloat16(x);
    lo = __float2bfloat16(x - __bfloat162float(hi));
}

// ---------------------------------------------------------------------------
// Conversion kernels
// ---------------------------------------------------------------------------
__global__ void convert_act(const float* __restrict__ X,
                            __nv_bfloat16* __restrict__ hi,
                            __nv_bfloat16* __restrict__ lo,
                            int M, int K, int Kp)
{
    int idx = blockIdx.x * blockDim.x + threadIdx.x;
    if (idx >= M * Kp) return;
    int m = idx / Kp, k = idx - m * Kp;
    float x = (k < K) ? X[(size_t)m * K + k] : 0.f;
    __nv_bfloat16 h, l;
    split_bf16(x, h, l);
    hi[idx] = h;
    lo[idx] = l;
}

__global__ void convert_wT(const float* __restrict__ W,
                           __nv_bfloat16* __restrict__ hiT,
                           __nv_bfloat16* __restrict__ loT,
                           int K, int N, int Kp)
{
    __shared__ float t[32][33];
    int k0 = blockIdx.x * 32, n0 = blockIdx.y * 32;
    int tx = threadIdx.x, ty = threadIdx.y;   // (32, 8)
#pragma unroll
    for (int i = 0; i < 4; i++) {
        int k = k0 + ty + i * 8;
        t[ty + i * 8][tx] = (k < K) ? W[(size_t)k * N + n0 + tx] : 0.f;
    }
    __syncthreads();
#pragma unroll
    for (int i = 0; i < 4; i++) {
        int n = n0 + ty + i * 8;
        float x = t[tx][ty + i * 8];
        __nv_bfloat16 h, l;
        split_bf16(x, h, l);
        size_t o = (size_t)n * Kp + k0 + tx;
        hiT[o] = h;
        loT[o] = l;
    }
}

// ---------------------------------------------------------------------------
// Split-bf16 (3-term) tensor-core GEMM, ldmatrix + cp.async version
//   C[M,N] = (Ahi+Alo)[M,Kp] @ (Bhi+Blo)[N,Kp]^T + bias
// BM=64, BN=128, BK=32, 256 threads, warp tile 16x64, 2-stage cp.async pipe.
// SMEM row stride 80B -> conflict-free ldmatrix row addressing.
// ---------------------------------------------------------------------------
#define BM 64
#define BN 128
#define BK 32
#define RSTRIDE 80
#define AHI_OFF 0
#define ALO_OFF (64 * RSTRIDE)
#define BHI_OFF (2 * 64 * RSTRIDE)
#define BLO_OFF (BHI_OFF + 128 * RSTRIDE)
#define STAGE   (BLO_OFF + 128 * RSTRIDE)   // 30720
#define GEMM_SMEM (2 * STAGE)

__global__ __launch_bounds__(256, 2) void gemm_bf3(
    const __nv_bfloat16* __restrict__ Ahi, const __nv_bfloat16* __restrict__ Alo,
    const __nv_bfloat16* __restrict__ Bhi, const __nv_bfloat16* __restrict__ Blo,
    const float* __restrict__ bias, float* __restrict__ C,
    int N, int Kp)
{
    extern __shared__ char smc[];
    const uint32_t sb = smem_u32(smc);
    const int tid  = threadIdx.x;
    const int lane = tid & 31;
    const int wid  = tid >> 5;
    const int qid  = lane >> 2;
    const int tq   = lane & 3;
    const int warpM = wid & 3;
    const int warpN = wid >> 2;
    const int bm = blockIdx.y * BM;
    const int bn = blockIdx.x * BN;
    const int chunks = Kp / BK;

    const int ar   = tid >> 2;
    const int aseg = tid & 3;

    // ldmatrix per-lane base offsets (within a stage)
    const uint32_t g = lane >> 3;
    const uint32_t aOff = AHI_OFF
        + (warpM * 16 + (g & 1) * 8 + (lane & 7)) * RSTRIDE + ((g >> 1) * 8) * 2;
    const uint32_t bOff = BHI_OFF
        + (warpN * 64 + (g >> 1) * 8 + (lane & 7)) * RSTRIDE + ((g & 1) * 8) * 2;

    float acc[8][4];
#pragma unroll
    for (int t = 0; t < 8; t++)
#pragma unroll
        for (int j = 0; j < 4; j++) acc[t][j] = 0.f;

    auto PREFETCH = [&](int c, int s) {
        uint32_t stb = sb + s * STAGE;
        size_t ao = (size_t)(bm + ar) * Kp + c * BK + aseg * 8;
        uint32_t ad = stb + ar * RSTRIDE + aseg * 16;
        cp16(ad + AHI_OFF, &Ahi[ao]);
        cp16(ad + ALO_OFF, &Alo[ao]);
#pragma unroll
        for (int i = 0; i < 2; i++) {
            int u = tid + i * 256;
            size_t bo = (size_t)(bn + (u >> 2)) * Kp + c * BK + (u & 3) * 8;
            uint32_t bd = stb + (u >> 2) * RSTRIDE + (u & 3) * 16;
            cp16(bd + BHI_OFF, &Bhi[bo]);
            cp16(bd + BLO_OFF, &Blo[bo]);
        }
        cp_commit();
    };

    auto COMPUTE = [&](int s) {
        uint32_t stb = sb + s * STAGE;
#pragma unroll
        for (int ks = 0; ks < 2; ks++) {
            uint32_t ka = stb + aOff + ks * 32;
            uint32_t ah0, ah1, ah2, ah3, al0, al1, al2, al3;
            ldsm4(ah0, ah1, ah2, ah3, ka);
            ldsm4(al0, al1, al2, al3, ka + (ALO_OFF - AHI_OFF));
#pragma unroll
            for (int p = 0; p < 4; p++) {
                uint32_t kb = stb + bOff + p * (16 * RSTRIDE) + ks * 32;
                uint32_t bh0, bh1, bh2, bh3, bl0, bl1, bl2, bl3;
                ldsm4(bh0, bh1, bh2, bh3, kb);
                ldsm4(bl0, bl1, bl2, bl3, kb + (BLO_OFF - BHI_OFF));
                mma16816(acc[p * 2],     ah0, ah1, ah2, ah3, bh0, bh1);
                mma16816(acc[p * 2],     ah0, ah1, ah2, ah3, bl0, bl1);
                mma16816(acc[p * 2],     al0, al1, al2, al3, bh0, bh1);
                mma16816(acc[p * 2 + 1], ah0, ah1, ah2, ah3, bh2, bh3);
                mma16816(acc[p * 2 + 1], ah0, ah1, ah2, ah3, bl2, bl3);
                mma16816(acc[p * 2 + 1], al0, al1, al2, al3, bh2, bh3);
            }
        }
    };

    PREFETCH(0, 0);
    cp_wait0();
    __syncthreads();

    for (int c = 0; c < chunks; c++) {
        int s = c & 1;
        if (c + 1 < chunks) PREFETCH(c + 1, s ^ 1);
        COMPUTE(s);
        if (c + 1 < chunks) cp_wait0();
        __syncthreads();
    }

    // ---- epilogue: bias + store fp32 ----
    const int r0 = bm + warpM * 16 + qid;
#pragma unroll
    for (int tn = 0; tn < 8; tn++) {
        const int col = bn + warpN * 64 + tn * 8 + tq * 2;
        float2 b2 = *(const float2*)&bias[col];
        float2 v0 = make_float2(acc[tn][0] + b2.x, acc[tn][1] + b2.y);
        float2 v1 = make_float2(acc[tn][2] + b2.x, acc[tn][3] + b2.y);
        *(float2*)&C[(size_t)r0 * N + col]       = v0;
        *(float2*)&C[(size_t)(r0 + 8) * N + col] = v1;
    }
}

// ---------------------------------------------------------------------------
// Segment boundaries
// ---------------------------------------------------------------------------
__global__ void seg_bounds_kernel(const int* __restrict__ seg, int n,
                                  int* __restrict__ start, int* __restrict__ end)
{
    int i = blockIdx.x * blockDim.x + threadIdx.x;
    if (i >= n) return;
    int s = seg[i];
    if (i == 0     || seg[i - 1] != s) start[s] = i;
    if (i == n - 1 || seg[i + 1] != s) end[s]   = i + 1;
}

// ---------------------------------------------------------------------------
// Attention (unchanged from round 6; writes split-bf16 WV directly)
// ---------------------------------------------------------------------------
__global__ __launch_bounds__(256) void attn_kernel()
{
    __shared__ float Ks[64 * 64];
    __shared__ float Vs[64 * 64];
    const int h  = blockIdx.x;
    const int s  = blockIdx.y;
    const int qb = blockIdx.z;
    const int k0 = g_kv_start[s], k1 = g_kv_end[s];
    const int qs = g_q_start[s],  qe = g_q_end[s];
    const int q0 = qs + qb * 64;
    const int q1 = min(qs + (qb + 1) * 64, qe);
    if (q0 >= q1) return;

    const int tid = threadIdx.x, wid = tid >> 5, lid = tid & 31;

    float2 qv[8], acc[8];
    float  m[8], den[8];
    int nq = 0;
#pragma unroll
    for (int j = 0; j < 8; j++) {
        int q = q0 + wid + 8 * j;
        if (q < q1) {
            nq = j + 1;
            qv[j] = *(const float2*)&g_Q[(size_t)q * D_QK + h * HEAD_DIM + 2 * lid];
        } else {
            qv[j] = make_float2(0.f, 0.f);
        }
        m[j] = -1e30f; den[j] = 0.f; acc[j] = make_float2(0.f, 0.f);
    }

    for (int kc = k0; kc < k1; kc += 64) {
        int cl = min(64, k1 - kc);
        __syncthreads();
        for (int f4 = tid; f4 < cl * 16; f4 += 256) {
            int kk = f4 >> 4, c4 = f4 & 15;
            *(float4*)&Ks[kk * 64 + c4 * 4] =
                *(const float4*)&g_K[(size_t)(kc + kk) * D_QK + h * HEAD_DIM + c4 * 4];
            *(float4*)&Vs[kk * 64 + c4 * 4] =
                *(const float4*)&g_V[(size_t)(kc + kk) * D_V + h * HEAD_DIM + c4 * 4];
        }
        __syncthreads();
        for (int kk = 0; kk < cl; kk++) {
            float2 kv = *(const float2*)&Ks[kk * 64 + 2 * lid];
            float2 vv = *(const float2*)&Vs[kk * 64 + 2 * lid];
#pragma unroll
            for (int j = 0; j < 8; j++) {
                if (j >= nq) break;
                float part = qv[j].x * kv.x + qv[j].y * kv.y;
#pragma unroll
                for (int o = 16; o; o >>= 1)
                    part += __shfl_xor_sync(0xffffffffu, part, o);
                float sc = part * SCALER;
                if (sc > m[j]) {
                    float corr = __expf(m[j] - sc);
                    den[j] = den[j] * corr + 1.f;
                    acc[j].x = acc[j].x * corr + vv.x;
                    acc[j].y = acc[j].y * corr + vv.y;
                    m[j] = sc;
                } else {
                    float p = __expf(sc - m[j]);
                    den[j] += p;
                    acc[j].x += p * vv.x;
                    acc[j].y += p * vv.y;
                }
            }
        }
    }

    for (int j = 0; j < nq; j++) {
        int q = q0 + wid + 8 * j;
        if (q < q1) {
            float inv = 1.f / den[j];
            float ox = acc[j].x * inv, oy = acc[j].y * inv;
            __nv_bfloat16 hx, lx, hy, ly;
            split_bf16(ox, hx, lx);
            split_bf16(oy, hy, ly);
            __nv_bfloat162 hv, lv;
            hv.x = hx; hv.y = hy;
            lv.x = lx; lv.y = ly;
            size_t o = (size_t)q * KP_A + h * HEAD_DIM + 2 * lid;
            *(__nv_bfloat162*)&g_WVhi[o] = hv;
            *(__nv_bfloat162*)&g_WVlo[o] = lv;
        }
    }
}

// ---------------------------------------------------------------------------
// Launch
// ---------------------------------------------------------------------------
extern "C" void kernel_launch(void* const* d_in, const int* in_sizes, int n_in,
                              void* d_out, int out_size)
{
    const float* A     = (const float*)d_in[0];
    const float* B0    = (const float*)d_in[1];
    const int*   seg_q = (const int*)  d_in[2];
    const int*   seg_kv= (const int*)  d_in[3];
    const float* Wq    = (const float*)d_in[4];
    const float* bq    = (const float*)d_in[5];
    const float* Wk    = (const float*)d_in[6];
    const float* bk    = (const float*)d_in[7];
    const float* Wv    = (const float*)d_in[8];
    const float* bv    = (const float*)d_in[9];
    const float* Wf    = (const float*)d_in[10];
    const float* bf    = (const float*)d_in[11];
    float*       out   = (float*)d_out;

    float *Qp, *Kp, *Vp;
    int *kvS, *kvE, *qS, *qE;
    __nv_bfloat16 *Ahi, *Alo, *B0hi, *B0lo, *WVhi, *WVlo;
    __nv_bfloat16 *WqThi, *WqTlo, *WkThi, *WkTlo, *WvThi, *WvTlo, *WfThi, *WfTlo;
    cudaGetSymbolAddress((void**)&Qp,  g_Q);
    cudaGetSymbolAddress((void**)&Kp,  g_K);
    cudaGetSymbolAddress((void**)&Vp,  g_V);
    cudaGetSymbolAddress((void**)&kvS, g_kv_start);
    cudaGetSymbolAddress((void**)&kvE, g_kv_end);
    cudaGetSymbolAddress((void**)&qS,  g_q_start);
    cudaGetSymbolAddress((void**)&qE,  g_q_end);
    cudaGetSymbolAddress((void**)&Ahi,  g_Ahi);  cudaGetSymbolAddress((void**)&Alo,  g_Alo);
    cudaGetSymbolAddress((void**)&B0hi, g_B0hi); cudaGetSymbolAddress((void**)&B0lo, g_B0lo);
    cudaGetSymbolAddress((void**)&WVhi, g_WVhi); cudaGetSymbolAddress((void**)&WVlo, g_WVlo);
    cudaGetSymbolAddress((void**)&WqThi, g_WqThi); cudaGetSymbolAddress((void**)&WqTlo, g_WqTlo);
    cudaGetSymbolAddress((void**)&WkThi, g_WkThi); cudaGetSymbolAddress((void**)&WkTlo, g_WkTlo);
    cudaGetSymbolAddress((void**)&WvThi, g_WvThi); cudaGetSymbolAddress((void**)&WvTlo, g_WvTlo);
    cudaGetSymbolAddress((void**)&WfThi, g_WfThi); cudaGetSymbolAddress((void**)&WfTlo, g_WfTlo);

    cudaFuncSetAttribute(gemm_bf3, cudaFuncAttributeMaxDynamicSharedMemorySize, GEMM_SMEM);

    seg_bounds_kernel<<<(TOTAL_KV + 255) / 256, 256>>>(seg_kv, TOTAL_KV, kvS, kvE);
    seg_bounds_kernel<<<(TOTAL_Q  + 255) / 256, 256>>>(seg_q,  TOTAL_Q,  qS,  qE);

    dim3 wb(32, 8);
    convert_act<<<(TOTAL_Q  * KP_A + 255) / 256, 256>>>(A,  Ahi,  Alo,  TOTAL_Q,  Q_IN,  KP_A);
    convert_act<<<(TOTAL_KV * KP_B + 255) / 256, 256>>>(B0, B0hi, B0lo, TOTAL_KV, KV_IN, KP_B);
    convert_wT<<<dim3(KP_A / 32, D_QK / 32), wb>>>(Wq, WqThi, WqTlo, Q_IN,  D_QK, KP_A);
    convert_wT<<<dim3(KP_B / 32, D_QK / 32), wb>>>(Wk, WkThi, WkTlo, KV_IN, D_QK, KP_B);
    convert_wT<<<dim3(KP_B / 32, D_V  / 32), wb>>>(Wv, WvThi, WvTlo, KV_IN, D_V,  KP_B);
    convert_wT<<<dim3(KP_A / 32, Q_IN / 32), wb>>>(Wf, WfThi, WfTlo, D_V,   Q_IN, KP_A);

    dim3 ggrid(D_QK / BN, TOTAL_Q / BM);   // (8, 32)
    gemm_bf3<<<ggrid, 256, GEMM_SMEM>>>(Ahi,  Alo,  WqThi, WqTlo, bq, Qp, D_QK, KP_A);
    gemm_bf3<<<ggrid, 256, GEMM_SMEM>>>(B0hi, B0lo, WkThi, WkTlo, bk, Kp, D_QK, KP_B);
    gemm_bf3<<<ggrid, 256, GEMM_SMEM>>>(B0hi, B0lo, WvThi, WvTlo, bv, Vp, D_V,  KP_B);

    attn_kernel<<<dim3(N_HEADS, N_IMAGES, 8), 256>>>();

    gemm_bf3<<<ggrid, 256, GEMM_SMEM>>>(WVhi, WVlo, WfThi, WfTlo, bf, out, Q_IN, KP_A);
}

// round 8
// speedup vs baseline: 1.9757x; 1.1015x over previous
#include <cuda_runtime.h>
#include <cuda_fp16.h>
#include <cstdint>
#include <math.h>

// ---------------------------------------------------------------------------
// Problem constants
// ---------------------------------------------------------------------------
#define TOTAL_Q   2048
#define TOTAL_KV  2048
#define Q_IN      1024
#define KV_IN     1033
#define D_QK      1024
#define D_V       1024
#define N_HEADS   16
#define HEAD_DIM  64
#define N_IMAGES  32
#define SCALER    0.125f

#define KP_A 1024
#define KP_B 1056

// ---------------------------------------------------------------------------
// Device scratch
// ---------------------------------------------------------------------------
__device__ float g_Q [TOTAL_Q  * D_QK];
__device__ float g_K [TOTAL_KV * D_QK];
__device__ float g_V [TOTAL_KV * D_V ];
__device__ int   g_kv_start[N_IMAGES], g_kv_end[N_IMAGES];
__device__ int   g_q_start [N_IMAGES], g_q_end [N_IMAGES];

__device__ __half g_Ah  [TOTAL_Q  * KP_A];
__device__ __half g_B0h [TOTAL_KV * KP_B];
__device__ __half g_WVh [TOTAL_Q  * KP_A];
__device__ __half g_WqThi[D_QK * KP_A], g_WqTlo[D_QK * KP_A];
__device__ __half g_WkThi[D_QK * KP_B], g_WkTlo[D_QK * KP_B];
__device__ __half g_WvThi[D_V  * KP_B], g_WvTlo[D_V  * KP_B];
__device__ __half g_WfThi[Q_IN * KP_A], g_WfTlo[Q_IN * KP_A];

// ---------------------------------------------------------------------------
// PTX helpers
// ---------------------------------------------------------------------------
__device__ __forceinline__ uint32_t smem_u32(const void* p) {
    uint32_t a;
    asm("{ .reg .u64 t; cvta.to.shared.u64 t, %1; cvt.u32.u64 %0, t; }" : "=r"(a) : "l"(p));
    return a;
}
__device__ __forceinline__ void mma16816h(float* c,
    uint32_t a0, uint32_t a1, uint32_t a2, uint32_t a3,
    uint32_t b0, uint32_t b1)
{
    asm volatile(
        "mma.sync.aligned.m16n8k16.row.col.f32.f16.f16.f32 "
        "{%0,%1,%2,%3}, {%4,%5,%6,%7}, {%8,%9}, {%0,%1,%2,%3};"
        : "+f"(c[0]), "+f"(c[1]), "+f"(c[2]), "+f"(c[3])
        : "r"(a0), "r"(a1), "r"(a2), "r"(a3), "r"(b0), "r"(b1));
}
__device__ __forceinline__ void ldsm4(uint32_t& r0, uint32_t& r1, uint32_t& r2, uint32_t& r3,
                                      uint32_t addr)
{
    asm volatile("ldmatrix.sync.aligned.m8n8.x4.shared.b16 {%0,%1,%2,%3}, [%4];"
                 : "=r"(r0), "=r"(r1), "=r"(r2), "=r"(r3) : "r"(addr));
}
__device__ __forceinline__ void cp16(uint32_t dst, const void* src)
{
    asm volatile("cp.async.cg.shared.global [%0], [%1], 16;" :: "r"(dst), "l"(src) : "memory");
}
__device__ __forceinline__ void cp_commit() { asm volatile("cp.async.commit_group;" ::: "memory"); }
__device__ __forceinline__ void cp_wait0()  { asm volatile("cp.async.wait_group 0;"  ::: "memory"); }

__device__ __forceinline__ void split_fp16(float x, __half& hi, __half& lo)
{
    hi = __float2half(x);
    lo = __float2half(x - __half2float(hi));
}

// ---------------------------------------------------------------------------
// Conversion kernels
// ---------------------------------------------------------------------------
// X[M,K] fp32 -> fp16 [M,Kp] (zero-padded)
__global__ void convert_act_h(const float* __restrict__ X,
                              __half* __restrict__ H,
                              int M, int K, int Kp)
{
    int idx = blockIdx.x * blockDim.x + threadIdx.x;
    if (idx >= M * Kp) return;
    int m = idx / Kp, k = idx - m * Kp;
    float x = (k < K) ? X[(size_t)m * K + k] : 0.f;
    H[idx] = __float2half(x);
}

// W[K,N] fp32 -> transposed hi/lo fp16 [N,Kp] (zero-padded)
__global__ void convert_wT_h(const float* __restrict__ W,
                             __half* __restrict__ hiT,
                             __half* __restrict__ loT,
                             int K, int N, int Kp)
{
    __shared__ float t[32][33];
    int k0 = blockIdx.x * 32, n0 = blockIdx.y * 32;
    int tx = threadIdx.x, ty = threadIdx.y;   // (32, 8)
#pragma unroll
    for (int i = 0; i < 4; i++) {
        int k = k0 + ty + i * 8;
        t[ty + i * 8][tx] = (k < K) ? W[(size_t)k * N + n0 + tx] : 0.f;
    }
    __syncthreads();
#pragma unroll
    for (int i = 0; i < 4; i++) {
        int n = n0 + ty + i * 8;
        float x = t[tx][ty + i * 8];
        __half h, l;
        split_fp16(x, h, l);
        size_t o = (size_t)n * Kp + k0 + tx;
        hiT[o] = h;
        loT[o] = l;
    }
}

// ---------------------------------------------------------------------------
// fp16 2-term tensor-core GEMM:
//   C[M,N] = Ah[M,Kp] @ (Whi+Wlo)[N,Kp]^T + bias
// BM=64, BN=128, BK=32, 256 threads, warp tile 16x64, 2-stage cp.async pipe,
// ldmatrix fragment loads. SMEM row stride 80B (conflict-free).
// ---------------------------------------------------------------------------
#define BM 64
#define BN 128
#define BK 32
#define RSTRIDE 80
#define A_OFF   0
#define BHI_OFF (64 * RSTRIDE)                 // 5120
#define BLO_OFF (BHI_OFF + 128 * RSTRIDE)      // 15360
#define STAGE   (BLO_OFF + 128 * RSTRIDE)      // 25600
#define GEMM_SMEM (2 * STAGE)                  // 51200

__global__ __launch_bounds__(256, 2) void gemm_fp16x2(
    const __half* __restrict__ Ah,
    const __half* __restrict__ Bhi, const __half* __restrict__ Blo,
    const float* __restrict__ bias, float* __restrict__ C,
    int N, int Kp)
{
    extern __shared__ char smc[];
    const uint32_t sb = smem_u32(smc);
    const int tid  = threadIdx.x;
    const int lane = tid & 31;
    const int wid  = tid >> 5;
    const int qid  = lane >> 2;
    const int tq   = lane & 3;
    const int warpM = wid & 3;
    const int warpN = wid >> 2;
    const int bm = blockIdx.y * BM;
    const int bn = blockIdx.x * BN;
    const int chunks = Kp / BK;

    const int ar   = tid >> 2;    // 0..63
    const int aseg = tid & 3;     // 0..3

    const uint32_t g = lane >> 3;
    const uint32_t aOff = A_OFF
        + (warpM * 16 + (g & 1) * 8 + (lane & 7)) * RSTRIDE + ((g >> 1) * 8) * 2;
    const uint32_t bOff = BHI_OFF
        + (warpN * 64 + (g >> 1) * 8 + (lane & 7)) * RSTRIDE + ((g & 1) * 8) * 2;

    float acc[8][4];
#pragma unroll
    for (int t = 0; t < 8; t++)
#pragma unroll
        for (int j = 0; j < 4; j++) acc[t][j] = 0.f;

    auto PREFETCH = [&](int c, int s) {
        uint32_t stb = sb + s * STAGE;
        size_t ao = (size_t)(bm + ar) * Kp + c * BK + aseg * 8;
        cp16(stb + A_OFF + ar * RSTRIDE + aseg * 16, &Ah[ao]);
#pragma unroll
        for (int i = 0; i < 2; i++) {
            int u = tid + i * 256;
            size_t bo = (size_t)(bn + (u >> 2)) * Kp + c * BK + (u & 3) * 8;
            uint32_t bd = stb + (u >> 2) * RSTRIDE + (u & 3) * 16;
            cp16(bd + BHI_OFF, &Bhi[bo]);
            cp16(bd + BLO_OFF, &Blo[bo]);
        }
        cp_commit();
    };

    auto COMPUTE = [&](int s) {
        uint32_t stb = sb + s * STAGE;
#pragma unroll
        for (int ks = 0; ks < 2; ks++) {
            uint32_t ka = stb + aOff + ks * 32;
            uint32_t a0, a1, a2, a3;
            ldsm4(a0, a1, a2, a3, ka);
#pragma unroll
            for (int p = 0; p < 4; p++) {
                uint32_t kb = stb + bOff + p * (16 * RSTRIDE) + ks * 32;
                uint32_t bh0, bh1, bh2, bh3, bl0, bl1, bl2, bl3;
                ldsm4(bh0, bh1, bh2, bh3, kb);
                ldsm4(bl0, bl1, bl2, bl3, kb + (BLO_OFF - BHI_OFF));
                mma16816h(acc[p * 2],     a0, a1, a2, a3, bh0, bh1);
                mma16816h(acc[p * 2],     a0, a1, a2, a3, bl0, bl1);
                mma16816h(acc[p * 2 + 1], a0, a1, a2, a3, bh2, bh3);
                mma16816h(acc[p * 2 + 1], a0, a1, a2, a3, bl2, bl3);
            }
        }
    };

    PREFETCH(0, 0);
    cp_wait0();
    __syncthreads();

    for (int c = 0; c < chunks; c++) {
        int s = c & 1;
        if (c + 1 < chunks) PREFETCH(c + 1, s ^ 1);
        COMPUTE(s);
        if (c + 1 < chunks) cp_wait0();
        __syncthreads();
    }

    // ---- epilogue: bias + store fp32 ----
    const int r0 = bm + warpM * 16 + qid;
#pragma unroll
    for (int tn = 0; tn < 8; tn++) {
        const int col = bn + warpN * 64 + tn * 8 + tq * 2;
        float2 b2 = *(const float2*)&bias[col];
        float2 v0 = make_float2(acc[tn][0] + b2.x, acc[tn][1] + b2.y);
        float2 v1 = make_float2(acc[tn][2] + b2.x, acc[tn][3] + b2.y);
        *(float2*)&C[(size_t)r0 * N + col]       = v0;
        *(float2*)&C[(size_t)(r0 + 8) * N + col] = v1;
    }
}

// ---------------------------------------------------------------------------
// Segment boundaries
// ---------------------------------------------------------------------------
__global__ void seg_bounds_kernel(const int* __restrict__ seg, int n,
                                  int* __restrict__ start, int* __restrict__ end)
{
    int i = blockIdx.x * blockDim.x + threadIdx.x;
    if (i >= n) return;
    int s = seg[i];
    if (i == 0     || seg[i - 1] != s) start[s] = i;
    if (i == n - 1 || seg[i + 1] != s) end[s]   = i + 1;
}

// ---------------------------------------------------------------------------
// Attention: block = (head, segment, qblock of 64 queries), 8 warps.
// K/V staged in SMEM in 64-row chunks; online softmax, 8 queries per warp.
// Output written as fp16 (feeds final GEMM's A operand).
// ---------------------------------------------------------------------------
__global__ __launch_bounds__(256) void attn_kernel()
{
    __shared__ float Ks[64 * 64];
    __shared__ float Vs[64 * 64];
    const int h  = blockIdx.x;
    const int s  = blockIdx.y;
    const int qb = blockIdx.z;
    const int k0 = g_kv_start[s], k1 = g_kv_end[s];
    const int qs = g_q_start[s],  qe = g_q_end[s];
    const int q0 = qs + qb * 64;
    const int q1 = min(qs + (qb + 1) * 64, qe);
    if (q0 >= q1) return;

    const int tid = threadIdx.x, wid = tid >> 5, lid = tid & 31;

    float2 qv[8], acc[8];
    float  m[8], den[8];
    int nq = 0;
#pragma unroll
    for (int j = 0; j < 8; j++) {
        int q = q0 + wid + 8 * j;
        if (q < q1) {
            nq = j + 1;
            qv[j] = *(const float2*)&g_Q[(size_t)q * D_QK + h * HEAD_DIM + 2 * lid];
        } else {
            qv[j] = make_float2(0.f, 0.f);
        }
        m[j] = -1e30f; den[j] = 0.f; acc[j] = make_float2(0.f, 0.f);
    }

    for (int kc = k0; kc < k1; kc += 64) {
        int cl = min(64, k1 - kc);
        __syncthreads();
        for (int f4 = tid; f4 < cl * 16; f4 += 256) {
            int kk = f4 >> 4, c4 = f4 & 15;
            *(float4*)&Ks[kk * 64 + c4 * 4] =
                *(const float4*)&g_K[(size_t)(kc + kk) * D_QK + h * HEAD_DIM + c4 * 4];
            *(float4*)&Vs[kk * 64 + c4 * 4] =
                *(const float4*)&g_V[(size_t)(kc + kk) * D_V + h * HEAD_DIM + c4 * 4];
        }
        __syncthreads();
        for (int kk = 0; kk < cl; kk++) {
            float2 kv = *(const float2*)&Ks[kk * 64 + 2 * lid];
            float2 vv = *(const float2*)&Vs[kk * 64 + 2 * lid];
#pragma unroll
            for (int j = 0; j < 8; j++) {
                if (j >= nq) break;
                float part = qv[j].x * kv.x + qv[j].y * kv.y;
#pragma unroll
                for (int o = 16; o; o >>= 1)
                    part += __shfl_xor_sync(0xffffffffu, part, o);
                float sc = part * SCALER;
                if (sc > m[j]) {
                    float corr = __expf(m[j] - sc);
                    den[j] = den[j] * corr + 1.f;
                    acc[j].x = acc[j].x * corr + vv.x;
                    acc[j].y = acc[j].y * corr + vv.y;
                    m[j] = sc;
                } else {
                    float p = __expf(sc - m[j]);
                    den[j] += p;
                    acc[j].x += p * vv.x;
                    acc[j].y += p * vv.y;
                }
            }
        }
    }

    for (int j = 0; j < nq; j++) {
        int q = q0 + wid + 8 * j;
        if (q < q1) {
            float inv = 1.f / den[j];
            __half2 hv;
            hv.x = __float2half(acc[j].x * inv);
            hv.y = __float2half(acc[j].y * inv);
            *(__half2*)&g_WVh[(size_t)q * KP_A + h * HEAD_DIM + 2 * lid] = hv;
        }
    }
}

// ---------------------------------------------------------------------------
// Launch
// ---------------------------------------------------------------------------
extern "C" void kernel_launch(void* const* d_in, const int* in_sizes, int n_in,
                              void* d_out, int out_size)
{
    const float* A     = (const float*)d_in[0];
    const float* B0    = (const float*)d_in[1];
    const int*   seg_q = (const int*)  d_in[2];
    const int*   seg_kv= (const int*)  d_in[3];
    const float* Wq    = (const float*)d_in[4];
    const float* bq    = (const float*)d_in[5];
    const float* Wk    = (const float*)d_in[6];
    const float* bk    = (const float*)d_in[7];
    const float* Wv    = (const float*)d_in[8];
    const float* bv    = (const float*)d_in[9];
    const float* Wf    = (const float*)d_in[10];
    const float* bf    = (const float*)d_in[11];
    float*       out   = (float*)d_out;

    float *Qp, *Kp, *Vp;
    int *kvS, *kvE, *qS, *qE;
    __half *Ahp, *B0hp, *WVhp;
    __half *WqThi, *WqTlo, *WkThi, *WkTlo, *WvThi, *WvTlo, *WfThi, *WfTlo;
    cudaGetSymbolAddress((void**)&Qp,  g_Q);
    cudaGetSymbolAddress((void**)&Kp,  g_K);
    cudaGetSymbolAddress((void**)&Vp,  g_V);
    cudaGetSymbolAddress((void**)&kvS, g_kv_start);
    cudaGetSymbolAddress((void**)&kvE, g_kv_end);
    cudaGetSymbolAddress((void**)&qS,  g_q_start);
    cudaGetSymbolAddress((void**)&qE,  g_q_end);
    cudaGetSymbolAddress((void**)&Ahp,  g_Ah);
    cudaGetSymbolAddress((void**)&B0hp, g_B0h);
    cudaGetSymbolAddress((void**)&WVhp, g_WVh);
    cudaGetSymbolAddress((void**)&WqThi, g_WqThi); cudaGetSymbolAddress((void**)&WqTlo, g_WqTlo);
    cudaGetSymbolAddress((void**)&WkThi, g_WkThi); cudaGetSymbolAddress((void**)&WkTlo, g_WkTlo);
    cudaGetSymbolAddress((void**)&WvThi, g_WvThi); cudaGetSymbolAddress((void**)&WvTlo, g_WvTlo);
    cudaGetSymbolAddress((void**)&WfThi, g_WfThi); cudaGetSymbolAddress((void**)&WfTlo, g_WfTlo);

    cudaFuncSetAttribute(gemm_fp16x2, cudaFuncAttributeMaxDynamicSharedMemorySize, GEMM_SMEM);

    seg_bounds_kernel<<<(TOTAL_KV + 255) / 256, 256>>>(seg_kv, TOTAL_KV, kvS, kvE);
    seg_bounds_kernel<<<(TOTAL_Q  + 255) / 256, 256>>>(seg_q,  TOTAL_Q,  qS,  qE);

    dim3 wb(32, 8);
    convert_act_h<<<(TOTAL_Q  * KP_A + 255) / 256, 256>>>(A,  Ahp,  TOTAL_Q,  Q_IN,  KP_A);
    convert_act_h<<<(TOTAL_KV * KP_B + 255) / 256, 256>>>(B0, B0hp, TOTAL_KV, KV_IN, KP_B);
    convert_wT_h<<<dim3(KP_A / 32, D_QK / 32), wb>>>(Wq, WqThi, WqTlo, Q_IN,  D_QK, KP_A);
    convert_wT_h<<<dim3(KP_B / 32, D_QK / 32), wb>>>(Wk, WkThi, WkTlo, KV_IN, D_QK, KP_B);
    convert_wT_h<<<dim3(KP_B / 32, D_V  / 32), wb>>>(Wv, WvThi, WvTlo, KV_IN, D_V,  KP_B);
    convert_wT_h<<<dim3(KP_A / 32, Q_IN / 32), wb>>>(Wf, WfThi, WfTlo, D_V,   Q_IN, KP_A);

    dim3 ggrid(D_QK / BN, TOTAL_Q / BM);   // (8, 32)
    gemm_fp16x2<<<ggrid, 256, GEMM_SMEM>>>(Ahp,  WqThi, WqTlo, bq, Qp, D_QK, KP_A);
    gemm_fp16x2<<<ggrid, 256, GEMM_SMEM>>>(B0hp, WkThi, WkTlo, bk, Kp, D_QK, KP_B);
    gemm_fp16x2<<<ggrid, 256, GEMM_SMEM>>>(B0hp, WvThi, WvTlo, bv, Vp, D_V,  KP_B);

    attn_kernel<<<dim3(N_HEADS, N_IMAGES, 8), 256>>>();

    gemm_fp16x2<<<ggrid, 256, GEMM_SMEM>>>(WVhp, WfThi, WfTlo, bf, out, Q_IN, KP_A);
}

// round 9
// speedup vs baseline: 2.2535x; 1.1406x over previous
#include <cuda_runtime.h>
#include <cuda_fp16.h>
#include <cstdint>
#include <math.h>

// ---------------------------------------------------------------------------
// Problem constants
// ---------------------------------------------------------------------------
#define TOTAL_Q   2048
#define TOTAL_KV  2048
#define Q_IN      1024
#define KV_IN     1033
#define D_QK      1024
#define D_V       1024
#define N_HEADS   16
#define HEAD_DIM  64
#define N_IMAGES  32
#define SCALER    0.125f

#define KP_A 1024
#define KP_B 1088              // 17 * 64

// ---------------------------------------------------------------------------
// Device scratch
// ---------------------------------------------------------------------------
__device__ float g_Q [TOTAL_Q  * D_QK];
__device__ float g_K [TOTAL_KV * D_QK];
__device__ float g_V [TOTAL_KV * D_V ];
__device__ int   g_kv_start[N_IMAGES], g_kv_end[N_IMAGES];
__device__ int   g_q_start [N_IMAGES], g_q_end [N_IMAGES];

__device__ __half g_Ah  [TOTAL_Q  * KP_A];
__device__ __half g_B0h [TOTAL_KV * KP_B];
__device__ __half g_WVh [TOTAL_Q  * KP_A];
__device__ __half g_WqThi[D_QK * KP_A], g_WqTlo[D_QK * KP_A];
__device__ __half g_WkThi[D_QK * KP_B], g_WkTlo[D_QK * KP_B];
__device__ __half g_WvThi[D_V  * KP_B], g_WvTlo[D_V  * KP_B];
__device__ __half g_WfThi[Q_IN * KP_A], g_WfTlo[Q_IN * KP_A];

// ---------------------------------------------------------------------------
// PTX helpers
// ---------------------------------------------------------------------------
__device__ __forceinline__ uint32_t smem_u32(const void* p) {
    uint32_t a;
    asm("{ .reg .u64 t; cvta.to.shared.u64 t, %1; cvt.u32.u64 %0, t; }" : "=r"(a) : "l"(p));
    return a;
}
__device__ __forceinline__ void mma16816h(float* c,
    uint32_t a0, uint32_t a1, uint32_t a2, uint32_t a3,
    uint32_t b0, uint32_t b1)
{
    asm volatile(
        "mma.sync.aligned.m16n8k16.row.col.f32.f16.f16.f32 "
        "{%0,%1,%2,%3}, {%4,%5,%6,%7}, {%8,%9}, {%0,%1,%2,%3};"
        : "+f"(c[0]), "+f"(c[1]), "+f"(c[2]), "+f"(c[3])
        : "r"(a0), "r"(a1), "r"(a2), "r"(a3), "r"(b0), "r"(b1));
}
__device__ __forceinline__ void ldsm4(uint32_t& r0, uint32_t& r1, uint32_t& r2, uint32_t& r3,
                                      uint32_t addr)
{
    asm volatile("ldmatrix.sync.aligned.m8n8.x4.shared.b16 {%0,%1,%2,%3}, [%4];"
                 : "=r"(r0), "=r"(r1), "=r"(r2), "=r"(r3) : "r"(addr));
}
__device__ __forceinline__ void cp16(uint32_t dst, const void* src)
{
    asm volatile("cp.async.cg.shared.global [%0], [%1], 16;" :: "r"(dst), "l"(src) : "memory");
}
__device__ __forceinline__ void cp_commit() { asm volatile("cp.async.commit_group;" ::: "memory"); }
__device__ __forceinline__ void cp_wait0()  { asm volatile("cp.async.wait_group 0;"  ::: "memory"); }

__device__ __forceinline__ void split_fp16(float x, __half& hi, __half& lo)
{
    hi = __float2half(x);
    lo = __float2half(x - __half2float(hi));
}

// ---------------------------------------------------------------------------
// Fused segment bounds (q + kv in one launch)
// ---------------------------------------------------------------------------
__global__ void seg_bounds2(const int* __restrict__ sq, const int* __restrict__ skv)
{
    int i = blockIdx.x * blockDim.x + threadIdx.x;
    if (i < TOTAL_Q) {
        int s = sq[i];
        if (i == 0           || sq[i - 1] != s) g_q_start[s] = i;
        if (i == TOTAL_Q - 1 || sq[i + 1] != s) g_q_end[s]   = i + 1;
    }
    if (i < TOTAL_KV) {
        int s = skv[i];
        if (i == 0            || skv[i - 1] != s) g_kv_start[s] = i;
        if (i == TOTAL_KV - 1 || skv[i + 1] != s) g_kv_end[s]   = i + 1;
    }
}

// ---------------------------------------------------------------------------
// Fused conversions: one flat grid covering 6 jobs
//  J0 act A  -> g_Ah          blocks 8192
//  J1 act B0 -> g_B0h         blocks 8704
//  J2 Wq^T hi/lo              blocks 1024
//  J3 Wk^T hi/lo              blocks 1088
//  J4 Wv^T hi/lo              blocks 1088
//  J5 Wf^T hi/lo              blocks 1024
// ---------------------------------------------------------------------------
#define CV_O1 8192
#define CV_O2 16896
#define CV_O3 17920
#define CV_O4 19008
#define CV_O5 20096
#define CV_TOT 21120

__device__ __forceinline__ void wT_job(const float* __restrict__ W,
                                       __half* __restrict__ hiT, __half* __restrict__ loT,
                                       int K, int N, int Kp, int local, int tid)
{
    __shared__ float t[32][33];
    int kbn = Kp >> 5;
    int kb = local % kbn, nb = local / kbn;
    int k0 = kb * 32, n0 = nb * 32;
    int tx = tid & 31, ty = tid >> 5;   // (32, 8)
#pragma unroll
    for (int i = 0; i < 4; i++) {
        int k = k0 + ty + i * 8;
        t[ty + i * 8][tx] = (k < K) ? W[(size_t)k * N + n0 + tx] : 0.f;
    }
    __syncthreads();
#pragma unroll
    for (int i = 0; i < 4; i++) {
        int n = n0 + ty + i * 8;
        float x = t[tx][ty + i * 8];
        __half h, l;
        split_fp16(x, h, l);
        size_t o = (size_t)n * Kp + k0 + tx;
        hiT[o] = h;
        loT[o] = l;
    }
}

__global__ __launch_bounds__(256) void convert_all(
    const float* __restrict__ A,  const float* __restrict__ B0,
    const float* __restrict__ Wq, const float* __restrict__ Wk,
    const float* __restrict__ Wv, const float* __restrict__ Wf)
{
    const int b = blockIdx.x, tid = threadIdx.x;
    if (b < CV_O1) {                       // act A: K=Kp=1024
        int idx = b * 256 + tid;
        g_Ah[idx] = __float2half(A[idx]);  // no pad needed
    } else if (b < CV_O2) {                // act B0: K=1033, Kp=1088
        int idx = (b - CV_O1) * 256 + tid;
        int m = idx / KP_B, k = idx - m * KP_B;
        float x = (k < KV_IN) ? B0[(size_t)m * KV_IN + k] : 0.f;
        g_B0h[idx] = __float2half(x);
    } else if (b < CV_O3) {
        wT_job(Wq, g_WqThi, g_WqTlo, Q_IN,  D_QK, KP_A, b - CV_O2, tid);
    } else if (b < CV_O4) {
        wT_job(Wk, g_WkThi, g_WkTlo, KV_IN, D_QK, KP_B, b - CV_O3, tid);
    } else if (b < CV_O5) {
        wT_job(Wv, g_WvThi, g_WvTlo, KV_IN, D_V,  KP_B, b - CV_O4, tid);
    } else {
        wT_job(Wf, g_WfThi, g_WfTlo, D_V,   Q_IN, KP_A, b - CV_O5, tid);
    }
}

// ---------------------------------------------------------------------------
// fp16 2-term tensor-core GEMM core:
//   C[bm:bm+64, bn:bn+128] = Ah[M,Kp] @ (Whi+Wlo)[N,Kp]^T + bias
// BK=64, 256 threads, warp tile 16x64, 2-stage cp.async pipe, ldmatrix.
// SMEM row stride 144B (conflict-free ldmatrix).
// ---------------------------------------------------------------------------
#define BM 64
#define BN 128
#define BK 64
#define RSTRIDE 144
#define A_OFF   0
#define BHI_OFF (64 * RSTRIDE)                 // 9216
#define BLO_OFF (BHI_OFF + 128 * RSTRIDE)      // 27648
#define STAGE   (BLO_OFF + 128 * RSTRIDE)      // 46080
#define GEMM_SMEM (2 * STAGE)                  // 92160

__device__ __forceinline__ void gemm_core(
    char* smc,
    const __half* __restrict__ Ah,
    const __half* __restrict__ Bhi, const __half* __restrict__ Blo,
    const float* __restrict__ bias, float* __restrict__ C,
    int N, int Kp, int bm, int bn)
{
    const uint32_t sb = smem_u32(smc);
    const int tid  = threadIdx.x;
    const int lane = tid & 31;
    const int wid  = tid >> 5;
    const int qid  = lane >> 2;
    const int tq   = lane & 3;
    const int warpM = wid & 3;
    const int warpN = wid >> 2;
    const int chunks = Kp >> 6;

    const uint32_t g = lane >> 3;
    const uint32_t aOff = A_OFF
        + (warpM * 16 + (g & 1) * 8 + (lane & 7)) * RSTRIDE + ((g >> 1) * 8) * 2;
    const uint32_t bOff = BHI_OFF
        + (warpN * 64 + (g >> 1) * 8 + (lane & 7)) * RSTRIDE + ((g & 1) * 8) * 2;

    float acc[8][4];
#pragma unroll
    for (int t = 0; t < 8; t++)
#pragma unroll
        for (int j = 0; j < 4; j++) acc[t][j] = 0.f;

    auto PREFETCH = [&](int c, int s) {
        uint32_t stb = sb + s * STAGE;
        const int kb = c * BK;
#pragma unroll
        for (int i = 0; i < 2; i++) {           // A: 64 rows x 8 segs
            int u = tid + i * 256;
            int row = u >> 3, seg = u & 7;
            cp16(stb + A_OFF + row * RSTRIDE + seg * 16,
                 &Ah[(size_t)(bm + row) * Kp + kb + seg * 8]);
        }
#pragma unroll
        for (int i = 0; i < 4; i++) {           // B hi+lo: 128 rows x 8 segs
            int u = tid + i * 256;
            int row = u >> 3, seg = u & 7;
            size_t bo = (size_t)(bn + row) * Kp + kb + seg * 8;
            uint32_t bd = stb + row * RSTRIDE + seg * 16;
            cp16(bd + BHI_OFF, &Bhi[bo]);
            cp16(bd + BLO_OFF, &Blo[bo]);
        }
        cp_commit();
    };

    auto COMPUTE = [&](int s) {
        uint32_t stb = sb + s * STAGE;
#pragma unroll
        for (int ks = 0; ks < 4; ks++) {
            uint32_t ka = stb + aOff + ks * 32;
            uint32_t a0, a1, a2, a3;
            ldsm4(a0, a1, a2, a3, ka);
#pragma unroll
            for (int p = 0; p < 4; p++) {
                uint32_t kb2 = stb + bOff + p * (16 * RSTRIDE) + ks * 32;
                uint32_t bh0, bh1, bh2, bh3, bl0, bl1, bl2, bl3;
                ldsm4(bh0, bh1, bh2, bh3, kb2);
                ldsm4(bl0, bl1, bl2, bl3, kb2 + (BLO_OFF - BHI_OFF));
                mma16816h(acc[p * 2],     a0, a1, a2, a3, bh0, bh1);
                mma16816h(acc[p * 2],     a0, a1, a2, a3, bl0, bl1);
                mma16816h(acc[p * 2 + 1], a0, a1, a2, a3, bh2, bh3);
                mma16816h(acc[p * 2 + 1], a0, a1, a2, a3, bl2, bl3);
            }
        }
    };

    PREFETCH(0, 0);
    cp_wait0();
    __syncthreads();

    for (int c = 0; c < chunks; c++) {
        int s = c & 1;
        if (c + 1 < chunks) PREFETCH(c + 1, s ^ 1);
        COMPUTE(s);
        if (c + 1 < chunks) cp_wait0();
        __syncthreads();
    }

    const int r0 = bm + warpM * 16 + qid;
#pragma unroll
    for (int tn = 0; tn < 8; tn++) {
        const int col = bn + warpN * 64 + tn * 8 + tq * 2;
        float2 b2 = *(const float2*)&bias[col];
        float2 v0 = make_float2(acc[tn][0] + b2.x, acc[tn][1] + b2.y);
        float2 v1 = make_float2(acc[tn][2] + b2.x, acc[tn][3] + b2.y);
        *(float2*)&C[(size_t)r0 * N + col]       = v0;
        *(float2*)&C[(size_t)(r0 + 8) * N + col] = v1;
    }
}

// Fused Q/K/V projection: blockIdx.z selects the job
__global__ __launch_bounds__(256, 2) void gemm_qkv(
    const __half* __restrict__ Ah,   const __half* __restrict__ B0h,
    const __half* __restrict__ WqHi, const __half* __restrict__ WqLo,
    const __half* __restrict__ WkHi, const __half* __restrict__ WkLo,
    const __half* __restrict__ WvHi, const __half* __restrict__ WvLo,
    const float* __restrict__ bq, const float* __restrict__ bk,
    const float* __restrict__ bv,
    float* __restrict__ Q, float* __restrict__ K, float* __restrict__ V)
{
    extern __shared__ char smc[];
    const int z = blockIdx.z;
    const __half* A   = (z == 0) ? Ah : B0h;
    const __half* Bhi = (z == 0) ? WqHi : (z == 1) ? WkHi : WvHi;
    const __half* Blo = (z == 0) ? WqLo : (z == 1) ? WkLo : WvLo;
    const float* bias = (z == 0) ? bq : (z == 1) ? bk : bv;
    float* C          = (z == 0) ? Q  : (z == 1) ? K  : V;
    const int Kp      = (z == 0) ? KP_A : KP_B;
    gemm_core(smc, A, Bhi, Blo, bias, C, D_QK, Kp,
              blockIdx.y * BM, blockIdx.x * BN);
}

// Final projection
__global__ __launch_bounds__(256, 2) void gemm_final(
    const __half* __restrict__ WVh,
    const __half* __restrict__ WfHi, const __half* __restrict__ WfLo,
    const float* __restrict__ bf, float* __restrict__ out)
{
    extern __shared__ char smc[];
    gemm_core(smc, WVh, WfHi, WfLo, bf, out, Q_IN, KP_A,
              blockIdx.y * BM, blockIdx.x * BN);
}

// ---------------------------------------------------------------------------
// Attention: block = (head, segment, qblock of 64 queries), 8 warps.
// Online softmax, 8 queries per warp; K/V staged in SMEM; fp16 output.
// ---------------------------------------------------------------------------
__global__ __launch_bounds__(256) void attn_kernel()
{
    __shared__ float Ks[64 * 64];
    __shared__ float Vs[64 * 64];
    const int h  = blockIdx.x;
    const int s  = blockIdx.y;
    const int qb = blockIdx.z;
    const int k0 = g_kv_start[s], k1 = g_kv_end[s];
    const int qs = g_q_start[s],  qe = g_q_end[s];
    const int q0 = qs + qb * 64;
    const int q1 = min(qs + (qb + 1) * 64, qe);
    if (q0 >= q1) return;

    const int tid = threadIdx.x, wid = tid >> 5, lid = tid & 31;

    float2 qv[8], acc[8];
    float  m[8], den[8];
    int nq = 0;
#pragma unroll
    for (int j = 0; j < 8; j++) {
        int q = q0 + wid + 8 * j;
        if (q < q1) {
            nq = j + 1;
            qv[j] = *(const float2*)&g_Q[(size_t)q * D_QK + h * HEAD_DIM + 2 * lid];
        } else {
            qv[j] = make_float2(0.f, 0.f);
        }
        m[j] = -1e30f; den[j] = 0.f; acc[j] = make_float2(0.f, 0.f);
    }

    for (int kc = k0; kc < k1; kc += 64) {
        int cl = min(64, k1 - kc);
        __syncthreads();
        for (int f4 = tid; f4 < cl * 16; f4 += 256) {
            int kk = f4 >> 4, c4 = f4 & 15;
            *(float4*)&Ks[kk * 64 + c4 * 4] =
                *(const float4*)&g_K[(size_t)(kc + kk) * D_QK + h * HEAD_DIM + c4 * 4];
            *(float4*)&Vs[kk * 64 + c4 * 4] =
                *(const float4*)&g_V[(size_t)(kc + kk) * D_V + h * HEAD_DIM + c4 * 4];
        }
        __syncthreads();
        for (int kk = 0; kk < cl; kk++) {
            float2 kv = *(const float2*)&Ks[kk * 64 + 2 * lid];
            float2 vv = *(const float2*)&Vs[kk * 64 + 2 * lid];
#pragma unroll
            for (int j = 0; j < 8; j++) {
                if (j >= nq) break;
                float part = qv[j].x * kv.x + qv[j].y * kv.y;
#pragma unroll
                for (int o = 16; o; o >>= 1)
                    part += __shfl_xor_sync(0xffffffffu, part, o);
                float sc = part * SCALER;
                if (sc > m[j]) {
                    float corr = __expf(m[j] - sc);
                    den[j] = den[j] * corr + 1.f;
                    acc[j].x = acc[j].x * corr + vv.x;
                    acc[j].y = acc[j].y * corr + vv.y;
                    m[j] = sc;
                } else {
                    float p = __expf(sc - m[j]);
                    den[j] += p;
                    acc[j].x += p * vv.x;
                    acc[j].y += p * vv.y;
                }
            }
        }
    }

    for (int j = 0; j < nq; j++) {
        int q = q0 + wid + 8 * j;
        if (q < q1) {
            float inv = 1.f / den[j];
            __half2 hv;
            hv.x = __float2half(acc[j].x * inv);
            hv.y = __float2half(acc[j].y * inv);
            *(__half2*)&g_WVh[(size_t)q * KP_A + h * HEAD_DIM + 2 * lid] = hv;
        }
    }
}

// ---------------------------------------------------------------------------
// Launch
// ---------------------------------------------------------------------------
extern "C" void kernel_launch(void* const* d_in, const int* in_sizes, int n_in,
                              void* d_out, int out_size)
{
    const float* A     = (const float*)d_in[0];
    const float* B0    = (const float*)d_in[1];
    const int*   seg_q = (const int*)  d_in[2];
    const int*   seg_kv= (const int*)  d_in[3];
    const float* Wq    = (const float*)d_in[4];
    const float* bq    = (const float*)d_in[5];
    const float* Wk    = (const float*)d_in[6];
    const float* bk    = (const float*)d_in[7];
    const float* Wv    = (const float*)d_in[8];
    const float* bv    = (const float*)d_in[9];
    const float* Wf    = (const float*)d_in[10];
    const float* bf    = (const float*)d_in[11];
    float*       out   = (float*)d_out;

    float *Qp, *Kp2, *Vp;
    __half *Ahp, *B0hp, *WVhp;
    __half *WqThi, *WqTlo, *WkThi, *WkTlo, *WvThi, *WvTlo, *WfThi, *WfTlo;
    cudaGetSymbolAddress((void**)&Qp,  g_Q);
    cudaGetSymbolAddress((void**)&Kp2, g_K);
    cudaGetSymbolAddress((void**)&Vp,  g_V);
    cudaGetSymbolAddress((void**)&Ahp,  g_Ah);
    cudaGetSymbolAddress((void**)&B0hp, g_B0h);
    cudaGetSymbolAddress((void**)&WVhp, g_WVh);
    cudaGetSymbolAddress((void**)&WqThi, g_WqThi); cudaGetSymbolAddress((void**)&WqTlo, g_WqTlo);
    cudaGetSymbolAddress((void**)&WkThi, g_WkThi); cudaGetSymbolAddress((void**)&WkTlo, g_WkTlo);
    cudaGetSymbolAddress((void**)&WvThi, g_WvThi); cudaGetSymbolAddress((void**)&WvTlo, g_WvTlo);
    cudaGetSymbolAddress((void**)&WfThi, g_WfThi); cudaGetSymbolAddress((void**)&WfTlo, g_WfTlo);

    cudaFuncSetAttribute(gemm_qkv,   cudaFuncAttributeMaxDynamicSharedMemorySize, GEMM_SMEM);
    cudaFuncSetAttribute(gemm_final, cudaFuncAttributeMaxDynamicSharedMemorySize, GEMM_SMEM);

    // 1. segment bounds
    seg_bounds2<<<(TOTAL_Q + 255) / 256, 256>>>(seg_q, seg_kv);

    // 2. all conversions
    convert_all<<<CV_TOT, 256>>>(A, B0, Wq, Wk, Wv, Wf);

    // 3. fused Q/K/V projections
    gemm_qkv<<<dim3(D_QK / BN, TOTAL_Q / BM, 3), 256, GEMM_SMEM>>>(
        Ahp, B0hp, WqThi, WqTlo, WkThi, WkTlo, WvThi, WvTlo,
        bq, bk, bv, Qp, Kp2, Vp);

    // 4. attention
    attn_kernel<<<dim3(N_HEADS, N_IMAGES, 8), 256>>>();

    // 5. output projection
    gemm_final<<<dim3(Q_IN / BN, TOTAL_Q / BM), 256, GEMM_SMEM>>>(
        WVhp, WfThi, WfTlo, bf, out);
}

// round 11
// speedup vs baseline: 3.9271x; 1.7427x over previous
#include <cuda_runtime.h>
#include <cuda_fp16.h>
#include <cstdint>
#include <math.h>

// ---------------------------------------------------------------------------
// Problem constants
// ---------------------------------------------------------------------------
#define TOTAL_Q   2048
#define TOTAL_KV  2048
#define Q_IN      1024
#define KV_IN     1033
#define D_QK      1024
#define D_V       1024
#define N_HEADS   16
#define HEAD_DIM  64
#define N_IMAGES  32
#define SCALER    0.125f

#define KP_A 1024
#define KP_B 1088              // 17 * 64

// ---------------------------------------------------------------------------
// Device scratch
// ---------------------------------------------------------------------------
__device__ int   g_kv_start[N_IMAGES], g_kv_end[N_IMAGES];
__device__ int   g_q_start [N_IMAGES], g_q_end [N_IMAGES];

__device__ __half g_Ah  [TOTAL_Q  * KP_A];
__device__ __half g_B0h [TOTAL_KV * KP_B];
__device__ __half g_WVh [TOTAL_Q  * KP_A];
__device__ __half g_Qhi [TOTAL_Q  * D_QK], g_Qlo [TOTAL_Q  * D_QK];
__device__ __half g_Khi [TOTAL_KV * D_QK], g_Klo [TOTAL_KV * D_QK];
__device__ __half g_Vhi [TOTAL_KV * D_V ], g_Vlo [TOTAL_KV * D_V ];
__device__ __half g_WqThi[D_QK * KP_A], g_WqTlo[D_QK * KP_A];
__device__ __half g_WkThi[D_QK * KP_B], g_WkTlo[D_QK * KP_B];
__device__ __half g_WvThi[D_V  * KP_B], g_WvTlo[D_V  * KP_B];
__device__ __half g_WfThi[Q_IN * KP_A], g_WfTlo[Q_IN * KP_A];

// ---------------------------------------------------------------------------
// PTX helpers
// ---------------------------------------------------------------------------
__device__ __forceinline__ uint32_t smem_u32(const void* p) {
    uint32_t a;
    asm("{ .reg .u64 t; cvta.to.shared.u64 t, %1; cvt.u32.u64 %0, t; }" : "=r"(a) : "l"(p));
    return a;
}
__device__ __forceinline__ void mma16816h(float* c,
    uint32_t a0, uint32_t a1, uint32_t a2, uint32_t a3,
    uint32_t b0, uint32_t b1)
{
    asm volatile(
        "mma.sync.aligned.m16n8k16.row.col.f32.f16.f16.f32 "
        "{%0,%1,%2,%3}, {%4,%5,%6,%7}, {%8,%9}, {%0,%1,%2,%3};"
        : "+f"(c[0]), "+f"(c[1]), "+f"(c[2]), "+f"(c[3])
        : "r"(a0), "r"(a1), "r"(a2), "r"(a3), "r"(b0), "r"(b1));
}
__device__ __forceinline__ void ldsm4(uint32_t& r0, uint32_t& r1, uint32_t& r2, uint32_t& r3,
                                      uint32_t addr)
{
    asm volatile("ldmatrix.sync.aligned.m8n8.x4.shared.b16 {%0,%1,%2,%3}, [%4];"
                 : "=r"(r0), "=r"(r1), "=r"(r2), "=r"(r3) : "r"(addr));
}
__device__ __forceinline__ void ldsm4t(uint32_t& r0, uint32_t& r1, uint32_t& r2, uint32_t& r3,
                                       uint32_t addr)
{
    asm volatile("ldmatrix.sync.aligned.m8n8.x4.trans.shared.b16 {%0,%1,%2,%3}, [%4];"
                 : "=r"(r0), "=r"(r1), "=r"(r2), "=r"(r3) : "r"(addr));
}
__device__ __forceinline__ void cp16(uint32_t dst, const void* src)
{
    asm volatile("cp.async.cg.shared.global [%0], [%1], 16;" :: "r"(dst), "l"(src) : "memory");
}
__device__ __forceinline__ void cp_commit() { asm volatile("cp.async.commit_group;" ::: "memory"); }
__device__ __forceinline__ void cp_wait0()  { asm volatile("cp.async.wait_group 0;"  ::: "memory"); }

__device__ __forceinline__ void split_fp16(float x, __half& hi, __half& lo)
{
    hi = __float2half(x);
    lo = __float2half(x - __half2float(hi));
}
__device__ __forceinline__ uint32_t pack2(__half a, __half b)
{
    __half2 h = __halves2half2(a, b);
    return *(uint32_t*)&h;
}

// ---------------------------------------------------------------------------
// Fused segment bounds
// ---------------------------------------------------------------------------
__global__ void seg_bounds2(const int* __restrict__ sq, const int* __restrict__ skv)
{
    int i = blockIdx.x * blockDim.x + threadIdx.x;
    if (i < TOTAL_Q) {
        int s = sq[i];
        if (i == 0           || sq[i - 1] != s) g_q_start[s] = i;
        if (i == TOTAL_Q - 1 || sq[i + 1] != s) g_q_end[s]   = i + 1;
    }
    if (i < TOTAL_KV) {
        int s = skv[i];
        if (i == 0            || skv[i - 1] != s) g_kv_start[s] = i;
        if (i == TOTAL_KV - 1 || skv[i + 1] != s) g_kv_end[s]   = i + 1;
    }
}

// ---------------------------------------------------------------------------
// Fused conversions (one flat grid, 6 jobs)
// ---------------------------------------------------------------------------
#define CV_O1 8192
#define CV_O2 16896
#define CV_O3 17920
#define CV_O4 19008
#define CV_O5 20096
#define CV_TOT 21120

__device__ __forceinline__ void wT_job(const float* __restrict__ W,
                                       __half* __restrict__ hiT, __half* __restrict__ loT,
                                       int K, int N, int Kp, int local, int tid)
{
    __shared__ float t[32][33];
    int kbn = Kp >> 5;
    int kb = local % kbn, nb = local / kbn;
    int k0 = kb * 32, n0 = nb * 32;
    int tx = tid & 31, ty = tid >> 5;
#pragma unroll
    for (int i = 0; i < 4; i++) {
        int k = k0 + ty + i * 8;
        t[ty + i * 8][tx] = (k < K) ? W[(size_t)k * N + n0 + tx] : 0.f;
    }
    __syncthreads();
#pragma unroll
    for (int i = 0; i < 4; i++) {
        int n = n0 + ty + i * 8;
        float x = t[tx][ty + i * 8];
        __half h, l;
        split_fp16(x, h, l);
        size_t o = (size_t)n * Kp + k0 + tx;
        hiT[o] = h;
        loT[o] = l;
    }
}

__global__ __launch_bounds__(256) void convert_all(
    const float* __restrict__ A,  const float* __restrict__ B0,
    const float* __restrict__ Wq, const float* __restrict__ Wk,
    const float* __restrict__ Wv, const float* __restrict__ Wf)
{
    const int b = blockIdx.x, tid = threadIdx.x;
    if (b < CV_O1) {
        int idx = b * 256 + tid;
        g_Ah[idx] = __float2half(A[idx]);
    } else if (b < CV_O2) {
        int idx = (b - CV_O1) * 256 + tid;
        int m = idx / KP_B, k = idx - m * KP_B;
        float x = (k < KV_IN) ? B0[(size_t)m * KV_IN + k] : 0.f;
        g_B0h[idx] = __float2half(x);
    } else if (b < CV_O3) {
        wT_job(Wq, g_WqThi, g_WqTlo, Q_IN,  D_QK, KP_A, b - CV_O2, tid);
    } else if (b < CV_O4) {
        wT_job(Wk, g_WkThi, g_WkTlo, KV_IN, D_QK, KP_B, b - CV_O3, tid);
    } else if (b < CV_O5) {
        wT_job(Wv, g_WvThi, g_WvTlo, KV_IN, D_V,  KP_B, b - CV_O4, tid);
    } else {
        wT_job(Wf, g_WfThi, g_WfTlo, D_V,   Q_IN, KP_A, b - CV_O5, tid);
    }
}

// ---------------------------------------------------------------------------
// fp16 2-term GEMM core (BK=64), optional hi/lo split output
// ---------------------------------------------------------------------------
#define BM 64
#define BN 128
#define BK 64
#define RSTRIDE 144
#define A_OFF   0
#define BHI_OFF (64 * RSTRIDE)
#define BLO_OFF (BHI_OFF + 128 * RSTRIDE)
#define STAGE   (BLO_OFF + 128 * RSTRIDE)
#define GEMM_SMEM (2 * STAGE)

template<int SPLIT>
__device__ __forceinline__ void gemm_core(
    char* smc,
    const __half* __restrict__ Ah,
    const __half* __restrict__ Bhi, const __half* __restrict__ Blo,
    const float* __restrict__ bias,
    float* __restrict__ C, __half* __restrict__ Chi, __half* __restrict__ Clo,
    int N, int Kp, int bm, int bn)
{
    const uint32_t sb = smem_u32(smc);
    const int tid  = threadIdx.x;
    const int lane = tid & 31;
    const int wid  = tid >> 5;
    const int qid  = lane >> 2;
    const int tq   = lane & 3;
    const int warpM = wid & 3;
    const int warpN = wid >> 2;
    const int chunks = Kp >> 6;

    const uint32_t g = lane >> 3;
    const uint32_t aOff = A_OFF
        + (warpM * 16 + (g & 1) * 8 + (lane & 7)) * RSTRIDE + ((g >> 1) * 8) * 2;
    const uint32_t bOff = BHI_OFF
        + (warpN * 64 + (g >> 1) * 8 + (lane & 7)) * RSTRIDE + ((g & 1) * 8) * 2;

    float acc[8][4];
#pragma unroll
    for (int t = 0; t < 8; t++)
#pragma unroll
        for (int j = 0; j < 4; j++) acc[t][j] = 0.f;

    auto PREFETCH = [&](int c, int s) {
        uint32_t stb = sb + s * STAGE;
        const int kb = c * BK;
#pragma unroll
        for (int i = 0; i < 2; i++) {
            int u = tid + i * 256;
            int row = u >> 3, seg = u & 7;
            cp16(stb + A_OFF + row * RSTRIDE + seg * 16,
                 &Ah[(size_t)(bm + row) * Kp + kb + seg * 8]);
        }
#pragma unroll
        for (int i = 0; i < 4; i++) {
            int u = tid + i * 256;
            int row = u >> 3, seg = u & 7;
            size_t bo = (size_t)(bn + row) * Kp + kb + seg * 8;
            uint32_t bd = stb + row * RSTRIDE + seg * 16;
            cp16(bd + BHI_OFF, &Bhi[bo]);
            cp16(bd + BLO_OFF, &Blo[bo]);
        }
        cp_commit();
    };

    auto COMPUTE = [&](int s) {
        uint32_t stb = sb + s * STAGE;
#pragma unroll
        for (int ks = 0; ks < 4; ks++) {
            uint32_t ka = stb + aOff + ks * 32;
            uint32_t a0, a1, a2, a3;
            ldsm4(a0, a1, a2, a3, ka);
#pragma unroll
            for (int p = 0; p < 4; p++) {
                uint32_t kb2 = stb + bOff + p * (16 * RSTRIDE) + ks * 32;
                uint32_t bh0, bh1, bh2, bh3, bl0, bl1, bl2, bl3;
                ldsm4(bh0, bh1, bh2, bh3, kb2);
                ldsm4(bl0, bl1, bl2, bl3, kb2 + (BLO_OFF - BHI_OFF));
                mma16816h(acc[p * 2],     a0, a1, a2, a3, bh0, bh1);
                mma16816h(acc[p * 2],     a0, a1, a2, a3, bl0, bl1);
                mma16816h(acc[p * 2 + 1], a0, a1, a2, a3, bh2, bh3);
                mma16816h(acc[p * 2 + 1], a0, a1, a2, a3, bl2, bl3);
            }
        }
    };

    PREFETCH(0, 0);
    cp_wait0();
    __syncthreads();

    for (int c = 0; c < chunks; c++) {
        int s = c & 1;
        if (c + 1 < chunks) PREFETCH(c + 1, s ^ 1);
        COMPUTE(s);
        if (c + 1 < chunks) cp_wait0();
        __syncthreads();
    }

    const int r0 = bm + warpM * 16 + qid;
#pragma unroll
    for (int tn = 0; tn < 8; tn++) {
        const int col = bn + warpN * 64 + tn * 8 + tq * 2;
        float2 b2 = *(const float2*)&bias[col];
        float v0 = acc[tn][0] + b2.x, v1 = acc[tn][1] + b2.y;
        float v2 = acc[tn][2] + b2.x, v3 = acc[tn][3] + b2.y;
        if (SPLIT) {
            __half h0, l0, h1, l1, h2, l2, h3, l3;
            split_fp16(v0, h0, l0); split_fp16(v1, h1, l1);
            split_fp16(v2, h2, l2); split_fp16(v3, h3, l3);
            *(uint32_t*)&Chi[(size_t)r0 * N + col]       = pack2(h0, h1);
            *(uint32_t*)&Clo[(size_t)r0 * N + col]       = pack2(l0, l1);
            *(uint32_t*)&Chi[(size_t)(r0 + 8) * N + col] = pack2(h2, h3);
            *(uint32_t*)&Clo[(size_t)(r0 + 8) * N + col] = pack2(l2, l3);
        } else {
            *(float2*)&C[(size_t)r0 * N + col]       = make_float2(v0, v1);
            *(float2*)&C[(size_t)(r0 + 8) * N + col] = make_float2(v2, v3);
        }
    }
}

__global__ __launch_bounds__(256, 2) void gemm_qkv(
    const __half* __restrict__ Ah,   const __half* __restrict__ B0h,
    const float* __restrict__ bq, const float* __restrict__ bk,
    const float* __restrict__ bv)
{
    extern __shared__ char smc[];
    const int z = blockIdx.z;
    const __half* A   = (z == 0) ? Ah : B0h;
    const __half* Bhi = (z == 0) ? g_WqThi : (z == 1) ? g_WkThi : g_WvThi;
    const __half* Blo = (z == 0) ? g_WqTlo : (z == 1) ? g_WkTlo : g_WvTlo;
    const float* bias = (z == 0) ? bq : (z == 1) ? bk : bv;
    __half* Chi       = (z == 0) ? g_Qhi : (z == 1) ? g_Khi : g_Vhi;
    __half* Clo       = (z == 0) ? g_Qlo : (z == 1) ? g_Klo : g_Vlo;
    const int Kp      = (z == 0) ? KP_A : KP_B;
    gemm_core<1>(smc, A, Bhi, Blo, bias, nullptr, Chi, Clo, D_QK, Kp,
                 blockIdx.y * BM, blockIdx.x * BN);
}

__global__ __launch_bounds__(256, 2) void gemm_final(
    const float* __restrict__ bf, float* __restrict__ out)
{
    extern __shared__ char smc[];
    gemm_core<0>(smc, g_WVh, g_WfThi, g_WfTlo, bf, out, nullptr, nullptr,
                 Q_IN, KP_A, blockIdx.y * BM, blockIdx.x * BN);
}

// ---------------------------------------------------------------------------
// Flash attention: block = (head, seg, 64-q tile), 4 warps, warp = 16 q rows.
// S = Q@K^T (3-term hi/lo mma), fragment online softmax, O += P@V (3-term).
// ---------------------------------------------------------------------------
#define AT_RS 144
#define AQH 0
#define AQL 9216
#define AKH (2 * 9216)
#define AVH (4 * 9216)
#define ATTN_SMEM (6 * 9216)     // 55296

__global__ __launch_bounds__(128) void attn_fa()
{
    extern __shared__ char smc[];
    const uint32_t sb = smem_u32(smc);
    const int h = blockIdx.x, s = blockIdx.y, qb = blockIdx.z;
    const int k0 = g_kv_start[s], k1 = g_kv_end[s];
    const int qs = g_q_start[s],  qe = g_q_end[s];
    const int q0 = qs + qb * 64;
    if (q0 >= qe) return;
    const int q1 = min(q0 + 64, qe);

    const int tid = threadIdx.x, lane = tid & 31, wid = tid >> 5;
    const int qid = lane >> 2, tq = lane & 3;
    const uint32_t g = lane >> 3;

    const uint32_t aQ = (wid * 16 + (g & 1) * 8 + (lane & 7)) * AT_RS + ((g >> 1) * 8) * 2;
    const uint32_t bK = ((g >> 1) * 8 + (lane & 7)) * AT_RS + ((g & 1) * 8) * 2;
    const uint32_t bV = ((g & 1) * 8 + (lane & 7)) * AT_RS + ((g >> 1) * 8) * 2;

    // Q tile (hi+lo): 1024 cp16 over 128 threads
#pragma unroll
    for (int i = 0; i < 8; i++) {
        int u = tid + i * 128;
        int plane = u >> 9, idx = u & 511;
        int row = idx >> 3, seg = idx & 7;
        int qrow = min(q0 + row, TOTAL_Q - 1);
        const __half* src = (plane ? g_Qlo : g_Qhi) + (size_t)qrow * D_QK + h * 64 + seg * 8;
        cp16(sb + (plane ? AQL : AQH) + row * AT_RS + seg * 16, src);
    }

    auto LOADKV = [&](int kc) {
#pragma unroll
        for (int i = 0; i < 16; i++) {
            int u = tid + i * 128;
            int plane = u >> 9, idx = u & 511;    // 0:Khi 1:Klo 2:Vhi 3:Vlo
            int row = idx >> 3, seg = idx & 7;
            int krow = min(kc + row, TOTAL_KV - 1);
            const __half* base = (plane == 0) ? g_Khi : (plane == 1) ? g_Klo
                               : (plane == 2) ? g_Vhi : g_Vlo;
            cp16(sb + AKH + plane * 9216 + row * AT_RS + seg * 16,
                 base + (size_t)krow * D_QK + h * 64 + seg * 8);
        }
        cp_commit();
    };

    LOADKV(k0);
    cp_wait0();
    __syncthreads();

    float m0 = -1e30f, m1 = -1e30f, den0 = 0.f, den1 = 0.f;
    float acc_o[8][4];
#pragma unroll
    for (int t = 0; t < 8; t++)
#pragma unroll
        for (int j = 0; j < 4; j++) acc_o[t][j] = 0.f;

    for (int kc = k0; kc < k1; kc += 64) {
        const int cl = min(64, k1 - kc);

        // ---- S = Q @ K^T ----
        float sc[8][4];
#pragma unroll
        for (int t = 0; t < 8; t++)
#pragma unroll
            for (int j = 0; j < 4; j++) sc[t][j] = 0.f;
#pragma unroll
        for (int ks = 0; ks < 4; ks++) {
            uint32_t qh0, qh1, qh2, qh3, ql0, ql1, ql2, ql3;
            ldsm4(qh0, qh1, qh2, qh3, sb + AQH + aQ + ks * 32);
            ldsm4(ql0, ql1, ql2, ql3, sb + AQL + aQ + ks * 32);
#pragma unroll
            for (int p = 0; p < 4; p++) {
                uint32_t kaddr = sb + AKH + bK + p * (16 * AT_RS) + ks * 32;
                uint32_t kh0, kh1, kh2, kh3, kl0, kl1, kl2, kl3;
                ldsm4(kh0, kh1, kh2, kh3, kaddr);
                ldsm4(kl0, kl1, kl2, kl3, kaddr + 9216);
                mma16816h(sc[p * 2],     qh0, qh1, qh2, qh3, kh0, kh1);
                mma16816h(sc[p * 2],     qh0, qh1, qh2, qh3, kl0, kl1);
                mma16816h(sc[p * 2],     ql0, ql1, ql2, ql3, kh0, kh1);
                mma16816h(sc[p * 2 + 1], qh0, qh1, qh2, qh3, kh2, kh3);
                mma16816h(sc[p * 2 + 1], qh0, qh1, qh2, qh3, kl2, kl3);
                mma16816h(sc[p * 2 + 1], ql0, ql1, ql2, ql3, kh2, kh3);
            }
        }

        // ---- scale + mask + row max ----
        float M0 = -1e30f, M1 = -1e30f;
#pragma unroll
        for (int tn = 0; tn < 8; tn++) {
            int c0 = tn * 8 + tq * 2, c1 = c0 + 1;
            sc[tn][0] = (c0 < cl) ? sc[tn][0] * SCALER : -1e30f;
            sc[tn][1] = (c1 < cl) ? sc[tn][1] * SCALER : -1e30f;
            sc[tn][2] = (c0 < cl) ? sc[tn][2] * SCALER : -1e30f;
            sc[tn][3] = (c1 < cl) ? sc[tn][3] * SCALER : -1e30f;
            M0 = fmaxf(M0, fmaxf(sc[tn][0], sc[tn][1]));
            M1 = fmaxf(M1, fmaxf(sc[tn][2], sc[tn][3]));
        }
        M0 = fmaxf(M0, __shfl_xor_sync(0xffffffffu, M0, 1));
        M0 = fmaxf(M0, __shfl_xor_sync(0xffffffffu, M0, 2));
        M1 = fmaxf(M1, __shfl_xor_sync(0xffffffffu, M1, 1));
        M1 = fmaxf(M1, __shfl_xor_sync(0xffffffffu, M1, 2));

        const float nm0 = fmaxf(m0, M0), nm1 = fmaxf(m1, M1);
        const float corr0 = __expf(m0 - nm0), corr1 = __expf(m1 - nm1);
        m0 = nm0; m1 = nm1;

        // ---- exp, P hi/lo fragments, row sums ----
        uint32_t Ph01[8], Ph23[8], Pl01[8], Pl23[8];
        float sum0 = 0.f, sum1 = 0.f;
#pragma unroll
        for (int tn = 0; tn < 8; tn++) {
            float p0 = __expf(sc[tn][0] - nm0), p1 = __expf(sc[tn][1] - nm0);
            float p2 = __expf(sc[tn][2] - nm1), p3 = __expf(sc[tn][3] - nm1);
            sum0 += p0 + p1; sum1 += p2 + p3;
            __half h0 = __float2half(p0), h1 = __float2half(p1);
            __half h2 = __float2half(p2), h3 = __float2half(p3);
            Ph01[tn] = pack2(h0, h1);
            Ph23[tn] = pack2(h2, h3);
            Pl01[tn] = pack2(__float2half(p0 - __half2float(h0)),
                             __float2half(p1 - __half2float(h1)));
            Pl23[tn] = pack2(__float2half(p2 - __half2float(h2)),
                             __float2half(p3 - __half2float(h3)));
        }
        sum0 += __shfl_xor_sync(0xffffffffu, sum0, 1);
        sum0 += __shfl_xor_sync(0xffffffffu, sum0, 2);
        sum1 += __shfl_xor_sync(0xffffffffu, sum1, 1);
        sum1 += __shfl_xor_sync(0xffffffffu, sum1, 2);
        den0 = den0 * corr0 + sum0;
        den1 = den1 * corr1 + sum1;

#pragma unroll
        for (int tn = 0; tn < 8; tn++) {
            acc_o[tn][0] *= corr0; acc_o[tn][1] *= corr0;
            acc_o[tn][2] *= corr1; acc_o[tn][3] *= corr1;
        }

        // ---- O += P @ V ----
#pragma unroll
        for (int kt = 0; kt < 4; kt++) {
            uint32_t ah0 = Ph01[2 * kt], ah1 = Ph23[2 * kt];
            uint32_t ah2 = Ph01[2 * kt + 1], ah3 = Ph23[2 * kt + 1];
            uint32_t al0 = Pl01[2 * kt], al1 = Pl23[2 * kt];
            uint32_t al2 = Pl01[2 * kt + 1], al3 = Pl23[2 * kt + 1];
#pragma unroll
            for (int dp = 0; dp < 4; dp++) {
                uint32_t vaddr = sb + AVH + bV + kt * (16 * AT_RS) + dp * 32;
                uint32_t vh0, vh1, vh2, vh3, vl0, vl1, vl2, vl3;
                ldsm4t(vh0, vh1, vh2, vh3, vaddr);
                ldsm4t(vl0, vl1, vl2, vl3, vaddr + 9216);
                mma16816h(acc_o[dp * 2],     ah0, ah1, ah2, ah3, vh0, vh1);
                mma16816h(acc_o[dp * 2],     ah0, ah1, ah2, ah3, vl0, vl1);
                mma16816h(acc_o[dp * 2],     al0, al1, al2, al3, vh0, vh1);
                mma16816h(acc_o[dp * 2 + 1], ah0, ah1, ah2, ah3, vh2, vh3);
                mma16816h(acc_o[dp * 2 + 1], ah0, ah1, ah2, ah3, vl2, vl3);
                mma16816h(acc_o[dp * 2 + 1], al0, al1, al2, al3, vh2, vh3);
            }
        }

        __syncthreads();
        if (kc + 64 < k1) {
            LOADKV(kc + 64);
            cp_wait0();
            __syncthreads();
        }
    }

    // ---- normalize + store fp16 ----
    const float inv0 = 1.f / den0, inv1 = 1.f / den1;
    const int row0 = q0 + wid * 16 + qid, row1 = row0 + 8;
#pragma unroll
    for (int tn = 0; tn < 8; tn++) {
        int col = h * 64 + tn * 8 + tq * 2;
        if (row0 < q1)
            *(uint32_t*)&g_WVh[(size_t)row0 * KP_A + col] =
                pack2(__float2half(acc_o[tn][0] * inv0), __float2half(acc_o[tn][1] * inv0));
        if (row1 < q1)
            *(uint32_t*)&g_WVh[(size_t)row1 * KP_A + col] =
                pack2(__float2half(acc_o[tn][2] * inv1), __float2half(acc_o[tn][3] * inv1));
    }
}

// ---------------------------------------------------------------------------
// Launch
// ---------------------------------------------------------------------------
extern "C" void kernel_launch(void* const* d_in, const int* in_sizes, int n_in,
                              void* d_out, int out_size)
{
    const float* A     = (const float*)d_in[0];
    const float* B0    = (const float*)d_in[1];
    const int*   seg_q = (const int*)  d_in[2];
    const int*   seg_kv= (const int*)  d_in[3];
    const float* Wq    = (const float*)d_in[4];
    const float* bq    = (const float*)d_in[5];
    const float* Wk    = (const float*)d_in[6];
    const float* bk    = (const float*)d_in[7];
    const float* Wv    = (const float*)d_in[8];
    const float* bv    = (const float*)d_in[9];
    const float* Wf    = (const float*)d_in[10];
    const float* bf    = (const float*)d_in[11];
    float*       out   = (float*)d_out;

    __half *Ahp, *B0hp;
    cudaGetSymbolAddress((void**)&Ahp,  g_Ah);
    cudaGetSymbolAddress((void**)&B0hp, g_B0h);

    cudaFuncSetAttribute(gemm_qkv,   cudaFuncAttributeMaxDynamicSharedMemorySize, GEMM_SMEM);
    cudaFuncSetAttribute(gemm_final, cudaFuncAttributeMaxDynamicSharedMemorySize, GEMM_SMEM);
    cudaFuncSetAttribute(attn_fa,    cudaFuncAttributeMaxDynamicSharedMemorySize, ATTN_SMEM);

    seg_bounds2<<<(TOTAL_Q + 255) / 256, 256>>>(seg_q, seg_kv);
    convert_all<<<CV_TOT, 256>>>(A, B0, Wq, Wk, Wv, Wf);

    gemm_qkv<<<dim3(D_QK / BN, TOTAL_Q / BM, 3), 256, GEMM_SMEM>>>(
        Ahp, B0hp, bq, bk, bv);

    attn_fa<<<dim3(N_HEADS, N_IMAGES, 8), 128, ATTN_SMEM>>>();

    gemm_final<<<dim3(Q_IN / BN, TOTAL_Q / BM), 256, GEMM_SMEM>>>(bf, out);
}

// round 12
// speedup vs baseline: 5.7988x; 1.4766x over previous
#include <cuda_runtime.h>
#include <cuda_fp16.h>
#include <cstdint>
#include <math.h>

// ---------------------------------------------------------------------------
// Problem constants
// ---------------------------------------------------------------------------
#define TOTAL_Q   2048
#define TOTAL_KV  2048
#define Q_IN      1024
#define KV_IN     1033
#define D_QK      1024
#define D_V       1024
#define N_HEADS   16
#define HEAD_DIM  64
#define N_IMAGES  32
#define SCALER    0.125f

#define KP_A 1024
#define KP_B 1088              // 17 * 64

// ---------------------------------------------------------------------------
// Device scratch
// ---------------------------------------------------------------------------
__device__ int   g_kv_start[N_IMAGES], g_kv_end[N_IMAGES];
__device__ int   g_q_start [N_IMAGES], g_q_end [N_IMAGES];

__device__ __half g_Ah  [TOTAL_Q  * KP_A];
__device__ __half g_B0h [TOTAL_KV * KP_B];
__device__ __half g_WVh [TOTAL_Q  * KP_A];
__device__ __half g_Qhi [TOTAL_Q  * D_QK], g_Qlo [TOTAL_Q  * D_QK];
__device__ __half g_Khi [TOTAL_KV * D_QK], g_Klo [TOTAL_KV * D_QK];
__device__ __half g_Vhi [TOTAL_KV * D_V ], g_Vlo [TOTAL_KV * D_V ];
__device__ __half g_WqT [D_QK * KP_A];
__device__ __half g_WkT [D_QK * KP_B];
__device__ __half g_WvT [D_V  * KP_B];
__device__ __half g_WfT [Q_IN * KP_A];

// ---------------------------------------------------------------------------
// PTX helpers
// ---------------------------------------------------------------------------
__device__ __forceinline__ uint32_t smem_u32(const void* p) {
    uint32_t a;
    asm("{ .reg .u64 t; cvta.to.shared.u64 t, %1; cvt.u32.u64 %0, t; }" : "=r"(a) : "l"(p));
    return a;
}
__device__ __forceinline__ void mma16816h(float* c,
    uint32_t a0, uint32_t a1, uint32_t a2, uint32_t a3,
    uint32_t b0, uint32_t b1)
{
    asm volatile(
        "mma.sync.aligned.m16n8k16.row.col.f32.f16.f16.f32 "
        "{%0,%1,%2,%3}, {%4,%5,%6,%7}, {%8,%9}, {%0,%1,%2,%3};"
        : "+f"(c[0]), "+f"(c[1]), "+f"(c[2]), "+f"(c[3])
        : "r"(a0), "r"(a1), "r"(a2), "r"(a3), "r"(b0), "r"(b1));
}
__device__ __forceinline__ void ldsm4(uint32_t& r0, uint32_t& r1, uint32_t& r2, uint32_t& r3,
                                      uint32_t addr)
{
    asm volatile("ldmatrix.sync.aligned.m8n8.x4.shared.b16 {%0,%1,%2,%3}, [%4];"
                 : "=r"(r0), "=r"(r1), "=r"(r2), "=r"(r3) : "r"(addr));
}
__device__ __forceinline__ void ldsm4t(uint32_t& r0, uint32_t& r1, uint32_t& r2, uint32_t& r3,
                                       uint32_t addr)
{
    asm volatile("ldmatrix.sync.aligned.m8n8.x4.trans.shared.b16 {%0,%1,%2,%3}, [%4];"
                 : "=r"(r0), "=r"(r1), "=r"(r2), "=r"(r3) : "r"(addr));
}
__device__ __forceinline__ void cp16(uint32_t dst, const void* src)
{
    asm volatile("cp.async.cg.shared.global [%0], [%1], 16;" :: "r"(dst), "l"(src) : "memory");
}
__device__ __forceinline__ void cp_commit() { asm volatile("cp.async.commit_group;" ::: "memory"); }
__device__ __forceinline__ void cp_wait0()  { asm volatile("cp.async.wait_group 0;"  ::: "memory"); }

__device__ __forceinline__ void split_fp16(float x, __half& hi, __half& lo)
{
    hi = __float2half(x);
    lo = __float2half(x - __half2float(hi));
}
__device__ __forceinline__ uint32_t pack2(__half a, __half b)
{
    __half2 h = __halves2half2(a, b);
    return *(uint32_t*)&h;
}

// ---------------------------------------------------------------------------
// Fused conversions + segment bounds (one flat grid)
//  J0 act A  -> g_Ah     8192 blocks
//  J1 act B0 -> g_B0h    8704
//  J2-J5 W^T (hi only)   1024/1088/1088/1024
//  J6 seg bounds         8
// ---------------------------------------------------------------------------
#define CV_O1 8192
#define CV_O2 16896
#define CV_O3 17920
#define CV_O4 19008
#define CV_O5 20096
#define CV_O6 21120
#define CV_TOT (CV_O6 + 8)

__device__ __forceinline__ void wT_job(const float* __restrict__ W,
                                       __half* __restrict__ hiT,
                                       int K, int N, int Kp, int local, int tid)
{
    __shared__ float t[32][33];
    int kbn = Kp >> 5;
    int kb = local % kbn, nb = local / kbn;
    int k0 = kb * 32, n0 = nb * 32;
    int tx = tid & 31, ty = tid >> 5;
#pragma unroll
    for (int i = 0; i < 4; i++) {
        int k = k0 + ty + i * 8;
        t[ty + i * 8][tx] = (k < K) ? W[(size_t)k * N + n0 + tx] : 0.f;
    }
    __syncthreads();
#pragma unroll
    for (int i = 0; i < 4; i++) {
        int n = n0 + ty + i * 8;
        hiT[(size_t)n * Kp + k0 + tx] = __float2half(t[tx][ty + i * 8]);
    }
}

__global__ __launch_bounds__(256) void convert_all(
    const float* __restrict__ A,  const float* __restrict__ B0,
    const float* __restrict__ Wq, const float* __restrict__ Wk,
    const float* __restrict__ Wv, const float* __restrict__ Wf,
    const int* __restrict__ sq,   const int* __restrict__ skv)
{
    const int b = blockIdx.x, tid = threadIdx.x;
    if (b < CV_O1) {
        int idx = b * 256 + tid;
        g_Ah[idx] = __float2half(A[idx]);
    } else if (b < CV_O2) {
        int idx = (b - CV_O1) * 256 + tid;
        int m = idx / KP_B, k = idx - m * KP_B;
        float x = (k < KV_IN) ? B0[(size_t)m * KV_IN + k] : 0.f;
        g_B0h[idx] = __float2half(x);
    } else if (b < CV_O3) {
        wT_job(Wq, g_WqT, Q_IN,  D_QK, KP_A, b - CV_O2, tid);
    } else if (b < CV_O4) {
        wT_job(Wk, g_WkT, KV_IN, D_QK, KP_B, b - CV_O3, tid);
    } else if (b < CV_O5) {
        wT_job(Wv, g_WvT, KV_IN, D_V,  KP_B, b - CV_O4, tid);
    } else if (b < CV_O6) {
        wT_job(Wf, g_WfT, D_V,   Q_IN, KP_A, b - CV_O5, tid);
    } else {
        int i = (b - CV_O6) * 256 + tid;
        if (i < TOTAL_Q) {
            int s = sq[i];
            if (i == 0           || sq[i - 1] != s) g_q_start[s] = i;
            if (i == TOTAL_Q - 1 || sq[i + 1] != s) g_q_end[s]   = i + 1;
        }
        if (i < TOTAL_KV) {
            int s = skv[i];
            if (i == 0            || skv[i - 1] != s) g_kv_start[s] = i;
            if (i == TOTAL_KV - 1 || skv[i + 1] != s) g_kv_end[s]   = i + 1;
        }
    }
}

// ---------------------------------------------------------------------------
// fp16 1-term GEMM core (BK=64): C = Ah @ WhiT^T + bias
// 256 threads, warp tile 16x64, 2-stage cp.async pipe, ldmatrix.
// SMEM row stride 144B (conflict-free ldmatrix).
// ---------------------------------------------------------------------------
#define BM 64
#define BN 128
#define BK 64
#define RSTRIDE 144
#define A_OFF   0
#define B_OFF   (64 * RSTRIDE)                 // 9216
#define STAGE   (B_OFF + 128 * RSTRIDE)        // 27648
#define GEMM_SMEM (2 * STAGE)                  // 55296

template<int SPLIT>
__device__ __forceinline__ void gemm_core(
    char* smc,
    const __half* __restrict__ Ah, const __half* __restrict__ Bh,
    const float* __restrict__ bias,
    float* __restrict__ C, __half* __restrict__ Chi, __half* __restrict__ Clo,
    int N, int Kp, int bm, int bn)
{
    const uint32_t sb = smem_u32(smc);
    const int tid  = threadIdx.x;
    const int lane = tid & 31;
    const int wid  = tid >> 5;
    const int qid  = lane >> 2;
    const int tq   = lane & 3;
    const int warpM = wid & 3;
    const int warpN = wid >> 2;
    const int chunks = Kp >> 6;

    const uint32_t g = lane >> 3;
    const uint32_t aOff = A_OFF
        + (warpM * 16 + (g & 1) * 8 + (lane & 7)) * RSTRIDE + ((g >> 1) * 8) * 2;
    const uint32_t bOff = B_OFF
        + (warpN * 64 + (g >> 1) * 8 + (lane & 7)) * RSTRIDE + ((g & 1) * 8) * 2;

    float acc[8][4];
#pragma unroll
    for (int t = 0; t < 8; t++)
#pragma unroll
        for (int j = 0; j < 4; j++) acc[t][j] = 0.f;

    auto PREFETCH = [&](int c, int s) {
        uint32_t stb = sb + s * STAGE;
        const int kb = c * BK;
#pragma unroll
        for (int i = 0; i < 2; i++) {           // A: 64 rows x 8 segs
            int u = tid + i * 256;
            int row = u >> 3, seg = u & 7;
            cp16(stb + A_OFF + row * RSTRIDE + seg * 16,
                 &Ah[(size_t)(bm + row) * Kp + kb + seg * 8]);
        }
#pragma unroll
        for (int i = 0; i < 4; i++) {           // B: 128 rows x 8 segs
            int u = tid + i * 256;
            int row = u >> 3, seg = u & 7;
            cp16(stb + B_OFF + row * RSTRIDE + seg * 16,
                 &Bh[(size_t)(bn + row) * Kp + kb + seg * 8]);
        }
        cp_commit();
    };

    auto COMPUTE = [&](int s) {
        uint32_t stb = sb + s * STAGE;
#pragma unroll
        for (int ks = 0; ks < 4; ks++) {
            uint32_t a0, a1, a2, a3;
            ldsm4(a0, a1, a2, a3, stb + aOff + ks * 32);
#pragma unroll
            for (int p = 0; p < 4; p++) {
                uint32_t b0, b1, b2, b3;
                ldsm4(b0, b1, b2, b3, stb + bOff + p * (16 * RSTRIDE) + ks * 32);
                mma16816h(acc[p * 2],     a0, a1, a2, a3, b0, b1);
                mma16816h(acc[p * 2 + 1], a0, a1, a2, a3, b2, b3);
            }
        }
    };

    PREFETCH(0, 0);
    cp_wait0();
    __syncthreads();

    for (int c = 0; c < chunks; c++) {
        int s = c & 1;
        if (c + 1 < chunks) PREFETCH(c + 1, s ^ 1);
        COMPUTE(s);
        if (c + 1 < chunks) cp_wait0();
        __syncthreads();
    }

    const int r0 = bm + warpM * 16 + qid;
#pragma unroll
    for (int tn = 0; tn < 8; tn++) {
        const int col = bn + warpN * 64 + tn * 8 + tq * 2;
        float2 b2 = *(const float2*)&bias[col];
        float v0 = acc[tn][0] + b2.x, v1 = acc[tn][1] + b2.y;
        float v2 = acc[tn][2] + b2.x, v3 = acc[tn][3] + b2.y;
        if (SPLIT) {
            __half h0, l0, h1, l1, h2, l2, h3, l3;
            split_fp16(v0, h0, l0); split_fp16(v1, h1, l1);
            split_fp16(v2, h2, l2); split_fp16(v3, h3, l3);
            *(uint32_t*)&Chi[(size_t)r0 * N + col]       = pack2(h0, h1);
            *(uint32_t*)&Clo[(size_t)r0 * N + col]       = pack2(l0, l1);
            *(uint32_t*)&Chi[(size_t)(r0 + 8) * N + col] = pack2(h2, h3);
            *(uint32_t*)&Clo[(size_t)(r0 + 8) * N + col] = pack2(l2, l3);
        } else {
            *(float2*)&C[(size_t)r0 * N + col]       = make_float2(v0, v1);
            *(float2*)&C[(size_t)(r0 + 8) * N + col] = make_float2(v2, v3);
        }
    }
}

__global__ __launch_bounds__(256, 2) void gemm_qkv(
    const __half* __restrict__ Ah, const __half* __restrict__ B0h,
    const float* __restrict__ bq, const float* __restrict__ bk,
    const float* __restrict__ bv)
{
    extern __shared__ char smc[];
    const int z = blockIdx.z;
    const __half* A   = (z == 0) ? Ah : B0h;
    const __half* Bh  = (z == 0) ? g_WqT : (z == 1) ? g_WkT : g_WvT;
    const float* bias = (z == 0) ? bq : (z == 1) ? bk : bv;
    __half* Chi       = (z == 0) ? g_Qhi : (z == 1) ? g_Khi : g_Vhi;
    __half* Clo       = (z == 0) ? g_Qlo : (z == 1) ? g_Klo : g_Vlo;
    const int Kp      = (z == 0) ? KP_A : KP_B;
    gemm_core<1>(smc, A, Bh, bias, nullptr, Chi, Clo, D_QK, Kp,
                 blockIdx.y * BM, blockIdx.x * BN);
}

__global__ __launch_bounds__(256, 2) void gemm_final(
    const float* __restrict__ bf, float* __restrict__ out)
{
    extern __shared__ char smc[];
    gemm_core<0>(smc, g_WVh, g_WfT, bf, out, nullptr, nullptr,
                 Q_IN, KP_A, blockIdx.y * BM, blockIdx.x * BN);
}

// ---------------------------------------------------------------------------
// Flash attention: block = (head, seg, 64-q tile), 4 warps, warp = 16 q rows.
// S = Q@K^T (3-term hi/lo mma), fragment online softmax, O += P@V (3-term).
// ---------------------------------------------------------------------------
#define AT_RS 144
#define AQH 0
#define AQL 9216
#define AKH (2 * 9216)
#define AVH (4 * 9216)
#define ATTN_SMEM (6 * 9216)     // 55296

__global__ __launch_bounds__(128) void attn_fa()
{
    extern __shared__ char smc[];
    const uint32_t sb = smem_u32(smc);
    const int h = blockIdx.x, s = blockIdx.y, qb = blockIdx.z;
    const int k0 = g_kv_start[s], k1 = g_kv_end[s];
    const int qs = g_q_start[s],  qe = g_q_end[s];
    const int q0 = qs + qb * 64;
    if (q0 >= qe) return;
    const int q1 = min(q0 + 64, qe);

    const int tid = threadIdx.x, lane = tid & 31, wid = tid >> 5;
    const int qid = lane >> 2, tq = lane & 3;
    const uint32_t g = lane >> 3;

    const uint32_t aQ = (wid * 16 + (g & 1) * 8 + (lane & 7)) * AT_RS + ((g >> 1) * 8) * 2;
    const uint32_t bK = ((g >> 1) * 8 + (lane & 7)) * AT_RS + ((g & 1) * 8) * 2;
    const uint32_t bV = ((g & 1) * 8 + (lane & 7)) * AT_RS + ((g >> 1) * 8) * 2;

#pragma unroll
    for (int i = 0; i < 8; i++) {
        int u = tid + i * 128;
        int plane = u >> 9, idx = u & 511;
        int row = idx >> 3, seg = idx & 7;
        int qrow = min(q0 + row, TOTAL_Q - 1);
        const __half* src = (plane ? g_Qlo : g_Qhi) + (size_t)qrow * D_QK + h * 64 + seg * 8;
        cp16(sb + (plane ? AQL : AQH) + row * AT_RS + seg * 16, src);
    }

    auto LOADKV = [&](int kc) {
#pragma unroll
        for (int i = 0; i < 16; i++) {
            int u = tid + i * 128;
            int plane = u >> 9, idx = u & 511;
            int row = idx >> 3, seg = idx & 7;
            int krow = min(kc + row, TOTAL_KV - 1);
            const __half* base = (plane == 0) ? g_Khi : (plane == 1) ? g_Klo
                               : (plane == 2) ? g_Vhi : g_Vlo;
            cp16(sb + AKH + plane * 9216 + row * AT_RS + seg * 16,
                 base + (size_t)krow * D_QK + h * 64 + seg * 8);
        }
        cp_commit();
    };

    LOADKV(k0);
    cp_wait0();
    __syncthreads();

    float m0 = -1e30f, m1 = -1e30f, den0 = 0.f, den1 = 0.f;
    float acc_o[8][4];
#pragma unroll
    for (int t = 0; t < 8; t++)
#pragma unroll
        for (int j = 0; j < 4; j++) acc_o[t][j] = 0.f;

    for (int kc = k0; kc < k1; kc += 64) {
        const int cl = min(64, k1 - kc);

        float sc[8][4];
#pragma unroll
        for (int t = 0; t < 8; t++)
#pragma unroll
            for (int j = 0; j < 4; j++) sc[t][j] = 0.f;
#pragma unroll
        for (int ks = 0; ks < 4; ks++) {
            uint32_t qh0, qh1, qh2, qh3, ql0, ql1, ql2, ql3;
            ldsm4(qh0, qh1, qh2, qh3, sb + AQH + aQ + ks * 32);
            ldsm4(ql0, ql1, ql2, ql3, sb + AQL + aQ + ks * 32);
#pragma unroll
            for (int p = 0; p < 4; p++) {
                uint32_t kaddr = sb + AKH + bK + p * (16 * AT_RS) + ks * 32;
                uint32_t kh0, kh1, kh2, kh3, kl0, kl1, kl2, kl3;
                ldsm4(kh0, kh1, kh2, kh3, kaddr);
                ldsm4(kl0, kl1, kl2, kl3, kaddr + 9216);
                mma16816h(sc[p * 2],     qh0, qh1, qh2, qh3, kh0, kh1);
                mma16816h(sc[p * 2],     qh0, qh1, qh2, qh3, kl0, kl1);
                mma16816h(sc[p * 2],     ql0, ql1, ql2, ql3, kh0, kh1);
                mma16816h(sc[p * 2 + 1], qh0, qh1, qh2, qh3, kh2, kh3);
                mma16816h(sc[p * 2 + 1], qh0, qh1, qh2, qh3, kl2, kl3);
                mma16816h(sc[p * 2 + 1], ql0, ql1, ql2, ql3, kh2, kh3);
            }
        }

        float M0 = -1e30f, M1 = -1e30f;
#pragma unroll
        for (int tn = 0; tn < 8; tn++) {
            int c0 = tn * 8 + tq * 2, c1 = c0 + 1;
            sc[tn][0] = (c0 < cl) ? sc[tn][0] * SCALER : -1e30f;
            sc[tn][1] = (c1 < cl) ? sc[tn][1] * SCALER : -1e30f;
            sc[tn][2] = (c0 < cl) ? sc[tn][2] * SCALER : -1e30f;
            sc[tn][3] = (c1 < cl) ? sc[tn][3] * SCALER : -1e30f;
            M0 = fmaxf(M0, fmaxf(sc[tn][0], sc[tn][1]));
            M1 = fmaxf(M1, fmaxf(sc[tn][2], sc[tn][3]));
        }
        M0 = fmaxf(M0, __shfl_xor_sync(0xffffffffu, M0, 1));
        M0 = fmaxf(M0, __shfl_xor_sync(0xffffffffu, M0, 2));
        M1 = fmaxf(M1, __shfl_xor_sync(0xffffffffu, M1, 1));
        M1 = fmaxf(M1, __shfl_xor_sync(0xffffffffu, M1, 2));

        const float nm0 = fmaxf(m0, M0), nm1 = fmaxf(m1, M1);
        const float corr0 = __expf(m0 - nm0), corr1 = __expf(m1 - nm1);
        m0 = nm0; m1 = nm1;

        uint32_t Ph01[8], Ph23[8], Pl01[8], Pl23[8];
        float sum0 = 0.f, sum1 = 0.f;
#pragma unroll
        for (int tn = 0; tn < 8; tn++) {
            float p0 = __expf(sc[tn][0] - nm0), p1 = __expf(sc[tn][1] - nm0);
            float p2 = __expf(sc[tn][2] - nm1), p3 = __expf(sc[tn][3] - nm1);
            sum0 += p0 + p1; sum1 += p2 + p3;
            __half h0 = __float2half(p0), h1 = __float2half(p1);
            __half h2 = __float2half(p2), h3 = __float2half(p3);
            Ph01[tn] = pack2(h0, h1);
            Ph23[tn] = pack2(h2, h3);
            Pl01[tn] = pack2(__float2half(p0 - __half2float(h0)),
                             __float2half(p1 - __half2float(h1)));
            Pl23[tn] = pack2(__float2half(p2 - __half2float(h2)),
                             __float2half(p3 - __half2float(h3)));
        }
        sum0 += __shfl_xor_sync(0xffffffffu, sum0, 1);
        sum0 += __shfl_xor_sync(0xffffffffu, sum0, 2);
        sum1 += __shfl_xor_sync(0xffffffffu, sum1, 1);
        sum1 += __shfl_xor_sync(0xffffffffu, sum1, 2);
        den0 = den0 * corr0 + sum0;
        den1 = den1 * corr1 + sum1;

#pragma unroll
        for (int tn = 0; tn < 8; tn++) {
            acc_o[tn][0] *= corr0; acc_o[tn][1] *= corr0;
            acc_o[tn][2] *= corr1; acc_o[tn][3] *= corr1;
        }

#pragma unroll
        for (int kt = 0; kt < 4; kt++) {
            uint32_t ah0 = Ph01[2 * kt], ah1 = Ph23[2 * kt];
            uint32_t ah2 = Ph01[2 * kt + 1], ah3 = Ph23[2 * kt + 1];
            uint32_t al0 = Pl01[2 * kt], al1 = Pl23[2 * kt];
            uint32_t al2 = Pl01[2 * kt + 1], al3 = Pl23[2 * kt + 1];
#pragma unroll
            for (int dp = 0; dp < 4; dp++) {
                uint32_t vaddr = sb + AVH + bV + kt * (16 * AT_RS) + dp * 32;
                uint32_t vh0, vh1, vh2, vh3, vl0, vl1, vl2, vl3;
                ldsm4t(vh0, vh1, vh2, vh3, vaddr);
                ldsm4t(vl0, vl1, vl2, vl3, vaddr + 9216);
                mma16816h(acc_o[dp * 2],     ah0, ah1, ah2, ah3, vh0, vh1);
                mma16816h(acc_o[dp * 2],     ah0, ah1, ah2, ah3, vl0, vl1);
                mma16816h(acc_o[dp * 2],     al0, al1, al2, al3, vh0, vh1);
                mma16816h(acc_o[dp * 2 + 1], ah0, ah1, ah2, ah3, vh2, vh3);
                mma16816h(acc_o[dp * 2 + 1], ah0, ah1, ah2, ah3, vl2, vl3);
                mma16816h(acc_o[dp * 2 + 1], al0, al1, al2, al3, vh2, vh3);
            }
        }

        __syncthreads();
        if (kc + 64 < k1) {
            LOADKV(kc + 64);
            cp_wait0();
            __syncthreads();
        }
    }

    const float inv0 = 1.f / den0, inv1 = 1.f / den1;
    const int row0 = q0 + wid * 16 + qid, row1 = row0 + 8;
#pragma unroll
    for (int tn = 0; tn < 8; tn++) {
        int col = h * 64 + tn * 8 + tq * 2;
        if (row0 < q1)
            *(uint32_t*)&g_WVh[(size_t)row0 * KP_A + col] =
                pack2(__float2half(acc_o[tn][0] * inv0), __float2half(acc_o[tn][1] * inv0));
        if (row1 < q1)
            *(uint32_t*)&g_WVh[(size_t)row1 * KP_A + col] =
                pack2(__float2half(acc_o[tn][2] * inv1), __float2half(acc_o[tn][3] * inv1));
    }
}

// ---------------------------------------------------------------------------
// Launch
// ---------------------------------------------------------------------------
extern "C" void kernel_launch(void* const* d_in, const int* in_sizes, int n_in,
                              void* d_out, int out_size)
{
    const float* A     = (const float*)d_in[0];
    const float* B0    = (const float*)d_in[1];
    const int*   seg_q = (const int*)  d_in[2];
    const int*   seg_kv= (const int*)  d_in[3];
    const float* Wq    = (const float*)d_in[4];
    const float* bq    = (const float*)d_in[5];
    const float* Wk    = (const float*)d_in[6];
    const float* bk    = (const float*)d_in[7];
    const float* Wv    = (const float*)d_in[8];
    const float* bv    = (const float*)d_in[9];
    const float* Wf    = (const float*)d_in[10];
    const float* bf    = (const float*)d_in[11];
    float*       out   = (float*)d_out;

    __half *Ahp, *B0hp;
    cudaGetSymbolAddress((void**)&Ahp,  g_Ah);
    cudaGetSymbolAddress((void**)&B0hp, g_B0h);

    cudaFuncSetAttribute(gemm_qkv,   cudaFuncAttributeMaxDynamicSharedMemorySize, GEMM_SMEM);
    cudaFuncSetAttribute(gemm_final, cudaFuncAttributeMaxDynamicSharedMemorySize, GEMM_SMEM);
    cudaFuncSetAttribute(attn_fa,    cudaFuncAttributeMaxDynamicSharedMemorySize, ATTN_SMEM);

    convert_all<<<CV_TOT, 256>>>(A, B0, Wq, Wk, Wv, Wf, seg_q, seg_kv);

    gemm_qkv<<<dim3(D_QK / BN, TOTAL_Q / BM, 3), 256, GEMM_SMEM>>>(
        Ahp, B0hp, bq, bk, bv);

    attn_fa<<<dim3(N_HEADS, N_IMAGES, 8), 128, ATTN_SMEM>>>();

    gemm_final<<<dim3(Q_IN / BN, TOTAL_Q / BM), 256, GEMM_SMEM>>>(bf, out);
}

// round 14
// speedup vs baseline: 6.3261x; 1.0909x over previous
#include <cuda_runtime.h>
#include <cuda_fp16.h>
#include <cstdint>
#include <math.h>

// ---------------------------------------------------------------------------
// Problem constants
// ---------------------------------------------------------------------------
#define TOTAL_Q   2048
#define TOTAL_KV  2048
#define Q_IN      1024
#define KV_IN     1033
#define D_QK      1024
#define D_V       1024
#define N_HEADS   16
#define HEAD_DIM  64
#define N_IMAGES  32
#define SCALER    0.125f

#define KP_A 1024
#define KP_B 1088              // 17 * 64

// ---------------------------------------------------------------------------
// Device scratch
// ---------------------------------------------------------------------------
__device__ int   g_kv_start[N_IMAGES], g_kv_end[N_IMAGES];
__device__ int   g_q_start [N_IMAGES], g_q_end [N_IMAGES];

__device__ __half g_Ah  [TOTAL_Q  * KP_A];
__device__ __half g_B0h [TOTAL_KV * KP_B];
__device__ __half g_WVh [TOTAL_Q  * KP_A];
__device__ __half g_Qhi [TOTAL_Q  * D_QK], g_Qlo [TOTAL_Q  * D_QK];
__device__ __half g_Khi [TOTAL_KV * D_QK], g_Klo [TOTAL_KV * D_QK];
__device__ __half g_Vhi [TOTAL_KV * D_V ], g_Vlo [TOTAL_KV * D_V ];
__device__ __half g_WqT [D_QK * KP_A];
__device__ __half g_WkT [D_QK * KP_B];
__device__ __half g_WvT [D_V  * KP_B];
__device__ __half g_WfT [Q_IN * KP_A];

// ---------------------------------------------------------------------------
// PTX helpers
// ---------------------------------------------------------------------------
__device__ __forceinline__ uint32_t smem_u32(const void* p) {
    uint32_t a;
    asm("{ .reg .u64 t; cvta.to.shared.u64 t, %1; cvt.u32.u64 %0, t; }" : "=r"(a) : "l"(p));
    return a;
}
__device__ __forceinline__ void mma16816h(float* c,
    uint32_t a0, uint32_t a1, uint32_t a2, uint32_t a3,
    uint32_t b0, uint32_t b1)
{
    asm volatile(
        "mma.sync.aligned.m16n8k16.row.col.f32.f16.f16.f32 "
        "{%0,%1,%2,%3}, {%4,%5,%6,%7}, {%8,%9}, {%0,%1,%2,%3};"
        : "+f"(c[0]), "+f"(c[1]), "+f"(c[2]), "+f"(c[3])
        : "r"(a0), "r"(a1), "r"(a2), "r"(a3), "r"(b0), "r"(b1));
}
__device__ __forceinline__ void ldsm4(uint32_t& r0, uint32_t& r1, uint32_t& r2, uint32_t& r3,
                                      uint32_t addr)
{
    asm volatile("ldmatrix.sync.aligned.m8n8.x4.shared.b16 {%0,%1,%2,%3}, [%4];"
                 : "=r"(r0), "=r"(r1), "=r"(r2), "=r"(r3) : "r"(addr));
}
__device__ __forceinline__ void ldsm4t(uint32_t& r0, uint32_t& r1, uint32_t& r2, uint32_t& r3,
                                       uint32_t addr)
{
    asm volatile("ldmatrix.sync.aligned.m8n8.x4.trans.shared.b16 {%0,%1,%2,%3}, [%4];"
                 : "=r"(r0), "=r"(r1), "=r"(r2), "=r"(r3) : "r"(addr));
}
__device__ __forceinline__ void cp16(uint32_t dst, const void* src)
{
    asm volatile("cp.async.cg.shared.global [%0], [%1], 16;" :: "r"(dst), "l"(src) : "memory");
}
__device__ __forceinline__ void cp_commit() { asm volatile("cp.async.commit_group;" ::: "memory"); }
__device__ __forceinline__ void cp_wait0()  { asm volatile("cp.async.wait_group 0;"  ::: "memory"); }
__device__ __forceinline__ void cp_wait1()  { asm volatile("cp.async.wait_group 1;"  ::: "memory"); }

__device__ __forceinline__ void split_fp16(float x, __half& hi, __half& lo)
{
    hi = __float2half(x);
    lo = __float2half(x - __half2float(hi));
}
__device__ __forceinline__ uint32_t pack2(__half a, __half b)
{
    __half2 h = __halves2half2(a, b);
    return *(uint32_t*)&h;
}

// ---------------------------------------------------------------------------
// Fused conversions + segment bounds (one flat grid)
// ---------------------------------------------------------------------------
#define CV_O1 8192
#define CV_O2 16896
#define CV_O3 17920
#define CV_O4 19008
#define CV_O5 20096
#define CV_O6 21120
#define CV_TOT (CV_O6 + 8)

__device__ __forceinline__ void wT_job(const float* __restrict__ W,
                                       __half* __restrict__ hiT,
                                       int K, int N, int Kp, int local, int tid)
{
    __shared__ float t[32][33];
    int kbn = Kp >> 5;
    int kb = local % kbn, nb = local / kbn;
    int k0 = kb * 32, n0 = nb * 32;
    int tx = tid & 31, ty = tid >> 5;
#pragma unroll
    for (int i = 0; i < 4; i++) {
        int k = k0 + ty + i * 8;
        t[ty + i * 8][tx] = (k < K) ? W[(size_t)k * N + n0 + tx] : 0.f;
    }
    __syncthreads();
#pragma unroll
    for (int i = 0; i < 4; i++) {
        int n = n0 + ty + i * 8;
        hiT[(size_t)n * Kp + k0 + tx] = __float2half(t[tx][ty + i * 8]);
    }
}

__global__ __launch_bounds__(256) void convert_all(
    const float* __restrict__ A,  const float* __restrict__ B0,
    const float* __restrict__ Wq, const float* __restrict__ Wk,
    const float* __restrict__ Wv, const float* __restrict__ Wf,
    const int* __restrict__ sq,   const int* __restrict__ skv)
{
    const int b = blockIdx.x, tid = threadIdx.x;
    if (b < CV_O1) {
        int idx = b * 256 + tid;
        g_Ah[idx] = __float2half(A[idx]);
    } else if (b < CV_O2) {
        int idx = (b - CV_O1) * 256 + tid;
        int m = idx / KP_B, k = idx - m * KP_B;
        float x = (k < KV_IN) ? B0[(size_t)m * KV_IN + k] : 0.f;
        g_B0h[idx] = __float2half(x);
    } else if (b < CV_O3) {
        wT_job(Wq, g_WqT, Q_IN,  D_QK, KP_A, b - CV_O2, tid);
    } else if (b < CV_O4) {
        wT_job(Wk, g_WkT, KV_IN, D_QK, KP_B, b - CV_O3, tid);
    } else if (b < CV_O5) {
        wT_job(Wv, g_WvT, KV_IN, D_V,  KP_B, b - CV_O4, tid);
    } else if (b < CV_O6) {
        wT_job(Wf, g_WfT, D_V,   Q_IN, KP_A, b - CV_O5, tid);
    } else {
        int i = (b - CV_O6) * 256 + tid;
        if (i < TOTAL_Q) {
            int s = sq[i];
            if (i == 0           || sq[i - 1] != s) g_q_start[s] = i;
            if (i == TOTAL_Q - 1 || sq[i + 1] != s) g_q_end[s]   = i + 1;
        }
        if (i < TOTAL_KV) {
            int s = skv[i];
            if (i == 0            || skv[i - 1] != s) g_kv_start[s] = i;
            if (i == TOTAL_KV - 1 || skv[i + 1] != s) g_kv_end[s]   = i + 1;
        }
    }
}

// ---------------------------------------------------------------------------
// fp16 1-term GEMM core: C = Ah @ WT^T + bias
// BM=128, BN=128, BK=32, 256 threads (4x2 warps, warp tile 32x64),
// 3-stage cp.async pipeline (wait_group 1), ldmatrix fragment loads.
// SMEM row = 32 fp16 = 64B, padded stride 80B (conflict-free ldmatrix).
// ---------------------------------------------------------------------------
#define BM 128
#define BN 128
#define BK 32
#define RS 80
#define A_OFF   0
#define B_OFF   (128 * RS)            // 10240
#define STAGE   (2 * 128 * RS)        // 20480
#define NSTG    3
#define GEMM_SMEM (NSTG * STAGE)      // 61440

template<int SPLIT>
__device__ __forceinline__ void gemm_core(
    char* smc,
    const __half* __restrict__ Ah, const __half* __restrict__ Bh,
    const float* __restrict__ bias,
    float* __restrict__ C, __half* __restrict__ Chi, __half* __restrict__ Clo,
    int N, int Kp, int bm, int bn)
{
    const uint32_t sb = smem_u32(smc);
    const int tid  = threadIdx.x;
    const int lane = tid & 31;
    const int wid  = tid >> 5;
    const int qid  = lane >> 2;
    const int tq   = lane & 3;
    const int warpM = wid & 3;        // 4 warps x 32 rows
    const int warpN = wid >> 2;       // 2 warps x 64 cols
    const int chunks = Kp >> 5;

    const uint32_t g = lane >> 3;
    const uint32_t aBase = (warpM * 32 + (g & 1) * 8 + (lane & 7)) * RS + (g >> 1) * 16;
    const uint32_t bBase = (warpN * 64 + (g >> 1) * 8 + (lane & 7)) * RS + (g & 1) * 16;

    float acc[2][8][4];
#pragma unroll
    for (int m2 = 0; m2 < 2; m2++)
#pragma unroll
        for (int t = 0; t < 8; t++)
#pragma unroll
            for (int j = 0; j < 4; j++) acc[m2][t][j] = 0.f;

    const int prow = tid >> 2;        // 0..63 (x2 iters -> 128 rows)
    const int pseg = tid & 3;         // 8-fp16 seg

    auto PREFETCH = [&](int c, int slot) {
        uint32_t stb = sb + slot * STAGE;
        const int kb = c * BK;
#pragma unroll
        for (int i = 0; i < 2; i++) {
            int row = prow + i * 64;
            cp16(stb + A_OFF + row * RS + pseg * 16,
                 &Ah[(size_t)(bm + row) * Kp + kb + pseg * 8]);
            cp16(stb + B_OFF + row * RS + pseg * 16,
                 &Bh[(size_t)(bn + row) * Kp + kb + pseg * 8]);
        }
        cp_commit();
    };

    auto COMPUTE = [&](int slot) {
        uint32_t stb = sb + slot * STAGE;
#pragma unroll
        for (int ks = 0; ks < 2; ks++) {
            uint32_t a0[2], a1[2], a2[2], a3[2];
#pragma unroll
            for (int m2 = 0; m2 < 2; m2++)
                ldsm4(a0[m2], a1[m2], a2[m2], a3[m2],
                      stb + A_OFF + aBase + m2 * (16 * RS) + ks * 32);
#pragma unroll
            for (int p = 0; p < 4; p++) {
                uint32_t b0, b1, b2, b3;
                ldsm4(b0, b1, b2, b3, stb + B_OFF + bBase + p * (16 * RS) + ks * 32);
#pragma unroll
                for (int m2 = 0; m2 < 2; m2++) {
                    mma16816h(acc[m2][p * 2],     a0[m2], a1[m2], a2[m2], a3[m2], b0, b1);
                    mma16816h(acc[m2][p * 2 + 1], a0[m2], a1[m2], a2[m2], a3[m2], b2, b3);
                }
            }
        }
    };

    PREFETCH(0, 0);
    PREFETCH(1, 1);

    int slot = 0;
    for (int c = 0; c < chunks; c++) {
        cp_wait1();
        __syncthreads();
        if (c + 2 < chunks) {
            int s2 = slot + 2; if (s2 >= NSTG) s2 -= NSTG;
            PREFETCH(c + 2, s2);
        }
        COMPUTE(slot);
        if (++slot == NSTG) slot = 0;
    }

    // ---- epilogue ----
#pragma unroll
    for (int m2 = 0; m2 < 2; m2++) {
        const int r0 = bm + warpM * 32 + m2 * 16 + qid;
#pragma unroll
        for (int tn = 0; tn < 8; tn++) {
            const int col = bn + warpN * 64 + tn * 8 + tq * 2;
            float2 b2 = *(const float2*)&bias[col];
            float v0 = acc[m2][tn][0] + b2.x, v1 = acc[m2][tn][1] + b2.y;
            float v2 = acc[m2][tn][2] + b2.x, v3 = acc[m2][tn][3] + b2.y;
            if (SPLIT) {
                __half h0, l0, h1, l1, h2, l2, h3, l3;
                split_fp16(v0, h0, l0); split_fp16(v1, h1, l1);
                split_fp16(v2, h2, l2); split_fp16(v3, h3, l3);
                *(uint32_t*)&Chi[(size_t)r0 * N + col]       = pack2(h0, h1);
                *(uint32_t*)&Clo[(size_t)r0 * N + col]       = pack2(l0, l1);
                *(uint32_t*)&Chi[(size_t)(r0 + 8) * N + col] = pack2(h2, h3);
                *(uint32_t*)&Clo[(size_t)(r0 + 8) * N + col] = pack2(l2, l3);
            } else {
                *(float2*)&C[(size_t)r0 * N + col]       = make_float2(v0, v1);
                *(float2*)&C[(size_t)(r0 + 8) * N + col] = make_float2(v2, v3);
            }
        }
    }
}

__global__ __launch_bounds__(256, 2) void gemm_qkv(
    const __half* __restrict__ Ah, const __half* __restrict__ B0h,
    const float* __restrict__ bq, const float* __restrict__ bk,
    const float* __restrict__ bv)
{
    extern __shared__ char smc[];
    const int z = blockIdx.z;
    const __half* A   = (z == 0) ? Ah : B0h;
    const __half* Bh  = (z == 0) ? g_WqT : (z == 1) ? g_WkT : g_WvT;
    const float* bias = (z == 0) ? bq : (z == 1) ? bk : bv;
    __half* Chi       = (z == 0) ? g_Qhi : (z == 1) ? g_Khi : g_Vhi;
    __half* Clo       = (z == 0) ? g_Qlo : (z == 1) ? g_Klo : g_Vlo;
    const int Kp      = (z == 0) ? KP_A : KP_B;
    gemm_core<1>(smc, A, Bh, bias, nullptr, Chi, Clo, D_QK, Kp,
                 blockIdx.y * BM, blockIdx.x * BN);
}

__global__ __launch_bounds__(256, 2) void gemm_final(
    const float* __restrict__ bf, float* __restrict__ out)
{
    extern __shared__ char smc[];
    gemm_core<0>(smc, g_WVh, g_WfT, bf, out, nullptr, nullptr,
                 Q_IN, KP_A, blockIdx.y * BM, blockIdx.x * BN);
}

// ---------------------------------------------------------------------------
// Flash attention: block = (head, seg, 64-q tile), 4 warps, warp = 16 q rows.
// S = Q@K^T (3-term hi/lo mma), fragment online softmax, O += P@V (3-term).
// ---------------------------------------------------------------------------
#define AT_RS 144
#define AQH 0
#define AQL 9216
#define AKH (2 * 9216)
#define AVH (4 * 9216)
#define ATTN_SMEM (6 * 9216)     // 55296

__global__ __launch_bounds__(128) void attn_fa()
{
    extern __shared__ char smc[];
    const uint32_t sb = smem_u32(smc);
    const int h = blockIdx.x, s = blockIdx.y, qb = blockIdx.z;
    const int k0 = g_kv_start[s], k1 = g_kv_end[s];
    const int qs = g_q_start[s],  qe = g_q_end[s];
    const int q0 = qs + qb * 64;
    if (q0 >= qe) return;
    const int q1 = min(q0 + 64, qe);

    const int tid = threadIdx.x, lane = tid & 31, wid = tid >> 5;
    const int qid = lane >> 2, tq = lane & 3;
    const uint32_t g = lane >> 3;

    const uint32_t aQ = (wid * 16 + (g & 1) * 8 + (lane & 7)) * AT_RS + ((g >> 1) * 8) * 2;
    const uint32_t bK = ((g >> 1) * 8 + (lane & 7)) * AT_RS + ((g & 1) * 8) * 2;
    const uint32_t bV = ((g & 1) * 8 + (lane & 7)) * AT_RS + ((g >> 1) * 8) * 2;

#pragma unroll
    for (int i = 0; i < 8; i++) {
        int u = tid + i * 128;
        int plane = u >> 9, idx = u & 511;
        int row = idx >> 3, seg = idx & 7;
        int qrow = min(q0 + row, TOTAL_Q - 1);
        const __half* src = (plane ? g_Qlo : g_Qhi) + (size_t)qrow * D_QK + h * 64 + seg * 8;
        cp16(sb + (plane ? AQL : AQH) + row * AT_RS + seg * 16, src);
    }

    auto LOADKV = [&](int kc) {
#pragma unroll
        for (int i = 0; i < 16; i++) {
            int u = tid + i * 128;
            int plane = u >> 9, idx = u & 511;
            int row = idx >> 3, seg = idx & 7;
            int krow = min(kc + row, TOTAL_KV - 1);
            const __half* base = (plane == 0) ? g_Khi : (plane == 1) ? g_Klo
                               : (plane == 2) ? g_Vhi : g_Vlo;
            cp16(sb + AKH + plane * 9216 + row * AT_RS + seg * 16,
                 base + (size_t)krow * D_QK + h * 64 + seg * 8);
        }
        cp_commit();
    };

    LOADKV(k0);
    cp_wait0();
    __syncthreads();

    float m0 = -1e30f, m1 = -1e30f, den0 = 0.f, den1 = 0.f;
    float acc_o[8][4];
#pragma unroll
    for (int t = 0; t < 8; t++)
#pragma unroll
        for (int j = 0; j < 4; j++) acc_o[t][j] = 0.f;

    for (int kc = k0; kc < k1; kc += 64) {
        const int cl = min(64, k1 - kc);

        float sc[8][4];
#pragma unroll
        for (int t = 0; t < 8; t++)
#pragma unroll
            for (int j = 0; j < 4; j++) sc[t][j] = 0.f;
#pragma unroll
        for (int ks = 0; ks < 4; ks++) {
            uint32_t qh0, qh1, qh2, qh3, ql0, ql1, ql2, ql3;
            ldsm4(qh0, qh1, qh2, qh3, sb + AQH + aQ + ks * 32);
            ldsm4(ql0, ql1, ql2, ql3, sb + AQL + aQ + ks * 32);
#pragma unroll
            for (int p = 0; p < 4; p++) {
                uint32_t kaddr = sb + AKH + bK + p * (16 * AT_RS) + ks * 32;
                uint32_t kh0, kh1, kh2, kh3, kl0, kl1, kl2, kl3;
                ldsm4(kh0, kh1, kh2, kh3, kaddr);
                ldsm4(kl0, kl1, kl2, kl3, kaddr + 9216);
                mma16816h(sc[p * 2],     qh0, qh1, qh2, qh3, kh0, kh1);
                mma16816h(sc[p * 2],     qh0, qh1, qh2, qh3, kl0, kl1);
                mma16816h(sc[p * 2],     ql0, ql1, ql2, ql3, kh0, kh1);
                mma16816h(sc[p * 2 + 1], qh0, qh1, qh2, qh3, kh2, kh3);
                mma16816h(sc[p * 2 + 1], qh0, qh1, qh2, qh3, kl2, kl3);
                mma16816h(sc[p * 2 + 1], ql0, ql1, ql2, ql3, kh2, kh3);
            }
        }

        float M0 = -1e30f, M1 = -1e30f;
#pragma unroll
        for (int tn = 0; tn < 8; tn++) {
            int c0 = tn * 8 + tq * 2, c1 = c0 + 1;
            sc[tn][0] = (c0 < cl) ? sc[tn][0] * SCALER : -1e30f;
            sc[tn][1] = (c1 < cl) ? sc[tn][1] * SCALER : -1e30f;
            sc[tn][2] = (c0 < cl) ? sc[tn][2] * SCALER : -1e30f;
            sc[tn][3] = (c1 < cl) ? sc[tn][3] * SCALER : -1e30f;
            M0 = fmaxf(M0, fmaxf(sc[tn][0], sc[tn][1]));
            M1 = fmaxf(M1, fmaxf(sc[tn][2], sc[tn][3]));
        }
        M0 = fmaxf(M0, __shfl_xor_sync(0xffffffffu, M0, 1));
        M0 = fmaxf(M0, __shfl_xor_sync(0xffffffffu, M0, 2));
        M1 = fmaxf(M1, __shfl_xor_sync(0xffffffffu, M1, 1));
        M1 = fmaxf(M1, __shfl_xor_sync(0xffffffffu, M1, 2));

        const float nm0 = fmaxf(m0, M0), nm1 = fmaxf(m1, M1);
        const float corr0 = __expf(m0 - nm0), corr1 = __expf(m1 - nm1);
        m0 = nm0; m1 = nm1;

        uint32_t Ph01[8], Ph23[8], Pl01[8], Pl23[8];
        float sum0 = 0.f, sum1 = 0.f;
#pragma unroll
        for (int tn = 0; tn < 8; tn++) {
            float p0 = __expf(sc[tn][0] - nm0), p1 = __expf(sc[tn][1] - nm0);
            float p2 = __expf(sc[tn][2] - nm1), p3 = __expf(sc[tn][3] - nm1);
            sum0 += p0 + p1; sum1 += p2 + p3;
            __half h0 = __float2half(p0), h1 = __float2half(p1);
            __half h2 = __float2half(p2), h3 = __float2half(p3);
            Ph01[tn] = pack2(h0, h1);
            Ph23[tn] = pack2(h2, h3);
            Pl01[tn] = pack2(__float2half(p0 - __half2float(h0)),
                             __float2half(p1 - __half2float(h1)));
            Pl23[tn] = pack2(__float2half(p2 - __half2float(h2)),
                             __float2half(p3 - __half2float(h3)));
        }
        sum0 += __shfl_xor_sync(0xffffffffu, sum0, 1);
        sum0 += __shfl_xor_sync(0xffffffffu, sum0, 2);
        sum1 += __shfl_xor_sync(0xffffffffu, sum1, 1);
        sum1 += __shfl_xor_sync(0xffffffffu, sum1, 2);
        den0 = den0 * corr0 + sum0;
        den1 = den1 * corr1 + sum1;

#pragma unroll
        for (int tn = 0; tn < 8; tn++) {
            acc_o[tn][0] *= corr0; acc_o[tn][1] *= corr0;
            acc_o[tn][2] *= corr1; acc_o[tn][3] *= corr1;
        }

#pragma unroll
        for (int kt = 0; kt < 4; kt++) {
            uint32_t ah0 = Ph01[2 * kt], ah1 = Ph23[2 * kt];
            uint32_t ah2 = Ph01[2 * kt + 1], ah3 = Ph23[2 * kt + 1];
            uint32_t al0 = Pl01[2 * kt], al1 = Pl23[2 * kt];
            uint32_t al2 = Pl01[2 * kt + 1], al3 = Pl23[2 * kt + 1];
#pragma unroll
            for (int dp = 0; dp < 4; dp++) {
                uint32_t vaddr = sb + AVH + bV + kt * (16 * AT_RS) + dp * 32;
                uint32_t vh0, vh1, vh2, vh3, vl0, vl1, vl2, vl3;
                ldsm4t(vh0, vh1, vh2, vh3, vaddr);
                ldsm4t(vl0, vl1, vl2, vl3, vaddr + 9216);
                mma16816h(acc_o[dp * 2],     ah0, ah1, ah2, ah3, vh0, vh1);
                mma16816h(acc_o[dp * 2],     ah0, ah1, ah2, ah3, vl0, vl1);
                mma16816h(acc_o[dp * 2],     al0, al1, al2, al3, vh0, vh1);
                mma16816h(acc_o[dp * 2 + 1], ah0, ah1, ah2, ah3, vh2, vh3);
                mma16816h(acc_o[dp * 2 + 1], ah0, ah1, ah2, ah3, vl2, vl3);
                mma16816h(acc_o[dp * 2 + 1], al0, al1, al2, al3, vh2, vh3);
            }
        }

        __syncthreads();
        if (kc + 64 < k1) {
            LOADKV(kc + 64);
            cp_wait0();
            __syncthreads();
        }
    }

    const float inv0 = 1.f / den0, inv1 = 1.f / den1;
    const int row0 = q0 + wid * 16 + qid, row1 = row0 + 8;
#pragma unroll
    for (int tn = 0; tn < 8; tn++) {
        int col = h * 64 + tn * 8 + tq * 2;
        if (row0 < q1)
            *(uint32_t*)&g_WVh[(size_t)row0 * KP_A + col] =
                pack2(__float2half(acc_o[tn][0] * inv0), __float2half(acc_o[tn][1] * inv0));
        if (row1 < q1)
            *(uint32_t*)&g_WVh[(size_t)row1 * KP_A + col] =
                pack2(__float2half(acc_o[tn][2] * inv1), __float2half(acc_o[tn][3] * inv1));
    }
}

// ---------------------------------------------------------------------------
// Launch
// ---------------------------------------------------------------------------
extern "C" void kernel_launch(void* const* d_in, const int* in_sizes, int n_in,
                              void* d_out, int out_size)
{
    const float* A     = (const float*)d_in[0];
    const float* B0    = (const float*)d_in[1];
    const int*   seg_q = (const int*)  d_in[2];
    const int*   seg_kv= (const int*)  d_in[3];
    const float* Wq    = (const float*)d_in[4];
    const float* bq    = (const float*)d_in[5];
    const float* Wk    = (const float*)d_in[6];
    const float* bk    = (const float*)d_in[7];
    const float* Wv    = (const float*)d_in[8];
    const float* bv    = (const float*)d_in[9];
    const float* Wf    = (const float*)d_in[10];
    const float* bf    = (const float*)d_in[11];
    float*       out   = (float*)d_out;

    __half *Ahp, *B0hp;
    cudaGetSymbolAddress((void**)&Ahp,  g_Ah);
    cudaGetSymbolAddress((void**)&B0hp, g_B0h);

    cudaFuncSetAttribute(gemm_qkv,   cudaFuncAttributeMaxDynamicSharedMemorySize, GEMM_SMEM);
    cudaFuncSetAttribute(gemm_final, cudaFuncAttributeMaxDynamicSharedMemorySize, GEMM_SMEM);
    cudaFuncSetAttribute(attn_fa,    cudaFuncAttributeMaxDynamicSharedMemorySize, ATTN_SMEM);

    convert_all<<<CV_TOT, 256>>>(A, B0, Wq, Wk, Wv, Wf, seg_q, seg_kv);

    gemm_qkv<<<dim3(D_QK / BN, TOTAL_Q / BM, 3), 256, GEMM_SMEM>>>(
        Ahp, B0hp, bq, bk, bv);

    attn_fa<<<dim3(N_HEADS, N_IMAGES, 4), 128, ATTN_SMEM>>>();

    gemm_final<<<dim3(Q_IN / BN, TOTAL_Q / BM), 256, GEMM_SMEM>>>(bf, out);
}

// round 17
// speedup vs baseline: 6.5188x; 1.0305x over previous
#include <cuda_runtime.h>
#include <cuda_fp16.h>
#include <cstdint>
#include <math.h>

// ---------------------------------------------------------------------------
// Problem constants
// ---------------------------------------------------------------------------
#define TOTAL_Q   2048
#define TOTAL_KV  2048
#define Q_IN      1024
#define KV_IN     1033
#define D_QK      1024
#define D_V       1024
#define N_HEADS   16
#define HEAD_DIM  64
#define N_IMAGES  32
#define SCALER    0.125f

#define KP_A 1024
#define KP_B 1088              // 17 * 64

// ---------------------------------------------------------------------------
// Device scratch
// ---------------------------------------------------------------------------
__device__ int   g_kv_start[N_IMAGES], g_kv_end[N_IMAGES];
__device__ int   g_q_start [N_IMAGES], g_q_end [N_IMAGES];

__device__ __half g_Ah  [TOTAL_Q  * KP_A];
__device__ __half g_B0h [TOTAL_KV * KP_B];
__device__ __half g_WVh [TOTAL_Q  * KP_A];
__device__ __half g_Qhi [TOTAL_Q  * D_QK], g_Qlo [TOTAL_Q  * D_QK];
__device__ __half g_Khi [TOTAL_KV * D_QK], g_Klo [TOTAL_KV * D_QK];
__device__ __half g_Vhi [TOTAL_KV * D_V ], g_Vlo [TOTAL_KV * D_V ];
__device__ __half g_WqT [D_QK * KP_A];
__device__ __half g_WkT [D_QK * KP_B];
__device__ __half g_WvT [D_V  * KP_B];
__device__ __half g_WfT [Q_IN * KP_A];

// ---------------------------------------------------------------------------
// PTX helpers
// ---------------------------------------------------------------------------
__device__ __forceinline__ uint32_t smem_u32(const void* p) {
    uint32_t a;
    asm("{ .reg .u64 t; cvta.to.shared.u64 t, %1; cvt.u32.u64 %0, t; }" : "=r"(a) : "l"(p));
    return a;
}
__device__ __forceinline__ void mma16816h(float* c,
    uint32_t a0, uint32_t a1, uint32_t a2, uint32_t a3,
    uint32_t b0, uint32_t b1)
{
    asm volatile(
        "mma.sync.aligned.m16n8k16.row.col.f32.f16.f16.f32 "
        "{%0,%1,%2,%3}, {%4,%5,%6,%7}, {%8,%9}, {%0,%1,%2,%3};"
        : "+f"(c[0]), "+f"(c[1]), "+f"(c[2]), "+f"(c[3])
        : "r"(a0), "r"(a1), "r"(a2), "r"(a3), "r"(b0), "r"(b1));
}
__device__ __forceinline__ void ldsm4(uint32_t& r0, uint32_t& r1, uint32_t& r2, uint32_t& r3,
                                      uint32_t addr)
{
    asm volatile("ldmatrix.sync.aligned.m8n8.x4.shared.b16 {%0,%1,%2,%3}, [%4];"
                 : "=r"(r0), "=r"(r1), "=r"(r2), "=r"(r3) : "r"(addr));
}
__device__ __forceinline__ void ldsm4t(uint32_t& r0, uint32_t& r1, uint32_t& r2, uint32_t& r3,
                                       uint32_t addr)
{
    asm volatile("ldmatrix.sync.aligned.m8n8.x4.trans.shared.b16 {%0,%1,%2,%3}, [%4];"
                 : "=r"(r0), "=r"(r1), "=r"(r2), "=r"(r3) : "r"(addr));
}
__device__ __forceinline__ void cp16(uint32_t dst, const void* src)
{
    asm volatile("cp.async.cg.shared.global [%0], [%1], 16;" :: "r"(dst), "l"(src) : "memory");
}
__device__ __forceinline__ void cp_commit() { asm volatile("cp.async.commit_group;" ::: "memory"); }
__device__ __forceinline__ void cp_wait0()  { asm volatile("cp.async.wait_group 0;"  ::: "memory"); }
__device__ __forceinline__ void cp_wait1()  { asm volatile("cp.async.wait_group 1;"  ::: "memory"); }

__device__ __forceinline__ void split_fp16(float x, __half& hi, __half& lo)
{
    hi = __float2half(x);
    lo = __float2half(x - __half2float(hi));
}
__device__ __forceinline__ uint32_t pack2(__half a, __half b)
{
    __half2 h = __halves2half2(a, b);
    return *(uint32_t*)&h;
}

// ---------------------------------------------------------------------------
// Fused conversions + segment bounds (one flat grid), vectorized
// ---------------------------------------------------------------------------
#define CV_O1 2048
#define CV_O2 (CV_O1 + 4352)            // 6400
#define CV_O3 (CV_O2 + 1024)            // 7424
#define CV_O4 (CV_O3 + 1088)            // 8512
#define CV_O5 (CV_O4 + 1088)            // 9600
#define CV_O6 (CV_O5 + 1024)            // 10624
#define CV_TOT (CV_O6 + 8)

__device__ __forceinline__ void wT_job(const float* __restrict__ W,
                                       __half* __restrict__ hiT,
                                       int K, int N, int Kp, int local, int tid)
{
    __shared__ float t[32][33];
    int kbn = Kp >> 5;
    int kb = local % kbn, nb = local / kbn;
    int k0 = kb * 32, n0 = nb * 32;
    int tx = tid & 31, ty = tid >> 5;
#pragma unroll
    for (int i = 0; i < 4; i++) {
        int k = k0 + ty + i * 8;
        t[ty + i * 8][tx] = (k < K) ? W[(size_t)k * N + n0 + tx] : 0.f;
    }
    __syncthreads();
#pragma unroll
    for (int i = 0; i < 4; i++) {
        int n = n0 + ty + i * 8;
        hiT[(size_t)n * Kp + k0 + tx] = __float2half(t[tx][ty + i * 8]);
    }
}

__global__ __launch_bounds__(256) void convert_all(
    const float* __restrict__ A,  const float* __restrict__ B0,
    const float* __restrict__ Wq, const float* __restrict__ Wk,
    const float* __restrict__ Wv, const float* __restrict__ Wf,
    const int* __restrict__ sq,   const int* __restrict__ skv)
{
    const int b = blockIdx.x, tid = threadIdx.x;
    if (b < CV_O1) {
        int idx = (b * 256 + tid) * 4;
        float4 v = *(const float4*)&A[idx];
        uint2 o;
        o.x = pack2(__float2half(v.x), __float2half(v.y));
        o.y = pack2(__float2half(v.z), __float2half(v.w));
        *(uint2*)&g_Ah[idx] = o;
    } else if (b < CV_O2) {
        int p = ((b - CV_O1) * 256 + tid);
        int m = p / (KP_B / 2), kk = (p - m * (KP_B / 2)) * 2;
        float x0 = (kk     < KV_IN) ? B0[(size_t)m * KV_IN + kk]     : 0.f;
        float x1 = (kk + 1 < KV_IN) ? B0[(size_t)m * KV_IN + kk + 1] : 0.f;
        *(uint32_t*)&g_B0h[(size_t)m * KP_B + kk] =
            pack2(__float2half(x0), __float2half(x1));
    } else if (b < CV_O3) {
        wT_job(Wq, g_WqT, Q_IN,  D_QK, KP_A, b - CV_O2, tid);
    } else if (b < CV_O4) {
        wT_job(Wk, g_WkT, KV_IN, D_QK, KP_B, b - CV_O3, tid);
    } else if (b < CV_O5) {
        wT_job(Wv, g_WvT, KV_IN, D_V,  KP_B, b - CV_O4, tid);
    } else if (b < CV_O6) {
        wT_job(Wf, g_WfT, D_V,   Q_IN, KP_A, b - CV_O5, tid);
    } else {
        int i = (b - CV_O6) * 256 + tid;
        if (i < TOTAL_Q) {
            int s = sq[i];
            if (i == 0           || sq[i - 1] != s) g_q_start[s] = i;
            if (i == TOTAL_Q - 1 || sq[i + 1] != s) g_q_end[s]   = i + 1;
        }
        if (i < TOTAL_KV) {
            int s = skv[i];
            if (i == 0            || skv[i - 1] != s) g_kv_start[s] = i;
            if (i == TOTAL_KV - 1 || skv[i + 1] != s) g_kv_end[s]   = i + 1;
        }
    }
}

// ---------------------------------------------------------------------------
// fp16 1-term GEMM core (qkv): BM=128, BN=128, BK=32, 256 threads,
// warp tile 32x64, 3-stage cp.async pipeline (race-free drain), ldmatrix.
// ---------------------------------------------------------------------------
#define BM 128
#define BN 128
#define BK 32
#define RS 80
#define A_OFF   0
#define B_OFF   (128 * RS)            // 10240
#define STAGE   (2 * 128 * RS)        // 20480
#define NSTG    3
#define GEMM_SMEM (NSTG * STAGE)      // 61440

__device__ __forceinline__ void gemm_core_split(
    char* smc,
    const __half* __restrict__ Ah, const __half* __restrict__ Bh,
    const float* __restrict__ bias,
    __half* __restrict__ Chi, __half* __restrict__ Clo,
    int N, int Kp, int bm, int bn)
{
    const uint32_t sb = smem_u32(smc);
    const int tid  = threadIdx.x;
    const int lane = tid & 31;
    const int wid  = tid >> 5;
    const int qid  = lane >> 2;
    const int tq   = lane & 3;
    const int warpM = wid & 3;
    const int warpN = wid >> 2;
    const int chunks = Kp >> 5;

    const uint32_t g = lane >> 3;
    const uint32_t aBase = (warpM * 32 + (g & 1) * 8 + (lane & 7)) * RS + (g >> 1) * 16;
    const uint32_t bBase = (warpN * 64 + (g >> 1) * 8 + (lane & 7)) * RS + (g & 1) * 16;

    float acc[2][8][4];
#pragma unroll
    for (int m2 = 0; m2 < 2; m2++)
#pragma unroll
        for (int t = 0; t < 8; t++)
#pragma unroll
            for (int j = 0; j < 4; j++) acc[m2][t][j] = 0.f;

    const int prow = tid >> 2;
    const int pseg = tid & 3;

    auto PREFETCH = [&](int c, int slot) {
        uint32_t stb = sb + slot * STAGE;
        const int kb = c * BK;
#pragma unroll
        for (int i = 0; i < 2; i++) {
            int row = prow + i * 64;
            cp16(stb + A_OFF + row * RS + pseg * 16,
                 &Ah[(size_t)(bm + row) * Kp + kb + pseg * 8]);
            cp16(stb + B_OFF + row * RS + pseg * 16,
                 &Bh[(size_t)(bn + row) * Kp + kb + pseg * 8]);
        }
        cp_commit();
    };

    auto COMPUTE = [&](int slot) {
        uint32_t stb = sb + slot * STAGE;
#pragma unroll
        for (int ks = 0; ks < 2; ks++) {
            uint32_t a0[2], a1[2], a2[2], a3[2];
#pragma unroll
            for (int m2 = 0; m2 < 2; m2++)
                ldsm4(a0[m2], a1[m2], a2[m2], a3[m2],
                      stb + A_OFF + aBase + m2 * (16 * RS) + ks * 32);
#pragma unroll
            for (int p = 0; p < 4; p++) {
                uint32_t b0, b1, b2, b3;
                ldsm4(b0, b1, b2, b3, stb + B_OFF + bBase + p * (16 * RS) + ks * 32);
#pragma unroll
                for (int m2 = 0; m2 < 2; m2++) {
                    mma16816h(acc[m2][p * 2],     a0[m2], a1[m2], a2[m2], a3[m2], b0, b1);
                    mma16816h(acc[m2][p * 2 + 1], a0[m2], a1[m2], a2[m2], a3[m2], b2, b3);
                }
            }
        }
    };

    PREFETCH(0, 0);
    PREFETCH(1, 1);

    int slot = 0;
    for (int c = 0; c < chunks; c++) {
        // Drain correctly: mid-loop 2 groups pending -> wait1 completes chunk c.
        // Last iteration only chunk c pending -> must wait0 (wait1 is a no-op!).
        if (c + 1 < chunks) cp_wait1(); else cp_wait0();
        __syncthreads();
        if (c + 2 < chunks) {
            int s2 = slot + 2; if (s2 >= NSTG) s2 -= NSTG;
            PREFETCH(c + 2, s2);
        }
        COMPUTE(slot);
        if (++slot == NSTG) slot = 0;
    }

#pragma unroll
    for (int m2 = 0; m2 < 2; m2++) {
        const int r0 = bm + warpM * 32 + m2 * 16 + qid;
#pragma unroll
        for (int tn = 0; tn < 8; tn++) {
            const int col = bn + warpN * 64 + tn * 8 + tq * 2;
            float2 b2 = *(const float2*)&bias[col];
            float v0 = acc[m2][tn][0] + b2.x, v1 = acc[m2][tn][1] + b2.y;
            float v2 = acc[m2][tn][2] + b2.x, v3 = acc[m2][tn][3] + b2.y;
            __half h0, l0, h1, l1, h2, l2, h3, l3;
            split_fp16(v0, h0, l0); split_fp16(v1, h1, l1);
            split_fp16(v2, h2, l2); split_fp16(v3, h3, l3);
            *(uint32_t*)&Chi[(size_t)r0 * N + col]       = pack2(h0, h1);
            *(uint32_t*)&Clo[(size_t)r0 * N + col]       = pack2(l0, l1);
            *(uint32_t*)&Chi[(size_t)(r0 + 8) * N + col] = pack2(h2, h3);
            *(uint32_t*)&Clo[(size_t)(r0 + 8) * N + col] = pack2(l2, l3);
        }
    }
}

__global__ __launch_bounds__(256, 2) void gemm_qkv(
    const __half* __restrict__ Ah, const __half* __restrict__ B0h,
    const float* __restrict__ bq, const float* __restrict__ bk,
    const float* __restrict__ bv)
{
    extern __shared__ char smc[];
    const int z = blockIdx.z;
    const __half* A   = (z == 0) ? Ah : B0h;
    const __half* Bh  = (z == 0) ? g_WqT : (z == 1) ? g_WkT : g_WvT;
    const float* bias = (z == 0) ? bq : (z == 1) ? bk : bv;
    __half* Chi       = (z == 0) ? g_Qhi : (z == 1) ? g_Khi : g_Vhi;
    __half* Clo       = (z == 0) ? g_Qlo : (z == 1) ? g_Klo : g_Vlo;
    const int Kp      = (z == 0) ? KP_A : KP_B;
    gemm_core_split(smc, A, Bh, bias, Chi, Clo, D_QK, Kp,
                    blockIdx.y * BM, blockIdx.x * BN);
}

// ---------------------------------------------------------------------------
// Final GEMM: BM=128, BN=64 (grid 16x16 = 256 CTAs, 2 resident/SM),
// warp tile 32x32, 3-stage cp.async (race-free drain), fp32 output.
// ---------------------------------------------------------------------------
#define B64_OFF (128 * RS)
#define STAGE64 ((128 + 64) * RS)           // 15360
#define GEMM64_SMEM (NSTG * STAGE64)        // 46080

__global__ __launch_bounds__(256, 2) void gemm_final(
    const float* __restrict__ bf, float* __restrict__ out)
{
    extern __shared__ char smc[];
    const uint32_t sb = smem_u32(smc);
    const __half* __restrict__ Ah = g_WVh;
    const __half* __restrict__ Bh = g_WfT;
    const int N = Q_IN, Kp = KP_A;
    const int bm = blockIdx.y * 128, bn = blockIdx.x * 64;
    const int tid  = threadIdx.x;
    const int lane = tid & 31;
    const int wid  = tid >> 5;
    const int qid  = lane >> 2;
    const int tq   = lane & 3;
    const int warpM = wid & 3;
    const int warpN = wid >> 2;
    const int chunks = Kp >> 5;

    const uint32_t g = lane >> 3;
    const uint32_t aBase = (warpM * 32 + (g & 1) * 8 + (lane & 7)) * RS + (g >> 1) * 16;
    const uint32_t bBase = (warpN * 32 + (g >> 1) * 8 + (lane & 7)) * RS + (g & 1) * 16;

    float acc[2][4][4];
#pragma unroll
    for (int m2 = 0; m2 < 2; m2++)
#pragma unroll
        for (int t = 0; t < 4; t++)
#pragma unroll
            for (int j = 0; j < 4; j++) acc[m2][t][j] = 0.f;

    auto PREFETCH = [&](int c, int slot) {
        uint32_t stb = sb + slot * STAGE64;
        const int kb = c * BK;
#pragma unroll
        for (int i = 0; i < 2; i++) {
            int u = tid + i * 256;
            int row = u >> 2, seg = u & 3;
            cp16(stb + row * RS + seg * 16,
                 &Ah[(size_t)(bm + row) * Kp + kb + seg * 8]);
        }
        {
            int row = tid >> 2, seg = tid & 3;
            cp16(stb + B64_OFF + row * RS + seg * 16,
                 &Bh[(size_t)(bn + row) * Kp + kb + seg * 8]);
        }
        cp_commit();
    };

    auto COMPUTE = [&](int slot) {
        uint32_t stb = sb + slot * STAGE64;
#pragma unroll
        for (int ks = 0; ks < 2; ks++) {
            uint32_t a0[2], a1[2], a2[2], a3[2];
#pragma unroll
            for (int m2 = 0; m2 < 2; m2++)
                ldsm4(a0[m2], a1[m2], a2[m2], a3[m2],
                      stb + aBase + m2 * (16 * RS) + ks * 32);
#pragma unroll
            for (int p = 0; p < 2; p++) {
                uint32_t b0, b1, b2, b3;
                ldsm4(b0, b1, b2, b3, stb + B64_OFF + bBase + p * (16 * RS) + ks * 32);
#pragma unroll
                for (int m2 = 0; m2 < 2; m2++) {
                    mma16816h(acc[m2][p * 2],     a0[m2], a1[m2], a2[m2], a3[m2], b0, b1);
                    mma16816h(acc[m2][p * 2 + 1], a0[m2], a1[m2], a2[m2], a3[m2], b2, b3);
                }
            }
        }
    };

    PREFETCH(0, 0);
    PREFETCH(1, 1);

    int slot = 0;
    for (int c = 0; c < chunks; c++) {
        if (c + 1 < chunks) cp_wait1(); else cp_wait0();
        __syncthreads();
        if (c + 2 < chunks) {
            int s2 = slot + 2; if (s2 >= NSTG) s2 -= NSTG;
            PREFETCH(c + 2, s2);
        }
        COMPUTE(slot);
        if (++slot == NSTG) slot = 0;
    }

#pragma unroll
    for (int m2 = 0; m2 < 2; m2++) {
        const int r0 = bm + warpM * 32 + m2 * 16 + qid;
#pragma unroll
        for (int tn = 0; tn < 4; tn++) {
            const int col = bn + warpN * 32 + tn * 8 + tq * 2;
            float2 b2 = *(const float2*)&bf[col];
            *(float2*)&out[(size_t)r0 * N + col] =
                make_float2(acc[m2][tn][0] + b2.x, acc[m2][tn][1] + b2.y);
            *(float2*)&out[(size_t)(r0 + 8) * N + col] =
                make_float2(acc[m2][tn][2] + b2.x, acc[m2][tn][3] + b2.y);
        }
    }
}

// ---------------------------------------------------------------------------
// Flash attention: block = (head, seg, 64-q tile), 4 warps.
// ---------------------------------------------------------------------------
#define AT_RS 144
#define AQH 0
#define AQL 9216
#define AKH (2 * 9216)
#define AVH (4 * 9216)
#define ATTN_SMEM (6 * 9216)

__global__ __launch_bounds__(128) void attn_fa()
{
    extern __shared__ char smc[];
    const uint32_t sb = smem_u32(smc);
    const int h = blockIdx.x, s = blockIdx.y, qb = blockIdx.z;
    const int k0 = g_kv_start[s], k1 = g_kv_end[s];
    const int qs = g_q_start[s],  qe = g_q_end[s];
    const int q0 = qs + qb * 64;
    if (q0 >= qe) return;
    const int q1 = min(q0 + 64, qe);

    const int tid = threadIdx.x, lane = tid & 31, wid = tid >> 5;
    const int qid = lane >> 2, tq = lane & 3;
    const uint32_t g = lane >> 3;

    const uint32_t aQ = (wid * 16 + (g & 1) * 8 + (lane & 7)) * AT_RS + ((g >> 1) * 8) * 2;
    const uint32_t bK = ((g >> 1) * 8 + (lane & 7)) * AT_RS + ((g & 1) * 8) * 2;
    const uint32_t bV = ((g & 1) * 8 + (lane & 7)) * AT_RS + ((g >> 1) * 8) * 2;

#pragma unroll
    for (int i = 0; i < 8; i++) {
        int u = tid + i * 128;
        int plane = u >> 9, idx = u & 511;
        int row = idx >> 3, seg = idx & 7;
        int qrow = min(q0 + row, TOTAL_Q - 1);
        const __half* src = (plane ? g_Qlo : g_Qhi) + (size_t)qrow * D_QK + h * 64 + seg * 8;
        cp16(sb + (plane ? AQL : AQH) + row * AT_RS + seg * 16, src);
    }

    auto LOADKV = [&](int kc) {
#pragma unroll
        for (int i = 0; i < 16; i++) {
            int u = tid + i * 128;
            int plane = u >> 9, idx = u & 511;
            int row = idx >> 3, seg = idx & 7;
            int krow = min(kc + row, TOTAL_KV - 1);
            const __half* base = (plane == 0) ? g_Khi : (plane == 1) ? g_Klo
                               : (plane == 2) ? g_Vhi : g_Vlo;
            cp16(sb + AKH + plane * 9216 + row * AT_RS + seg * 16,
                 base + (size_t)krow * D_QK + h * 64 + seg * 8);
        }
        cp_commit();
    };

    LOADKV(k0);
    cp_wait0();
    __syncthreads();

    float m0 = -1e30f, m1 = -1e30f, den0 = 0.f, den1 = 0.f;
    float acc_o[8][4];
#pragma unroll
    for (int t = 0; t < 8; t++)
#pragma unroll
        for (int j = 0; j < 4; j++) acc_o[t][j] = 0.f;

    for (int kc = k0; kc < k1; kc += 64) {
        const int cl = min(64, k1 - kc);

        float sc[8][4];
#pragma unroll
        for (int t = 0; t < 8; t++)
#pragma unroll
            for (int j = 0; j < 4; j++) sc[t][j] = 0.f;
#pragma unroll
        for (int ks = 0; ks < 4; ks++) {
            uint32_t qh0, qh1, qh2, qh3, ql0, ql1, ql2, ql3;
            ldsm4(qh0, qh1, qh2, qh3, sb + AQH + aQ + ks * 32);
            ldsm4(ql0, ql1, ql2, ql3, sb + AQL + aQ + ks * 32);
#pragma unroll
            for (int p = 0; p < 4; p++) {
                uint32_t kaddr = sb + AKH + bK + p * (16 * AT_RS) + ks * 32;
                uint32_t kh0, kh1, kh2, kh3, kl0, kl1, kl2, kl3;
                ldsm4(kh0, kh1, kh2, kh3, kaddr);
                ldsm4(kl0, kl1, kl2, kl3, kaddr + 9216);
                mma16816h(sc[p * 2],     qh0, qh1, qh2, qh3, kh0, kh1);
                mma16816h(sc[p * 2],     qh0, qh1, qh2, qh3, kl0, kl1);
                mma16816h(sc[p * 2],     ql0, ql1, ql2, ql3, kh0, kh1);
                mma16816h(sc[p * 2 + 1], qh0, qh1, qh2, qh3, kh2, kh3);
                mma16816h(sc[p * 2 + 1], qh0, qh1, qh2, qh3, kl2, kl3);
                mma16816h(sc[p * 2 + 1], ql0, ql1, ql2, ql3, kh2, kh3);
            }
        }

        float M0 = -1e30f, M1 = -1e30f;
#pragma unroll
        for (int tn = 0; tn < 8; tn++) {
            int c0 = tn * 8 + tq * 2, c1 = c0 + 1;
            sc[tn][0] = (c0 < cl) ? sc[tn][0] * SCALER : -1e30f;
            sc[tn][1] = (c1 < cl) ? sc[tn][1] * SCALER : -1e30f;
            sc[tn][2] = (c0 < cl) ? sc[tn][2] * SCALER : -1e30f;
            sc[tn][3] = (c1 < cl) ? sc[tn][3] * SCALER : -1e30f;
            M0 = fmaxf(M0, fmaxf(sc[tn][0], sc[tn][1]));
            M1 = fmaxf(M1, fmaxf(sc[tn][2], sc[tn][3]));
        }
        M0 = fmaxf(M0, __shfl_xor_sync(0xffffffffu, M0, 1));
        M0 = fmaxf(M0, __shfl_xor_sync(0xffffffffu, M0, 2));
        M1 = fmaxf(M1, __shfl_xor_sync(0xffffffffu, M1, 1));
        M1 = fmaxf(M1, __shfl_xor_sync(0xffffffffu, M1, 2));

        const float nm0 = fmaxf(m0, M0), nm1 = fmaxf(m1, M1);
        const float corr0 = __expf(m0 - nm0), corr1 = __expf(m1 - nm1);
        m0 = nm0; m1 = nm1;

        uint32_t Ph01[8], Ph23[8], Pl01[8], Pl23[8];
        float sum0 = 0.f, sum1 = 0.f;
#pragma unroll
        for (int tn = 0; tn < 8; tn++) {
            float p0 = __expf(sc[tn][0] - nm0), p1 = __expf(sc[tn][1] - nm0);
            float p2 = __expf(sc[tn][2] - nm1), p3 = __expf(sc[tn][3] - nm1);
            sum0 += p0 + p1; sum1 += p2 + p3;
            __half h0 = __float2half(p0), h1 = __float2half(p1);
            __half h2 = __float2half(p2), h3 = __float2half(p3);
            Ph01[tn] = pack2(h0, h1);
            Ph23[tn] = pack2(h2, h3);
            Pl01[tn] = pack2(__float2half(p0 - __half2float(h0)),
                             __float2half(p1 - __half2float(h1)));
            Pl23[tn] = pack2(__float2half(p2 - __half2float(h2)),
                             __float2half(p3 - __half2float(h3)));
        }
        sum0 += __shfl_xor_sync(0xffffffffu, sum0, 1);
        sum0 += __shfl_xor_sync(0xffffffffu, sum0, 2);
        sum1 += __shfl_xor_sync(0xffffffffu, sum1, 1);
        sum1 += __shfl_xor_sync(0xffffffffu, sum1, 2);
        den0 = den0 * corr0 + sum0;
        den1 = den1 * corr1 + sum1;

#pragma unroll
        for (int tn = 0; tn < 8; tn++) {
            acc_o[tn][0] *= corr0; acc_o[tn][1] *= corr0;
            acc_o[tn][2] *= corr1; acc_o[tn][3] *= corr1;
        }

#pragma unroll
        for (int kt = 0; kt < 4; kt++) {
            uint32_t ah0 = Ph01[2 * kt], ah1 = Ph23[2 * kt];
            uint32_t ah2 = Ph01[2 * kt + 1], ah3 = Ph23[2 * kt + 1];
            uint32_t al0 = Pl01[2 * kt], al1 = Pl23[2 * kt];
            uint32_t al2 = Pl01[2 * kt + 1], al3 = Pl23[2 * kt + 1];
#pragma unroll
            for (int dp = 0; dp < 4; dp++) {
                uint32_t vaddr = sb + AVH + bV + kt * (16 * AT_RS) + dp * 32;
                uint32_t vh0, vh1, vh2, vh3, vl0, vl1, vl2, vl3;
                ldsm4t(vh0, vh1, vh2, vh3, vaddr);
                ldsm4t(vl0, vl1, vl2, vl3, vaddr + 9216);
                mma16816h(acc_o[dp * 2],     ah0, ah1, ah2, ah3, vh0, vh1);
                mma16816h(acc_o[dp * 2],     ah0, ah1, ah2, ah3, vl0, vl1);
                mma16816h(acc_o[dp * 2],     al0, al1, al2, al3, vh0, vh1);
                mma16816h(acc_o[dp * 2 + 1], ah0, ah1, ah2, ah3, vh2, vh3);
                mma16816h(acc_o[dp * 2 + 1], ah0, ah1, ah2, ah3, vl2, vl3);
                mma16816h(acc_o[dp * 2 + 1], al0, al1, al2, al3, vh2, vh3);
            }
        }

        __syncthreads();
        if (kc + 64 < k1) {
            LOADKV(kc + 64);
            cp_wait0();
            __syncthreads();
        }
    }

    const float inv0 = 1.f / den0, inv1 = 1.f / den1;
    const int row0 = q0 + wid * 16 + qid, row1 = row0 + 8;
#pragma unroll
    for (int tn = 0; tn < 8; tn++) {
        int col = h * 64 + tn * 8 + tq * 2;
        if (row0 < q1)
            *(uint32_t*)&g_WVh[(size_t)row0 * KP_A + col] =
                pack2(__float2half(acc_o[tn][0] * inv0), __float2half(acc_o[tn][1] * inv0));
        if (row1 < q1)
            *(uint32_t*)&g_WVh[(size_t)row1 * KP_A + col] =
                pack2(__float2half(acc_o[tn][2] * inv1), __float2half(acc_o[tn][3] * inv1));
    }
}

// ---------------------------------------------------------------------------
// Launch
// ---------------------------------------------------------------------------
extern "C" void kernel_launch(void* const* d_in, const int* in_sizes, int n_in,
                              void* d_out, int out_size)
{
    const float* A     = (const float*)d_in[0];
    const float* B0    = (const float*)d_in[1];
    const int*   seg_q = (const int*)  d_in[2];
    const int*   seg_kv= (const int*)  d_in[3];
    const float* Wq    = (const float*)d_in[4];
    const float* bq    = (const float*)d_in[5];
    const float* Wk    = (const float*)d_in[6];
    const float* bk    = (const float*)d_in[7];
    const float* Wv    = (const float*)d_in[8];
    const float* bv    = (const float*)d_in[9];
    const float* Wf    = (const float*)d_in[10];
    const float* bf    = (const float*)d_in[11];
    float*       out   = (float*)d_out;

    __half *Ahp, *B0hp;
    cudaGetSymbolAddress((void**)&Ahp,  g_Ah);
    cudaGetSymbolAddress((void**)&B0hp, g_B0h);

    cudaFuncSetAttribute(gemm_qkv,   cudaFuncAttributeMaxDynamicSharedMemorySize, GEMM_SMEM);
    cudaFuncSetAttribute(gemm_final, cudaFuncAttributeMaxDynamicSharedMemorySize, GEMM64_SMEM);
    cudaFuncSetAttribute(attn_fa,    cudaFuncAttributeMaxDynamicSharedMemorySize, ATTN_SMEM);

    convert_all<<<CV_TOT, 256>>>(A, B0, Wq, Wk, Wv, Wf, seg_q, seg_kv);

    gemm_qkv<<<dim3(D_QK / BN, TOTAL_Q / BM, 3), 256, GEMM_SMEM>>>(
        Ahp, B0hp, bq, bk, bv);

    attn_fa<<<dim3(N_HEADS, N_IMAGES, 4), 128, ATTN_SMEM>>>();

    gemm_final<<<dim3(Q_IN / 64, TOTAL_Q / 128), 256, GEMM64_SMEM>>>(bf, out);
}